// round 8
// baseline (speedup 1.0000x reference)
#include <cuda_runtime.h>
#include <cuda_bf16.h>
#include <math.h>
#include <stdint.h>

typedef unsigned short u16;

// Problem constants
#define NN 32768
#define EE 262144
#define GG 64
#define HH 128

// ---------------- scratch ----------------------------------------------------
__device__ u16 g_wZU_h[256*384],  g_wZU_l[256*384];   // combined [zD | zS | U1] B
__device__ u16 g_wM0c_h[HH*HH],   g_wM0c_l[HH*HH];
__device__ u16 g_wM0d_h[HH*HH],   g_wM0d_l[HH*HH];
__device__ u16 g_wee_h[HH*HH],    g_wee_l[HH*HH];
__device__ u16 g_wM1_h[HH*HH],    g_wM1_l[HH*HH];
__device__ u16 g_wM2_h[HH*HH],    g_wM2_l[HH*HH];
__device__ u16 g_wM3_h[HH*HH],    g_wM3_l[HH*HH];
__device__ u16 g_wU2_h[HH*HH],    g_wU2_l[HH*HH];
__device__ u16 g_wQKV_h[3*HH*HH], g_wQKV_l[3*HH*HH];
__device__ u16 g_wWo_h[HH*HH],    g_wWo_l[HH*HH];
__device__ u16 g_wW1_h[2*HH*HH],  g_wW1_l[2*HH*HH];
__device__ u16 g_wW2_h[2*HH*HH],  g_wW2_l[2*HH*HH];
__device__ u16 g_wC_h[HH*HH],     g_wC_l[HH*HH];      // C = W_ee@M0c split
__device__ u16 g_wG_h[GG*HH],     g_wG_l[GG*HH];      // graph_fts split
// activations
__device__ float g_cvec[HH];
__device__ float g_GD[GG*HH];
__device__ float g_zc[(size_t)NN*384];                // [zD | zS | t1] strided 384
__device__ u16 g_z_h[NN*2*HH], g_z_l[NN*2*HH];
__device__ u16 g_m0h[(size_t)EE*HH], g_m0l[(size_t)EE*HH];
__device__ u16 g_m1h[(size_t)EE*HH], g_m1l[(size_t)EE*HH];
__device__ unsigned g_aggenc[NN*HH];
__device__ u16 g_agh[NN*HH], g_agl[NN*HH];
__device__ float g_h1[NN*HH];
__device__ float g_qkv[NN*3*HH];
__device__ u16 g_oh[NN*HH], g_ol[NN*HH];
__device__ float g_t2[NN*HH];
__device__ float g_h2[NN*HH];
__device__ float g_out[NN*HH];
__device__ u16 g_outh[NN*HH], g_outl[NN*HH];
__device__ u16 g_mlp1h[NN*2*HH], g_mlp1l[NN*2*HH];
__device__ float g_out2[NN*HH];
__device__ float g_part[256*256];
__device__ float g_stats[256];

// ---------------- helpers ----------------------------------------------------
__device__ __forceinline__ float leaky_f(float v) { return v > 0.0f ? v : 0.01f*v; }

__device__ __forceinline__ float fast_exp(float x) {
    x = fmaxf(x, -87.0f);
    float t  = x * 1.4426950408889634f;
    float fl = floorf(t);
    float f  = t - fl;
    float p  =            1.339077600e-4f;
    p = p * f + 9.618437357e-4f;
    p = p * f + 9.556031144e-3f;
    p = p * f + 5.550332471e-2f;
    p = p * f + 2.402264923e-1f;
    p = p * f + 6.931471825e-1f;
    p = p * f + 1.0f;
    int ei = (int)fl;
    return __int_as_float((ei + 127) << 23) * p;
}

__device__ __forceinline__ unsigned enc_f(float f) {
    unsigned u = __float_as_uint(f);
    return (u & 0x80000000u) ? ~u : (u | 0x80000000u);
}
__device__ __forceinline__ float dec_f(unsigned u) {
    return (u & 0x80000000u) ? __uint_as_float(u ^ 0x80000000u) : __uint_as_float(~u);
}
#define ENC_NEGINF 0x007FFFFFu

__device__ __forceinline__ uint32_t smem_u32(const void* p) {
    uint32_t a;
    asm("{ .reg .u64 t; cvta.to.shared.u64 t, %1; cvt.u32.u64 %0, t; }" : "=r"(a) : "l"(p));
    return a;
}

__device__ __forceinline__ void split2(float v, u16& hi, u16& lo) {
    __nv_bfloat16 h = __float2bfloat16(v);
    float r = v - __bfloat162float(h);
    __nv_bfloat16 l = __float2bfloat16(r);
    hi = *reinterpret_cast<u16*>(&h);
    lo = *reinterpret_cast<u16*>(&l);
}

// ---------------- MMA building blocks ----------------------------------------
#define LDM_X4(r, a) \
    asm volatile("ldmatrix.sync.aligned.m8n8.x4.shared.b16 {%0,%1,%2,%3}, [%4];" \
        : "=r"((r)[0]), "=r"((r)[1]), "=r"((r)[2]), "=r"((r)[3]) : "r"(a))
#define LDM_X4T(r, a) \
    asm volatile("ldmatrix.sync.aligned.m8n8.x4.trans.shared.b16 {%0,%1,%2,%3}, [%4];" \
        : "=r"((r)[0]), "=r"((r)[1]), "=r"((r)[2]), "=r"((r)[3]) : "r"(a))
#define MMA16816(c, a, b) \
    asm volatile("mma.sync.aligned.m16n8k16.row.col.f32.bf16.bf16.f32 " \
        "{%0,%1,%2,%3}, {%4,%5,%6,%7}, {%8,%9}, {%0,%1,%2,%3};" \
        : "+f"((c)[0]), "+f"((c)[1]), "+f"((c)[2]), "+f"((c)[3]) \
        : "r"((a)[0]), "r"((a)[1]), "r"((a)[2]), "r"((a)[3]), "r"((b)[0]), "r"((b)[1]))

#define CPA16(dst, src) asm volatile("cp.async.cg.shared.global [%0], [%1], 16;" :: "r"(dst), "l"(src))
#define CPA_COMMIT()    asm volatile("cp.async.commit_group;")
#define CPA_WAIT0()     asm volatile("cp.async.wait_group 0;" ::: "memory")

// XOR-swizzled offset inside a tile: rows of 256B, 16B chunks 0..15
__device__ __forceinline__ uint32_t swz(int row, int cb) {
    return (uint32_t)((row << 8) + (((cb ^ row) & 7) << 4) + ((cb & 8) << 4));
}

// ---------------- split-bf16 3-pass GEMM on mma.sync --------------------------
// Tile 64(M) x 128(N); 8 warps = 2x4; warp tile 32x32.
// Each CTA processes RB consecutive M-subtiles reusing the resident B tile;
// next subtile's A chunk is prefetched (cp.async) before the epilogue so the
// epilogue (stores / atomics) hides the fill.
// OUT: 0 = fp32 Cf; 1 = split to Ch/Cl; 2 = atomicMax into aggenc[dst[r]];
//      3 = gather-epilogue (+zD[dst]+zS[src]+GD[g]+cvec, leaky, split out)
template<int OUT, int ACT, bool BIAS, bool ACCUM, bool RESID, bool AF32>
__global__ void __launch_bounds__(256,2) gemm_ps(
    const void* Ah_, const u16* Al, int lda,
    const u16* __restrict__ Bh, const u16* __restrict__ Bl, int ldb,
    float* Cf, u16* Ch, u16* Cl, int ldc,
    const float* __restrict__ bias, const float* __restrict__ resid,
    const int* __restrict__ srcv, const int* __restrict__ dstv,
    const float* __restrict__ zD, const float* __restrict__ zS, int ldz,
    const float* __restrict__ GD, const float* __restrict__ cvec,
    unsigned* aggenc, int M, int N, int K, int PER, int tilesM, int RB)
{
    extern __shared__ char smem[];
    uint32_t sb = smem_u32(smem);
    const int tid = threadIdx.x;
    const int lane = tid & 31, w = tid >> 5;
    const int wm = w >> 2, wn = w & 3;
    const int ncol0 = blockIdx.x << 7;

    const uint32_t offB_h = 0;
    const uint32_t offB_l = (uint32_t)K * 256;
    const uint32_t offA_h = (uint32_t)K * 512;
    const uint32_t offA_l = offA_h + 16384;

    int ty0 = blockIdx.y * RB;
    int tyEnd = ty0 + RB; if (tyEnd > tilesM) tyEnd = tilesM;

    auto fillA = [&](int ty, int kc) {
        int mrow0 = ty << 6;
        if (AF32) {
            const float* Af = (const float*)Ah_;
            for (int idx = tid; idx < 64 * 16; idx += 256) {
                int row = idx >> 4, cb = idx & 15;
                const float* ap = Af + (size_t)(mrow0 + row) * lda + kc + cb * 8;
                float4 v0 = *reinterpret_cast<const float4*>(ap);
                float4 v1 = *reinterpret_cast<const float4*>(ap + 4);
                u16 h[8], l[8];
                split2(v0.x,h[0],l[0]); split2(v0.y,h[1],l[1]);
                split2(v0.z,h[2],l[2]); split2(v0.w,h[3],l[3]);
                split2(v1.x,h[4],l[4]); split2(v1.y,h[5],l[5]);
                split2(v1.z,h[6],l[6]); split2(v1.w,h[7],l[7]);
                uint32_t d = swz(row, cb);
                *reinterpret_cast<uint4*>(smem + offA_h + d) = make_uint4(
                    (uint32_t)h[0]|((uint32_t)h[1]<<16), (uint32_t)h[2]|((uint32_t)h[3]<<16),
                    (uint32_t)h[4]|((uint32_t)h[5]<<16), (uint32_t)h[6]|((uint32_t)h[7]<<16));
                *reinterpret_cast<uint4*>(smem + offA_l + d) = make_uint4(
                    (uint32_t)l[0]|((uint32_t)l[1]<<16), (uint32_t)l[2]|((uint32_t)l[3]<<16),
                    (uint32_t)l[4]|((uint32_t)l[5]<<16), (uint32_t)l[6]|((uint32_t)l[7]<<16));
            }
        } else {
            const u16* Ah = (const u16*)Ah_;
            for (int idx = tid; idx < 64 * 16; idx += 256) {
                int row = idx >> 4, cb = idx & 15;
                size_t so = (size_t)(mrow0 + row) * lda + kc + cb * 8;
                uint32_t d = swz(row, cb);
                CPA16(sb + offA_h + d, Ah + so);
                CPA16(sb + offA_l + d, Al + so);
            }
            CPA_COMMIT();
        }
    };

    // ---- B fill (whole K) + first A chunk ----
    for (int idx = tid; idx < K * 16; idx += 256) {
        int row = idx >> 4, cb = idx & 15;
        size_t so = (size_t)row * ldb + ncol0 + cb * 8;
        uint32_t d = swz(row, cb);
        CPA16(sb + offB_h + d, Bh + so);
        CPA16(sb + offB_l + d, Bl + so);
    }
    CPA_COMMIT();
    fillA(ty0, 0);

    for (int ty = ty0; ty < tyEnd; ty++) {
        const int mrow0 = ty << 6;
        float acc[2][4][4];
        #pragma unroll
        for (int i = 0; i < 2; i++)
            #pragma unroll
            for (int j = 0; j < 4; j++)
                #pragma unroll
                for (int q = 0; q < 4; q++) acc[i][j][q] = 0.0f;

        for (int kc = 0; kc < K; kc += 128) {
            CPA_WAIT0();
            __syncthreads();

            #pragma unroll
            for (int kk = 0; kk < 8; kk++) {
                uint32_t ah[2][4], al[2][4];
                #pragma unroll
                for (int i = 0; i < 2; i++) {
                    int row = wm*32 + i*16 + (lane & 15);
                    uint32_t ad = sb + offA_h + swz(row, kk*2 + (lane >> 4));
                    LDM_X4(ah[i], ad);
                    LDM_X4(al[i], ad + 16384);
                }
                uint32_t bh[4][2], bl[4][2];
                #pragma unroll
                for (int jj = 0; jj < 2; jj++) {
                    int krow = kc + kk*16 + (lane & 15);
                    uint32_t bd = sb + offB_h + swz(krow, wn*4 + jj*2 + (lane >> 4));
                    uint32_t t[4];
                    LDM_X4T(t, bd);
                    bh[jj*2][0]=t[0]; bh[jj*2][1]=t[1]; bh[jj*2+1][0]=t[2]; bh[jj*2+1][1]=t[3];
                    LDM_X4T(t, bd + offB_l);
                    bl[jj*2][0]=t[0]; bl[jj*2][1]=t[1]; bl[jj*2+1][0]=t[2]; bl[jj*2+1][1]=t[3];
                }
                #pragma unroll
                for (int i = 0; i < 2; i++)
                    #pragma unroll
                    for (int j = 0; j < 4; j++) {
                        MMA16816(acc[i][j], ah[i], bh[j]);
                        MMA16816(acc[i][j], ah[i], bl[j]);
                        MMA16816(acc[i][j], al[i], bh[j]);
                    }
            }
            __syncthreads();
            // prefetch next chunk / next subtile (overlaps epilogue below)
            if (kc + 128 < K) fillA(ty, kc + 128);
            else if (ty + 1 < tyEnd) fillA(ty + 1, 0);
        }

        // ---- epilogue ----
        #pragma unroll
        for (int i = 0; i < 2; i++) {
            int r0 = mrow0 + wm*32 + i*16 + (lane >> 2);
            #pragma unroll
            for (int half = 0; half < 2; half++) {
                int r = r0 + half*8;
                int sidx = 0, didx = 0, gidx = 0;
                if (OUT == 2 || OUT == 3) didx = dstv[r];
                if (OUT == 3) { sidx = srcv[r]; gidx = didx / PER; }
                #pragma unroll
                for (int j = 0; j < 4; j++) {
                    int c = ncol0 + wn*32 + j*8 + (lane & 3)*2;
                    size_t idx = (size_t)r * ldc + c;
                    float vx = acc[i][j][half*2], vy = acc[i][j][half*2 + 1];
                    if (BIAS)  { vx += bias[c]; vy += bias[c + 1]; }
                    if (OUT == 3) {
                        vx += zD[(size_t)didx*ldz + c] + zS[(size_t)sidx*ldz + c]
                            + GD[(size_t)gidx*HH + c] + cvec[c];
                        vy += zD[(size_t)didx*ldz + c+1] + zS[(size_t)sidx*ldz + c+1]
                            + GD[(size_t)gidx*HH + c+1] + cvec[c+1];
                        vx = leaky_f(vx); vy = leaky_f(vy);
                        u16 hx,lx,hy,ly; split2(vx,hx,lx); split2(vy,hy,ly);
                        *reinterpret_cast<uint32_t*>(Ch + idx) = (uint32_t)hx | ((uint32_t)hy<<16);
                        *reinterpret_cast<uint32_t*>(Cl + idx) = (uint32_t)lx | ((uint32_t)ly<<16);
                    } else if (OUT == 2) {
                        atomicMax(&aggenc[didx*HH + c],   enc_f(vx));
                        atomicMax(&aggenc[didx*HH + c+1], enc_f(vy));
                    } else {
                        if (ACCUM) { float2 t = *reinterpret_cast<float2*>(Cf + idx); vx += t.x; vy += t.y; }
                        if (RESID) { float2 t = *reinterpret_cast<const float2*>(resid + (size_t)r*HH + c); vx += t.x; vy += t.y; }
                        if (ACT == 1) { vx = fmaxf(vx, 0.f); vy = fmaxf(vy, 0.f); }
                        else if (ACT == 2) { vx = leaky_f(vx); vy = leaky_f(vy); }
                        if (OUT == 1) {
                            u16 hx,lx,hy,ly; split2(vx,hx,lx); split2(vy,hy,ly);
                            *reinterpret_cast<uint32_t*>(Ch + idx) = (uint32_t)hx | ((uint32_t)hy<<16);
                            *reinterpret_cast<uint32_t*>(Cl + idx) = (uint32_t)lx | ((uint32_t)ly<<16);
                        } else {
                            *reinterpret_cast<float2*>(Cf + idx) = make_float2(vx, vy);
                        }
                    }
                }
            }
        }
    }
}

// ---------------- small kernels ----------------------------------------------
__global__ void split_arr_k(const float* __restrict__ src, u16* __restrict__ hi,
                            u16* __restrict__ lo, int n)
{
    int i = blockIdx.x*blockDim.x + threadIdx.x;
    if (i >= n) return;
    u16 h, l; split2(src[i], h, l);
    hi[i] = h; lo[i] = l;
}

__global__ void build_zu_k(const float* __restrict__ M0, const float* __restrict__ U1)
{
    int i = blockIdx.x*blockDim.x + threadIdx.x;
    if (i >= 256*384) return;
    int k = i / 384, c = i - k*384;
    float v;
    if (c < 128)       v = M0[(size_t)k*HH + c];
    else if (c < 256)  v = M0[(size_t)(256 + k)*HH + (c - 128)];
    else               v = U1[(size_t)k*HH + (c - 256)];
    u16 h, l; split2(v, h, l);
    g_wZU_h[i] = h; g_wZU_l[i] = l;
}

__global__ void split_z_k(const float* __restrict__ node, const float* __restrict__ hid, int n)
{
    int i = blockIdx.x*blockDim.x + threadIdx.x;
    if (i >= n) return;
    int row = i >> 8, col = i & 255;
    float v = (col < 128) ? node[row*HH + col] : hid[row*HH + col - 128];
    u16 h, l; split2(v, h, l);
    g_z_h[i] = h; g_z_l[i] = l;
}

__global__ void cvec_k(const float* __restrict__ b_ee, const float* __restrict__ M0) {
    int j = threadIdx.x;
    float s = 0.0f;
    for (int t = 0; t < HH; t++) s += b_ee[t] * M0[(size_t)(4*HH + t)*HH + j];
    g_cvec[j] = s;
}

__global__ void agg_init_k(int total) {
    int i = blockIdx.x*blockDim.x + threadIdx.x;
    if (i < total) g_aggenc[i] = ENC_NEGINF;
}

__global__ void agg_decode_k(int total) {
    int i = blockIdx.x*blockDim.x + threadIdx.x;
    if (i >= total) return;
    float f = dec_f(g_aggenc[i]);
    if (!isfinite(f)) f = 0.0f;
    u16 h, l; split2(f, h, l);
    g_agh[i] = h; g_agl[i] = l;
}

__global__ void __launch_bounds__(512) attn_k(const float* __restrict__ qkv, int PER)
{
    __shared__ float Ks[128][32];
    __shared__ float Vs[128][32];
    int g = blockIdx.x, h = blockIdx.y;
    int tid = threadIdx.x;
    int n = g*PER + tid;
    const float scale = 0.17677669529663687f;
    float q[32];
    #pragma unroll
    for (int d = 0; d < 32; d++)
        q[d] = qkv[(size_t)n*384 + h*32 + d] * scale;

    float m = -INFINITY, l = 0.0f;
    float acc[32];
    #pragma unroll
    for (int d = 0; d < 32; d++) acc[d] = 0.0f;

    for (int c0 = 0; c0 < PER; c0 += 128) {
        __syncthreads();
        for (int i = tid; i < 128*32; i += 512) {
            int r = i >> 5, d = i & 31;
            size_t base = (size_t)(g*PER + c0 + r)*384 + h*32 + d;
            Ks[r][d] = qkv[base + 128];
            Vs[r][d] = qkv[base + 256];
        }
        __syncthreads();
        for (int j = 0; j < 128; j++) {
            float s = 0.0f;
            #pragma unroll
            for (int d = 0; d < 32; d++) s += q[d]*Ks[j][d];
            float mn = fmaxf(m, s);
            float a = fast_exp(m - mn);
            float p = fast_exp(s - mn);
            l = l*a + p;
            #pragma unroll
            for (int d = 0; d < 32; d++) acc[d] = acc[d]*a + p*Vs[j][d];
            m = mn;
        }
    }
    float inv = 1.0f / l;
    #pragma unroll
    for (int d = 0; d < 32; d += 2) {
        float vx = acc[d]*inv, vy = acc[d+1]*inv;
        u16 hx,lx,hy,ly; split2(vx,hx,lx); split2(vy,hy,ly);
        size_t idx = (size_t)n*HH + h*32 + d;
        *reinterpret_cast<uint32_t*>(g_oh + idx) = (uint32_t)hx | ((uint32_t)hy<<16);
        *reinterpret_cast<uint32_t*>(g_ol + idx) = (uint32_t)lx | ((uint32_t)ly<<16);
    }
}

__global__ void bn_stats1_k(const float* __restrict__ x, int ld, int rowsPer) {
    int c = threadIdx.x;
    int b = blockIdx.x;
    size_t r0 = (size_t)b * rowsPer;
    float s = 0.0f, s2 = 0.0f;
    for (int r = 0; r < rowsPer; r++) {
        float v = x[(r0 + r)*ld + c];
        s += v; s2 += v*v;
    }
    g_part[b*256 + c] = s;
    g_part[b*256 + 128 + c] = s2;
}
__global__ void bn_stats2_k(int nb, float invN) {
    int c = threadIdx.x;
    float s = 0.0f, s2 = 0.0f;
    for (int b = 0; b < nb; b++) { s += g_part[b*256 + c]; s2 += g_part[b*256 + 128 + c]; }
    float mu = s * invN;
    float var = s2 * invN - mu*mu;
    g_stats[c] = mu;
    g_stats[128 + c] = rsqrtf(var + 1e-5f);
}
__global__ void bn_apply_k(const float* __restrict__ x, int ld, const float* __restrict__ w,
                           const float* __restrict__ b, float* __restrict__ y, int total)
{
    int i = blockIdx.x*blockDim.x + threadIdx.x;
    if (i >= total) return;
    int c = i & 127;
    int row = i >> 7;
    y[i] = (x[(size_t)row*ld + c] - g_stats[c]) * g_stats[128 + c] * w[c] + b[c];
}

__global__ void add_split_k(const float* __restrict__ a, const float* __restrict__ b, int total)
{
    int i = blockIdx.x*blockDim.x + threadIdx.x;
    if (i >= total) return;
    float v = a[i] + b[i];
    g_out[i] = v;
    u16 h, l; split2(v, h, l);
    g_outh[i] = h; g_outl[i] = l;
}

// ---------------- host orchestration -----------------------------------------
template<int OUT, int ACT, bool BIAS, bool ACCUM, bool RESID, bool AF32>
static void run_gemm(const void* Ah, const u16* Al, int lda,
                     const u16* Bh, const u16* Bl, int ldb,
                     float* Cf, u16* Ch, u16* Cl, int ldc,
                     const float* bias, const float* resid,
                     const int* srcv, const int* dstv,
                     const float* zD, const float* zS, int ldz,
                     const float* GD, const float* cvec,
                     unsigned* aggenc, int M, int N, int K, int PER, int RB)
{
    auto kfn = gemm_ps<OUT,ACT,BIAS,ACCUM,RESID,AF32>;
    cudaFuncSetAttribute(kfn, cudaFuncAttributeMaxDynamicSharedMemorySize, 163840);
    size_t smemsz = (size_t)K*512 + 32768;
    int tilesM = (M + 63) / 64;
    int gy = (tilesM + RB - 1) / RB;
    dim3 grid(N/128, gy);
    kfn<<<grid, 256, smemsz>>>(Ah, Al, lda, Bh, Bl, ldb, Cf, Ch, Cl, ldc, bias, resid,
                               srcv, dstv, zD, zS, ldz, GD, cvec, aggenc, M, N, K, PER, tilesM, RB);
}

#define SYMADDR(p, s) cudaGetSymbolAddress((void**)&p, s)

extern "C" void kernel_launch(void* const* d_in, const int* in_sizes, int n_in,
                              void* d_out, int out_size)
{
    const float* node_fts  = (const float*)d_in[0];
    const float* edge_attr = (const float*)d_in[1];
    const float* graph_fts = (const float*)d_in[2];
    const float* hidden    = (const float*)d_in[3];
    const float* W_ee      = (const float*)d_in[4];
    const float* b_ee      = (const float*)d_in[5];
    const float* M0        = (const float*)d_in[6];
    const float* M1        = (const float*)d_in[7];
    const float* M2        = (const float*)d_in[8];
    const float* M3        = (const float*)d_in[9];
    const float* U1        = (const float*)d_in[10];
    const float* U2        = (const float*)d_in[11];
    const float* Wqkv      = (const float*)d_in[12];
    const float* bqkv      = (const float*)d_in[13];
    const float* Wo        = (const float*)d_in[14];
    const float* bo        = (const float*)d_in[15];
    const float* bn1_w     = (const float*)d_in[16];
    const float* bn1_b     = (const float*)d_in[17];
    const float* bn2_w     = (const float*)d_in[18];
    const float* bn2_b     = (const float*)d_in[19];
    const float* bn3_w     = (const float*)d_in[20];
    const float* bn3_b     = (const float*)d_in[21];
    const float* W1        = (const float*)d_in[22];
    const float* b1        = (const float*)d_in[23];
    const float* W2        = (const float*)d_in[24];
    const float* b2        = (const float*)d_in[25];
    const int*   edge_index= (const int*)d_in[26];

    const int N = in_sizes[0] / HH;
    const int E = in_sizes[1] / HH;
    const int G = in_sizes[2] / HH;
    const int PER = N / G;
    const int* src = edge_index;
    const int* dst = edge_index + E;
    float* outp = (float*)d_out;

    u16 *wZU_h,*wZU_l,*wM0c_h,*wM0c_l,*wM0d_h,*wM0d_l,*wee_h,*wee_l;
    u16 *wM1_h,*wM1_l,*wM2_h,*wM2_l,*wM3_h,*wM3_l,*wU2_h,*wU2_l;
    u16 *wQKV_h,*wQKV_l,*wWo_h,*wWo_l,*wW1_h,*wW1_l,*wW2_h,*wW2_l,*wC_h,*wC_l,*wG_h,*wG_l;
    u16 *z_h,*z_l,*m0h,*m0l,*m1h,*m1l,*agh,*agl,*oh,*ol,*outh,*outl,*mlp1h,*mlp1l;
    float *cvec,*GDp,*zc,*h1,*qkv,*t2,*h2,*outf,*out2;
    unsigned *aggenc;
    SYMADDR(wZU_h,g_wZU_h);   SYMADDR(wZU_l,g_wZU_l);
    SYMADDR(wM0c_h,g_wM0c_h); SYMADDR(wM0c_l,g_wM0c_l);
    SYMADDR(wM0d_h,g_wM0d_h); SYMADDR(wM0d_l,g_wM0d_l);
    SYMADDR(wee_h,g_wee_h);   SYMADDR(wee_l,g_wee_l);
    SYMADDR(wM1_h,g_wM1_h);   SYMADDR(wM1_l,g_wM1_l);
    SYMADDR(wM2_h,g_wM2_h);   SYMADDR(wM2_l,g_wM2_l);
    SYMADDR(wM3_h,g_wM3_h);   SYMADDR(wM3_l,g_wM3_l);
    SYMADDR(wU2_h,g_wU2_h);   SYMADDR(wU2_l,g_wU2_l);
    SYMADDR(wQKV_h,g_wQKV_h); SYMADDR(wQKV_l,g_wQKV_l);
    SYMADDR(wWo_h,g_wWo_h);   SYMADDR(wWo_l,g_wWo_l);
    SYMADDR(wW1_h,g_wW1_h);   SYMADDR(wW1_l,g_wW1_l);
    SYMADDR(wW2_h,g_wW2_h);   SYMADDR(wW2_l,g_wW2_l);
    SYMADDR(wC_h,g_wC_h);     SYMADDR(wC_l,g_wC_l);
    SYMADDR(wG_h,g_wG_h);     SYMADDR(wG_l,g_wG_l);
    SYMADDR(z_h,g_z_h);       SYMADDR(z_l,g_z_l);
    SYMADDR(m0h,g_m0h); SYMADDR(m0l,g_m0l); SYMADDR(m1h,g_m1h); SYMADDR(m1l,g_m1l);
    SYMADDR(agh,g_agh); SYMADDR(agl,g_agl); SYMADDR(oh,g_oh); SYMADDR(ol,g_ol);
    SYMADDR(outh,g_outh); SYMADDR(outl,g_outl); SYMADDR(mlp1h,g_mlp1h); SYMADDR(mlp1l,g_mlp1l);
    SYMADDR(cvec,g_cvec); SYMADDR(GDp,g_GD); SYMADDR(zc,g_zc);
    SYMADDR(h1,g_h1); SYMADDR(qkv,g_qkv); SYMADDR(t2,g_t2);
    SYMADDR(h2,g_h2); SYMADDR(outf,g_out); SYMADDR(out2,g_out2);
    SYMADDR(aggenc,g_aggenc);

    // ---- weight prep --------------------------------------------------------
    #define SPLIT(srcp, hp, lp, n) split_arr_k<<<((n)+255)/256, 256>>>(srcp, hp, lp, n)
    build_zu_k<<<(256*384 + 255)/256, 256>>>(M0, U1);
    SPLIT(M0 + (size_t)4*HH*HH,   wM0c_h, wM0c_l, HH*HH);
    SPLIT(M0 + (size_t)5*HH*HH,   wM0d_h, wM0d_l, HH*HH);
    SPLIT(W_ee,                   wee_h,  wee_l,  HH*HH);
    SPLIT(M1, wM1_h, wM1_l, HH*HH);
    SPLIT(M2, wM2_h, wM2_l, HH*HH);
    SPLIT(M3, wM3_h, wM3_l, HH*HH);
    SPLIT(U2, wU2_h, wU2_l, HH*HH);
    SPLIT(Wqkv, wQKV_h, wQKV_l, 3*HH*HH);
    SPLIT(Wo, wWo_h, wWo_l, HH*HH);
    SPLIT(W1, wW1_h, wW1_l, 2*HH*HH);
    SPLIT(W2, wW2_h, wW2_l, 2*HH*HH);
    SPLIT(graph_fts, wG_h, wG_l, G*HH);
    cvec_k<<<1, HH>>>(b_ee, M0);
    split_z_k<<<(N*256 + 255)/256, 256>>>(node_fts, hidden, N*256);
    agg_init_k<<<(N*HH + 255)/256, 256>>>(N*HH);

    // ---- C = W_ee @ M0c (split out); GD = graph_fts @ M0d ------------------
    run_gemm<1,0,false,false,false,false>(wee_h, wee_l, HH, wM0c_h, wM0c_l, HH,
        nullptr, wC_h, wC_l, HH, nullptr, nullptr, nullptr, nullptr,
        nullptr, nullptr, 0, nullptr, nullptr, nullptr, HH, HH, HH, PER, 8);
    run_gemm<0,0,false,false,false,false>(wG_h, wG_l, HH, wM0d_h, wM0d_l, HH,
        GDp, nullptr, nullptr, HH, nullptr, nullptr, nullptr, nullptr,
        nullptr, nullptr, 0, nullptr, nullptr, nullptr, G, HH, HH, PER, 8);

    // ---- combined [zD | zS | t1] = z @ [M0a | M0b | U1]  (K=256, N=384) ----
    run_gemm<0,0,false,false,false,false>(z_h, z_l, 256, wZU_h, wZU_l, 384,
        zc, nullptr, nullptr, 384, nullptr, nullptr, nullptr, nullptr,
        nullptr, nullptr, 0, nullptr, nullptr, nullptr, N, 384, 256, PER, 8);

    // ---- e0 GEMM + fused gather ------------------------------------------
    run_gemm<3,0,false,false,false,true>(edge_attr, nullptr, HH, wC_h, wC_l, HH,
        nullptr, m0h, m0l, HH, nullptr, nullptr, src, dst,
        zc, zc + 128, 384, GDp, cvec, nullptr, E, HH, HH, PER, 8);

    // ---- M1, M2 (split+leaky), M3 (fused segment-max atomics) --------------
    run_gemm<1,2,false,false,false,false>(m0h, m0l, HH, wM1_h, wM1_l, HH,
        nullptr, m1h, m1l, HH, nullptr, nullptr, nullptr, nullptr,
        nullptr, nullptr, 0, nullptr, nullptr, nullptr, E, HH, HH, PER, 8);
    run_gemm<1,2,false,false,false,false>(m1h, m1l, HH, wM2_h, wM2_l, HH,
        nullptr, m0h, m0l, HH, nullptr, nullptr, nullptr, nullptr,
        nullptr, nullptr, 0, nullptr, nullptr, nullptr, E, HH, HH, PER, 8);
    run_gemm<2,0,false,false,false,false>(m0h, m0l, HH, wM3_h, wM3_l, HH,
        nullptr, nullptr, nullptr, HH, nullptr, nullptr, nullptr, dst,
        nullptr, nullptr, 0, nullptr, nullptr, aggenc, E, HH, HH, PER, 8);
    agg_decode_k<<<(N*HH + 255)/256, 256>>>(N*HH);

    // ---- h1 = BN1(t1 + agg@U2 + node_fts);  t1 lives in zc cols 256.. ------
    run_gemm<0,0,false,true,true,false>(agh, agl, HH, wU2_h, wU2_l, HH,
        zc + 256, nullptr, nullptr, 384, nullptr, node_fts, nullptr, nullptr,
        nullptr, nullptr, 0, nullptr, nullptr, nullptr, N, HH, HH, PER, 8);
    {
        bn_stats1_k<<<256, 128>>>(zc + 256, 384, N/256);
        bn_stats2_k<<<1, 128>>>(256, 1.0f/(float)N);
        bn_apply_k<<<(N*HH + 255)/256, 256>>>(zc + 256, 384, bn1_w, bn1_b, h1, N*HH);
    }

    // ---- attention ---------------------------------------------------------
    run_gemm<0,0,true,false,false,false>(z_h, z_l, 256, wQKV_h, wQKV_l, 3*HH,
        qkv, nullptr, nullptr, 3*HH, bqkv, nullptr, nullptr, nullptr,
        nullptr, nullptr, 0, nullptr, nullptr, nullptr, N, 3*HH, HH, PER, 8);
    attn_k<<<dim3(G, 4), PER>>>(qkv, PER);
    run_gemm<0,0,true,false,true,false>(oh, ol, HH, wWo_h, wWo_l, HH,
        t2, nullptr, nullptr, HH, bo, node_fts, nullptr, nullptr,
        nullptr, nullptr, 0, nullptr, nullptr, nullptr, N, HH, HH, PER, 8);
    {
        bn_stats1_k<<<256, 128>>>(t2, HH, N/256);
        bn_stats2_k<<<1, 128>>>(256, 1.0f/(float)N);
        bn_apply_k<<<(N*HH + 255)/256, 256>>>(t2, HH, bn2_w, bn2_b, h2, N*HH);
    }

    // ---- combine + MLP ------------------------------------------------------
    add_split_k<<<(N*HH + 255)/256, 256>>>(h1, h2, N*HH);
    run_gemm<1,1,true,false,false,false>(outh, outl, HH, wW1_h, wW1_l, 2*HH,
        nullptr, mlp1h, mlp1l, 2*HH, b1, nullptr, nullptr, nullptr,
        nullptr, nullptr, 0, nullptr, nullptr, nullptr, N, 2*HH, HH, PER, 8);
    run_gemm<0,0,true,false,true,false>(mlp1h, mlp1l, 2*HH, wW2_h, wW2_l, HH,
        out2, nullptr, nullptr, HH, b2, outf, nullptr, nullptr,
        nullptr, nullptr, 0, nullptr, nullptr, nullptr, N, HH, 2*HH, PER, 8);

    // ---- BN3 -> output ------------------------------------------------------
    {
        bn_stats1_k<<<256, 128>>>(out2, HH, N/256);
        bn_stats2_k<<<1, 128>>>(256, 1.0f/(float)N);
        bn_apply_k<<<(N*HH + 255)/256, 256>>>(out2, HH, bn3_w, bn3_b, outp, N*HH);
    }
}

// round 9
// speedup vs baseline: 1.0703x; 1.0703x over previous
#include <cuda_runtime.h>
#include <cuda_bf16.h>
#include <math.h>
#include <stdint.h>

typedef unsigned short u16;

// Problem constants
#define NN 32768
#define EE 262144
#define GG 64
#define HH 128

// ---------------- scratch ----------------------------------------------------
__device__ u16 g_wZU_h[256*384],  g_wZU_l[256*384];   // combined [zD | zS | U1] B
__device__ u16 g_wM0c_h[HH*HH],   g_wM0c_l[HH*HH];
__device__ u16 g_wM0d_h[HH*HH],   g_wM0d_l[HH*HH];
__device__ u16 g_wee_h[HH*HH],    g_wee_l[HH*HH];
__device__ u16 g_wM1_h[HH*HH],    g_wM1_l[HH*HH];
__device__ u16 g_wM2_h[HH*HH],    g_wM2_l[HH*HH];
__device__ u16 g_wM3_h[HH*HH],    g_wM3_l[HH*HH];
__device__ u16 g_wU2_h[HH*HH],    g_wU2_l[HH*HH];
__device__ u16 g_wQKV_h[3*HH*HH], g_wQKV_l[3*HH*HH];
__device__ u16 g_wWo_h[HH*HH],    g_wWo_l[HH*HH];
__device__ u16 g_wW1_h[2*HH*HH],  g_wW1_l[2*HH*HH];
__device__ u16 g_wW2_h[2*HH*HH],  g_wW2_l[2*HH*HH];
__device__ u16 g_wC_h[HH*HH],     g_wC_l[HH*HH];      // C = W_ee@M0c split
__device__ u16 g_wG_h[GG*HH],     g_wG_l[GG*HH];      // graph_fts split
// activations
__device__ float g_cvec[HH];
__device__ float g_GD[GG*HH];
__device__ float g_zc[(size_t)NN*384];                // [zD | zS | t1] strided 384
__device__ u16 g_z_h[NN*2*HH], g_z_l[NN*2*HH];
__device__ u16 g_m0h[(size_t)EE*HH], g_m0l[(size_t)EE*HH];
__device__ u16 g_m1h[(size_t)EE*HH], g_m1l[(size_t)EE*HH];
__device__ unsigned g_aggenc[NN*HH];
__device__ u16 g_agh[NN*HH], g_agl[NN*HH];
__device__ float g_qkv[NN*3*HH];
__device__ u16 g_oh[NN*HH], g_ol[NN*HH];
__device__ float g_t2[NN*HH];
__device__ float g_out[NN*HH];
__device__ u16 g_outh[NN*HH], g_outl[NN*HH];
__device__ u16 g_mlp1h[NN*2*HH], g_mlp1l[NN*2*HH];
__device__ float g_out2[NN*HH];
__device__ float g_part[256*256];
__device__ float g_stats[512];     // [0:256) = BN1 (mu, rstd), [256:512) = BN2

// ---------------- helpers ----------------------------------------------------
__device__ __forceinline__ float leaky_f(float v) { return v > 0.0f ? v : 0.01f*v; }

__device__ __forceinline__ float fast_exp(float x) {
    x = fmaxf(x, -87.0f);
    float t  = x * 1.4426950408889634f;
    float fl = floorf(t);
    float f  = t - fl;
    float p  =            1.339077600e-4f;
    p = p * f + 9.618437357e-4f;
    p = p * f + 9.556031144e-3f;
    p = p * f + 5.550332471e-2f;
    p = p * f + 2.402264923e-1f;
    p = p * f + 6.931471825e-1f;
    p = p * f + 1.0f;
    int ei = (int)fl;
    return __int_as_float((ei + 127) << 23) * p;
}

__device__ __forceinline__ unsigned enc_f(float f) {
    unsigned u = __float_as_uint(f);
    return (u & 0x80000000u) ? ~u : (u | 0x80000000u);
}
__device__ __forceinline__ float dec_f(unsigned u) {
    return (u & 0x80000000u) ? __uint_as_float(u ^ 0x80000000u) : __uint_as_float(~u);
}
#define ENC_NEGINF 0x007FFFFFu

__device__ __forceinline__ uint32_t smem_u32(const void* p) {
    uint32_t a;
    asm("{ .reg .u64 t; cvta.to.shared.u64 t, %1; cvt.u32.u64 %0, t; }" : "=r"(a) : "l"(p));
    return a;
}

__device__ __forceinline__ void split2(float v, u16& hi, u16& lo) {
    __nv_bfloat16 h = __float2bfloat16(v);
    float r = v - __bfloat162float(h);
    __nv_bfloat16 l = __float2bfloat16(r);
    hi = *reinterpret_cast<u16*>(&h);
    lo = *reinterpret_cast<u16*>(&l);
}

// ---------------- MMA building blocks ----------------------------------------
#define LDM_X4(r, a) \
    asm volatile("ldmatrix.sync.aligned.m8n8.x4.shared.b16 {%0,%1,%2,%3}, [%4];" \
        : "=r"((r)[0]), "=r"((r)[1]), "=r"((r)[2]), "=r"((r)[3]) : "r"(a))
#define LDM_X4T(r, a) \
    asm volatile("ldmatrix.sync.aligned.m8n8.x4.trans.shared.b16 {%0,%1,%2,%3}, [%4];" \
        : "=r"((r)[0]), "=r"((r)[1]), "=r"((r)[2]), "=r"((r)[3]) : "r"(a))
#define MMA16816(c, a, b) \
    asm volatile("mma.sync.aligned.m16n8k16.row.col.f32.bf16.bf16.f32 " \
        "{%0,%1,%2,%3}, {%4,%5,%6,%7}, {%8,%9}, {%0,%1,%2,%3};" \
        : "+f"((c)[0]), "+f"((c)[1]), "+f"((c)[2]), "+f"((c)[3]) \
        : "r"((a)[0]), "r"((a)[1]), "r"((a)[2]), "r"((a)[3]), "r"((b)[0]), "r"((b)[1]))

#define CPA16(dst, src) asm volatile("cp.async.cg.shared.global [%0], [%1], 16;" :: "r"(dst), "l"(src))
#define CPA_COMMIT()    asm volatile("cp.async.commit_group;")
#define CPA_WAIT0()     asm volatile("cp.async.wait_group 0;" ::: "memory")

// XOR-swizzled offset inside a tile: rows of 256B, 16B chunks 0..15
__device__ __forceinline__ uint32_t swz(int row, int cb) {
    return (uint32_t)((row << 8) + (((cb ^ row) & 7) << 4) + ((cb & 8) << 4));
}

// ---------------- split-bf16 3-pass GEMM on mma.sync --------------------------
// Tile 64(M) x 128(N); 8 warps = 2x4; warp tile 32x32. RB M-subtiles reuse B.
template<int OUT, int ACT, bool BIAS, bool ACCUM, bool RESID, bool AF32>
__global__ void __launch_bounds__(256,2) gemm_ps(
    const void* Ah_, const u16* Al, int lda,
    const u16* __restrict__ Bh, const u16* __restrict__ Bl, int ldb,
    float* Cf, u16* Ch, u16* Cl, int ldc,
    const float* __restrict__ bias, const float* __restrict__ resid,
    const int* __restrict__ srcv, const int* __restrict__ dstv,
    const float* __restrict__ zD, const float* __restrict__ zS, int ldz,
    const float* __restrict__ GD, const float* __restrict__ cvec,
    unsigned* aggenc, int M, int N, int K, int PER, int tilesM, int RB)
{
    extern __shared__ char smem[];
    uint32_t sb = smem_u32(smem);
    const int tid = threadIdx.x;
    const int lane = tid & 31, w = tid >> 5;
    const int wm = w >> 2, wn = w & 3;
    const int ncol0 = blockIdx.x << 7;

    const uint32_t offB_h = 0;
    const uint32_t offB_l = (uint32_t)K * 256;
    const uint32_t offA_h = (uint32_t)K * 512;
    const uint32_t offA_l = offA_h + 16384;

    int ty0 = blockIdx.y * RB;
    int tyEnd = ty0 + RB; if (tyEnd > tilesM) tyEnd = tilesM;

    auto fillA = [&](int ty, int kc) {
        int mrow0 = ty << 6;
        if (AF32) {
            const float* Af = (const float*)Ah_;
            for (int idx = tid; idx < 64 * 16; idx += 256) {
                int row = idx >> 4, cb = idx & 15;
                const float* ap = Af + (size_t)(mrow0 + row) * lda + kc + cb * 8;
                float4 v0 = *reinterpret_cast<const float4*>(ap);
                float4 v1 = *reinterpret_cast<const float4*>(ap + 4);
                u16 h[8], l[8];
                split2(v0.x,h[0],l[0]); split2(v0.y,h[1],l[1]);
                split2(v0.z,h[2],l[2]); split2(v0.w,h[3],l[3]);
                split2(v1.x,h[4],l[4]); split2(v1.y,h[5],l[5]);
                split2(v1.z,h[6],l[6]); split2(v1.w,h[7],l[7]);
                uint32_t d = swz(row, cb);
                *reinterpret_cast<uint4*>(smem + offA_h + d) = make_uint4(
                    (uint32_t)h[0]|((uint32_t)h[1]<<16), (uint32_t)h[2]|((uint32_t)h[3]<<16),
                    (uint32_t)h[4]|((uint32_t)h[5]<<16), (uint32_t)h[6]|((uint32_t)h[7]<<16));
                *reinterpret_cast<uint4*>(smem + offA_l + d) = make_uint4(
                    (uint32_t)l[0]|((uint32_t)l[1]<<16), (uint32_t)l[2]|((uint32_t)l[3]<<16),
                    (uint32_t)l[4]|((uint32_t)l[5]<<16), (uint32_t)l[6]|((uint32_t)l[7]<<16));
            }
        } else {
            const u16* Ah = (const u16*)Ah_;
            for (int idx = tid; idx < 64 * 16; idx += 256) {
                int row = idx >> 4, cb = idx & 15;
                size_t so = (size_t)(mrow0 + row) * lda + kc + cb * 8;
                uint32_t d = swz(row, cb);
                CPA16(sb + offA_h + d, Ah + so);
                CPA16(sb + offA_l + d, Al + so);
            }
            CPA_COMMIT();
        }
    };

    // ---- B fill (whole K) + first A chunk ----
    for (int idx = tid; idx < K * 16; idx += 256) {
        int row = idx >> 4, cb = idx & 15;
        size_t so = (size_t)row * ldb + ncol0 + cb * 8;
        uint32_t d = swz(row, cb);
        CPA16(sb + offB_h + d, Bh + so);
        CPA16(sb + offB_l + d, Bl + so);
    }
    CPA_COMMIT();
    fillA(ty0, 0);

    for (int ty = ty0; ty < tyEnd; ty++) {
        const int mrow0 = ty << 6;
        float acc[2][4][4];
        #pragma unroll
        for (int i = 0; i < 2; i++)
            #pragma unroll
            for (int j = 0; j < 4; j++)
                #pragma unroll
                for (int q = 0; q < 4; q++) acc[i][j][q] = 0.0f;

        for (int kc = 0; kc < K; kc += 128) {
            CPA_WAIT0();
            __syncthreads();

            #pragma unroll
            for (int kk = 0; kk < 8; kk++) {
                uint32_t ah[2][4], al[2][4];
                #pragma unroll
                for (int i = 0; i < 2; i++) {
                    int row = wm*32 + i*16 + (lane & 15);
                    uint32_t ad = sb + offA_h + swz(row, kk*2 + (lane >> 4));
                    LDM_X4(ah[i], ad);
                    LDM_X4(al[i], ad + 16384);
                }
                uint32_t bh[4][2], bl[4][2];
                #pragma unroll
                for (int jj = 0; jj < 2; jj++) {
                    int krow = kc + kk*16 + (lane & 15);
                    uint32_t bd = sb + offB_h + swz(krow, wn*4 + jj*2 + (lane >> 4));
                    uint32_t t[4];
                    LDM_X4T(t, bd);
                    bh[jj*2][0]=t[0]; bh[jj*2][1]=t[1]; bh[jj*2+1][0]=t[2]; bh[jj*2+1][1]=t[3];
                    LDM_X4T(t, bd + offB_l);
                    bl[jj*2][0]=t[0]; bl[jj*2][1]=t[1]; bl[jj*2+1][0]=t[2]; bl[jj*2+1][1]=t[3];
                }
                #pragma unroll
                for (int i = 0; i < 2; i++)
                    #pragma unroll
                    for (int j = 0; j < 4; j++) {
                        MMA16816(acc[i][j], ah[i], bh[j]);
                        MMA16816(acc[i][j], ah[i], bl[j]);
                        MMA16816(acc[i][j], al[i], bh[j]);
                    }
            }
            __syncthreads();
            // prefetch next chunk / next subtile (overlaps epilogue below)
            if (kc + 128 < K) fillA(ty, kc + 128);
            else if (ty + 1 < tyEnd) fillA(ty + 1, 0);
        }

        // ---- epilogue ----
        #pragma unroll
        for (int i = 0; i < 2; i++) {
            int r0 = mrow0 + wm*32 + i*16 + (lane >> 2);
            #pragma unroll
            for (int half = 0; half < 2; half++) {
                int r = r0 + half*8;
                int sidx = 0, didx = 0, gidx = 0;
                if (OUT == 2 || OUT == 3) didx = dstv[r];
                if (OUT == 3) { sidx = srcv[r]; gidx = didx / PER; }
                #pragma unroll
                for (int j = 0; j < 4; j++) {
                    int c = ncol0 + wn*32 + j*8 + (lane & 3)*2;
                    size_t idx = (size_t)r * ldc + c;
                    float vx = acc[i][j][half*2], vy = acc[i][j][half*2 + 1];
                    if (BIAS)  { vx += bias[c]; vy += bias[c + 1]; }
                    if (OUT == 3) {
                        vx += zD[(size_t)didx*ldz + c] + zS[(size_t)sidx*ldz + c]
                            + GD[(size_t)gidx*HH + c] + cvec[c];
                        vy += zD[(size_t)didx*ldz + c+1] + zS[(size_t)sidx*ldz + c+1]
                            + GD[(size_t)gidx*HH + c+1] + cvec[c+1];
                        vx = leaky_f(vx); vy = leaky_f(vy);
                        u16 hx,lx,hy,ly; split2(vx,hx,lx); split2(vy,hy,ly);
                        *reinterpret_cast<uint32_t*>(Ch + idx) = (uint32_t)hx | ((uint32_t)hy<<16);
                        *reinterpret_cast<uint32_t*>(Cl + idx) = (uint32_t)lx | ((uint32_t)ly<<16);
                    } else if (OUT == 2) {
                        atomicMax(&aggenc[didx*HH + c],   enc_f(vx));
                        atomicMax(&aggenc[didx*HH + c+1], enc_f(vy));
                    } else {
                        if (ACCUM) { float2 t = *reinterpret_cast<float2*>(Cf + idx); vx += t.x; vy += t.y; }
                        if (RESID) { float2 t = *reinterpret_cast<const float2*>(resid + (size_t)r*HH + c); vx += t.x; vy += t.y; }
                        if (ACT == 1) { vx = fmaxf(vx, 0.f); vy = fmaxf(vy, 0.f); }
                        else if (ACT == 2) { vx = leaky_f(vx); vy = leaky_f(vy); }
                        if (OUT == 1) {
                            u16 hx,lx,hy,ly; split2(vx,hx,lx); split2(vy,hy,ly);
                            *reinterpret_cast<uint32_t*>(Ch + idx) = (uint32_t)hx | ((uint32_t)hy<<16);
                            *reinterpret_cast<uint32_t*>(Cl + idx) = (uint32_t)lx | ((uint32_t)ly<<16);
                        } else {
                            *reinterpret_cast<float2*>(Cf + idx) = make_float2(vx, vy);
                        }
                    }
                }
            }
        }
    }
}

// ---------------- small kernels ----------------------------------------------
__global__ void split_arr_k(const float* __restrict__ src, u16* __restrict__ hi,
                            u16* __restrict__ lo, int n)
{
    int i = blockIdx.x*blockDim.x + threadIdx.x;
    if (i >= n) return;
    u16 h, l; split2(src[i], h, l);
    hi[i] = h; lo[i] = l;
}

__global__ void build_zu_k(const float* __restrict__ M0, const float* __restrict__ U1)
{
    int i = blockIdx.x*blockDim.x + threadIdx.x;
    if (i >= 256*384) return;
    int k = i / 384, c = i - k*384;
    float v;
    if (c < 128)       v = M0[(size_t)k*HH + c];
    else if (c < 256)  v = M0[(size_t)(256 + k)*HH + (c - 128)];
    else               v = U1[(size_t)k*HH + (c - 256)];
    u16 h, l; split2(v, h, l);
    g_wZU_h[i] = h; g_wZU_l[i] = l;
}

__global__ void split_z_k(const float* __restrict__ node, const float* __restrict__ hid, int n)
{
    int i = blockIdx.x*blockDim.x + threadIdx.x;
    if (i >= n) return;
    int row = i >> 8, col = i & 255;
    float v = (col < 128) ? node[row*HH + col] : hid[row*HH + col - 128];
    u16 h, l; split2(v, h, l);
    g_z_h[i] = h; g_z_l[i] = l;
}

__global__ void cvec_k(const float* __restrict__ b_ee, const float* __restrict__ M0) {
    int j = threadIdx.x;
    float s = 0.0f;
    for (int t = 0; t < HH; t++) s += b_ee[t] * M0[(size_t)(4*HH + t)*HH + j];
    g_cvec[j] = s;
}

__global__ void agg_init_k(int total) {
    int i = blockIdx.x*blockDim.x + threadIdx.x;
    if (i < total) g_aggenc[i] = ENC_NEGINF;
}

__global__ void agg_decode_k(int total) {
    int i = blockIdx.x*blockDim.x + threadIdx.x;
    if (i >= total) return;
    float f = dec_f(g_aggenc[i]);
    if (!isfinite(f)) f = 0.0f;
    u16 h, l; split2(f, h, l);
    g_agh[i] = h; g_agl[i] = l;
}

__global__ void __launch_bounds__(512) attn_k(const float* __restrict__ qkv, int PER)
{
    __shared__ float Ks[128][32];
    __shared__ float Vs[128][32];
    int g = blockIdx.x, h = blockIdx.y;
    int tid = threadIdx.x;
    int n = g*PER + tid;
    const float scale = 0.17677669529663687f;
    float q[32];
    #pragma unroll
    for (int d = 0; d < 32; d++)
        q[d] = qkv[(size_t)n*384 + h*32 + d] * scale;

    float m = -INFINITY, l = 0.0f;
    float acc[32];
    #pragma unroll
    for (int d = 0; d < 32; d++) acc[d] = 0.0f;

    for (int c0 = 0; c0 < PER; c0 += 128) {
        __syncthreads();
        for (int i = tid; i < 128*32; i += 512) {
            int r = i >> 5, d = i & 31;
            size_t base = (size_t)(g*PER + c0 + r)*384 + h*32 + d;
            Ks[r][d] = qkv[base + 128];
            Vs[r][d] = qkv[base + 256];
        }
        __syncthreads();
        for (int j = 0; j < 128; j++) {
            float s = 0.0f;
            #pragma unroll
            for (int d = 0; d < 32; d++) s += q[d]*Ks[j][d];
            float mn = fmaxf(m, s);
            float a = fast_exp(m - mn);
            float p = fast_exp(s - mn);
            l = l*a + p;
            #pragma unroll
            for (int d = 0; d < 32; d++) acc[d] = acc[d]*a + p*Vs[j][d];
            m = mn;
        }
    }
    float inv = 1.0f / l;
    #pragma unroll
    for (int d = 0; d < 32; d += 2) {
        float vx = acc[d]*inv, vy = acc[d+1]*inv;
        u16 hx,lx,hy,ly; split2(vx,hx,lx); split2(vy,hy,ly);
        size_t idx = (size_t)n*HH + h*32 + d;
        *reinterpret_cast<uint32_t*>(g_oh + idx) = (uint32_t)hx | ((uint32_t)hy<<16);
        *reinterpret_cast<uint32_t*>(g_ol + idx) = (uint32_t)lx | ((uint32_t)ly<<16);
    }
}

__global__ void bn_stats1_k(const float* __restrict__ x, int ld, int rowsPer) {
    int c = threadIdx.x;
    int b = blockIdx.x;
    size_t r0 = (size_t)b * rowsPer;
    float s = 0.0f, s2 = 0.0f;
    for (int r = 0; r < rowsPer; r++) {
        float v = x[(r0 + r)*ld + c];
        s += v; s2 += v*v;
    }
    g_part[b*256 + c] = s;
    g_part[b*256 + 128 + c] = s2;
}
__global__ void bn_stats2_k(int nb, float invN, int sbase) {
    int c = threadIdx.x;
    float s = 0.0f, s2 = 0.0f;
    for (int b = 0; b < nb; b++) { s += g_part[b*256 + c]; s2 += g_part[b*256 + 128 + c]; }
    float mu = s * invN;
    float var = s2 * invN - mu*mu;
    g_stats[sbase + c] = mu;
    g_stats[sbase + 128 + c] = rsqrtf(var + 1e-5f);
}
__global__ void bn_apply_k(const float* __restrict__ x, int ld, const float* __restrict__ w,
                           const float* __restrict__ b, float* __restrict__ y, int total)
{
    int i = blockIdx.x*blockDim.x + threadIdx.x;
    if (i >= total) return;
    int c = i & 127;
    int row = i >> 7;
    y[i] = (x[(size_t)row*ld + c] - g_stats[c]) * g_stats[128 + c] * w[c] + b[c];
}

// fused: out = BN1(t1) + BN2(t2); writes fp32 + split hi/lo
__global__ void bn12_add_split_k(const float* __restrict__ t1, int ld1,
                                 const float* __restrict__ t2,
                                 const float* __restrict__ w1, const float* __restrict__ b1,
                                 const float* __restrict__ w2, const float* __restrict__ b2,
                                 int total)
{
    int i = blockIdx.x*blockDim.x + threadIdx.x;
    if (i >= total) return;
    int c = i & 127;
    int row = i >> 7;
    float v1 = (t1[(size_t)row*ld1 + c] - g_stats[c])       * g_stats[128 + c] * w1[c] + b1[c];
    float v2 = (t2[i]                   - g_stats[256 + c]) * g_stats[384 + c] * w2[c] + b2[c];
    float v = v1 + v2;
    g_out[i] = v;
    u16 h, l; split2(v, h, l);
    g_outh[i] = h; g_outl[i] = l;
}

// ---------------- host orchestration -----------------------------------------
template<int OUT, int ACT, bool BIAS, bool ACCUM, bool RESID, bool AF32>
static void run_gemm(const void* Ah, const u16* Al, int lda,
                     const u16* Bh, const u16* Bl, int ldb,
                     float* Cf, u16* Ch, u16* Cl, int ldc,
                     const float* bias, const float* resid,
                     const int* srcv, const int* dstv,
                     const float* zD, const float* zS, int ldz,
                     const float* GD, const float* cvec,
                     unsigned* aggenc, int M, int N, int K, int PER)
{
    auto kfn = gemm_ps<OUT,ACT,BIAS,ACCUM,RESID,AF32>;
    cudaFuncSetAttribute(kfn, cudaFuncAttributeMaxDynamicSharedMemorySize, 163840);
    size_t smemsz = (size_t)K*512 + 32768;
    int tilesM = (M + 63) / 64;
    int tilesN = N / 128;
    // adaptive B-reuse: keep >= ~304 CTAs (2 per SM) in flight
    int RB = (tilesM * tilesN) / 304;
    if (RB < 1) RB = 1;
    if (RB > 8) RB = 8;
    int gy = (tilesM + RB - 1) / RB;
    dim3 grid(tilesN, gy);
    kfn<<<grid, 256, smemsz>>>(Ah, Al, lda, Bh, Bl, ldb, Cf, Ch, Cl, ldc, bias, resid,
                               srcv, dstv, zD, zS, ldz, GD, cvec, aggenc, M, N, K, PER, tilesM, RB);
}

#define SYMADDR(p, s) cudaGetSymbolAddress((void**)&p, s)

extern "C" void kernel_launch(void* const* d_in, const int* in_sizes, int n_in,
                              void* d_out, int out_size)
{
    const float* node_fts  = (const float*)d_in[0];
    const float* edge_attr = (const float*)d_in[1];
    const float* graph_fts = (const float*)d_in[2];
    const float* hidden    = (const float*)d_in[3];
    const float* W_ee      = (const float*)d_in[4];
    const float* b_ee      = (const float*)d_in[5];
    const float* M0        = (const float*)d_in[6];
    const float* M1        = (const float*)d_in[7];
    const float* M2        = (const float*)d_in[8];
    const float* M3        = (const float*)d_in[9];
    const float* U1        = (const float*)d_in[10];
    const float* U2        = (const float*)d_in[11];
    const float* Wqkv      = (const float*)d_in[12];
    const float* bqkv      = (const float*)d_in[13];
    const float* Wo        = (const float*)d_in[14];
    const float* bo        = (const float*)d_in[15];
    const float* bn1_w     = (const float*)d_in[16];
    const float* bn1_b     = (const float*)d_in[17];
    const float* bn2_w     = (const float*)d_in[18];
    const float* bn2_b     = (const float*)d_in[19];
    const float* bn3_w     = (const float*)d_in[20];
    const float* bn3_b     = (const float*)d_in[21];
    const float* W1        = (const float*)d_in[22];
    const float* b1        = (const float*)d_in[23];
    const float* W2        = (const float*)d_in[24];
    const float* b2        = (const float*)d_in[25];
    const int*   edge_index= (const int*)d_in[26];

    const int N = in_sizes[0] / HH;
    const int E = in_sizes[1] / HH;
    const int G = in_sizes[2] / HH;
    const int PER = N / G;
    const int* src = edge_index;
    const int* dst = edge_index + E;
    float* outp = (float*)d_out;

    u16 *wZU_h,*wZU_l,*wM0c_h,*wM0c_l,*wM0d_h,*wM0d_l,*wee_h,*wee_l;
    u16 *wM1_h,*wM1_l,*wM2_h,*wM2_l,*wM3_h,*wM3_l,*wU2_h,*wU2_l;
    u16 *wQKV_h,*wQKV_l,*wWo_h,*wWo_l,*wW1_h,*wW1_l,*wW2_h,*wW2_l,*wC_h,*wC_l,*wG_h,*wG_l;
    u16 *z_h,*z_l,*m0h,*m0l,*m1h,*m1l,*agh,*agl,*oh,*ol,*outh,*outl,*mlp1h,*mlp1l;
    float *cvec,*GDp,*zc,*qkv,*t2,*outf,*out2;
    unsigned *aggenc;
    SYMADDR(wZU_h,g_wZU_h);   SYMADDR(wZU_l,g_wZU_l);
    SYMADDR(wM0c_h,g_wM0c_h); SYMADDR(wM0c_l,g_wM0c_l);
    SYMADDR(wM0d_h,g_wM0d_h); SYMADDR(wM0d_l,g_wM0d_l);
    SYMADDR(wee_h,g_wee_h);   SYMADDR(wee_l,g_wee_l);
    SYMADDR(wM1_h,g_wM1_h);   SYMADDR(wM1_l,g_wM1_l);
    SYMADDR(wM2_h,g_wM2_h);   SYMADDR(wM2_l,g_wM2_l);
    SYMADDR(wM3_h,g_wM3_h);   SYMADDR(wM3_l,g_wM3_l);
    SYMADDR(wU2_h,g_wU2_h);   SYMADDR(wU2_l,g_wU2_l);
    SYMADDR(wQKV_h,g_wQKV_h); SYMADDR(wQKV_l,g_wQKV_l);
    SYMADDR(wWo_h,g_wWo_h);   SYMADDR(wWo_l,g_wWo_l);
    SYMADDR(wW1_h,g_wW1_h);   SYMADDR(wW1_l,g_wW1_l);
    SYMADDR(wW2_h,g_wW2_h);   SYMADDR(wW2_l,g_wW2_l);
    SYMADDR(wC_h,g_wC_h);     SYMADDR(wC_l,g_wC_l);
    SYMADDR(wG_h,g_wG_h);     SYMADDR(wG_l,g_wG_l);
    SYMADDR(z_h,g_z_h);       SYMADDR(z_l,g_z_l);
    SYMADDR(m0h,g_m0h); SYMADDR(m0l,g_m0l); SYMADDR(m1h,g_m1h); SYMADDR(m1l,g_m1l);
    SYMADDR(agh,g_agh); SYMADDR(agl,g_agl); SYMADDR(oh,g_oh); SYMADDR(ol,g_ol);
    SYMADDR(outh,g_outh); SYMADDR(outl,g_outl); SYMADDR(mlp1h,g_mlp1h); SYMADDR(mlp1l,g_mlp1l);
    SYMADDR(cvec,g_cvec); SYMADDR(GDp,g_GD); SYMADDR(zc,g_zc);
    SYMADDR(qkv,g_qkv); SYMADDR(t2,g_t2);
    SYMADDR(outf,g_out); SYMADDR(out2,g_out2);
    SYMADDR(aggenc,g_aggenc);

    // ---- weight prep --------------------------------------------------------
    #define SPLIT(srcp, hp, lp, n) split_arr_k<<<((n)+255)/256, 256>>>(srcp, hp, lp, n)
    build_zu_k<<<(256*384 + 255)/256, 256>>>(M0, U1);
    SPLIT(M0 + (size_t)4*HH*HH,   wM0c_h, wM0c_l, HH*HH);
    SPLIT(M0 + (size_t)5*HH*HH,   wM0d_h, wM0d_l, HH*HH);
    SPLIT(W_ee,                   wee_h,  wee_l,  HH*HH);
    SPLIT(M1, wM1_h, wM1_l, HH*HH);
    SPLIT(M2, wM2_h, wM2_l, HH*HH);
    SPLIT(M3, wM3_h, wM3_l, HH*HH);
    SPLIT(U2, wU2_h, wU2_l, HH*HH);
    SPLIT(Wqkv, wQKV_h, wQKV_l, 3*HH*HH);
    SPLIT(Wo, wWo_h, wWo_l, HH*HH);
    SPLIT(W1, wW1_h, wW1_l, 2*HH*HH);
    SPLIT(W2, wW2_h, wW2_l, 2*HH*HH);
    SPLIT(graph_fts, wG_h, wG_l, G*HH);
    cvec_k<<<1, HH>>>(b_ee, M0);
    split_z_k<<<(N*256 + 255)/256, 256>>>(node_fts, hidden, N*256);
    agg_init_k<<<(N*HH + 255)/256, 256>>>(N*HH);

    // ---- C = W_ee @ M0c (split out); GD = graph_fts @ M0d ------------------
    run_gemm<1,0,false,false,false,false>(wee_h, wee_l, HH, wM0c_h, wM0c_l, HH,
        nullptr, wC_h, wC_l, HH, nullptr, nullptr, nullptr, nullptr,
        nullptr, nullptr, 0, nullptr, nullptr, nullptr, HH, HH, HH, PER);
    run_gemm<0,0,false,false,false,false>(wG_h, wG_l, HH, wM0d_h, wM0d_l, HH,
        GDp, nullptr, nullptr, HH, nullptr, nullptr, nullptr, nullptr,
        nullptr, nullptr, 0, nullptr, nullptr, nullptr, G, HH, HH, PER);

    // ---- combined [zD | zS | t1] = z @ [M0a | M0b | U1]  (K=256, N=384) ----
    run_gemm<0,0,false,false,false,false>(z_h, z_l, 256, wZU_h, wZU_l, 384,
        zc, nullptr, nullptr, 384, nullptr, nullptr, nullptr, nullptr,
        nullptr, nullptr, 0, nullptr, nullptr, nullptr, N, 384, 256, PER);

    // ---- e0 GEMM + fused gather ------------------------------------------
    run_gemm<3,0,false,false,false,true>(edge_attr, nullptr, HH, wC_h, wC_l, HH,
        nullptr, m0h, m0l, HH, nullptr, nullptr, src, dst,
        zc, zc + 128, 384, GDp, cvec, nullptr, E, HH, HH, PER);

    // ---- M1, M2 (split+leaky), M3 (fused segment-max atomics) --------------
    run_gemm<1,2,false,false,false,false>(m0h, m0l, HH, wM1_h, wM1_l, HH,
        nullptr, m1h, m1l, HH, nullptr, nullptr, nullptr, nullptr,
        nullptr, nullptr, 0, nullptr, nullptr, nullptr, E, HH, HH, PER);
    run_gemm<1,2,false,false,false,false>(m1h, m1l, HH, wM2_h, wM2_l, HH,
        nullptr, m0h, m0l, HH, nullptr, nullptr, nullptr, nullptr,
        nullptr, nullptr, 0, nullptr, nullptr, nullptr, E, HH, HH, PER);
    run_gemm<2,0,false,false,false,false>(m0h, m0l, HH, wM3_h, wM3_l, HH,
        nullptr, nullptr, nullptr, HH, nullptr, nullptr, nullptr, dst,
        nullptr, nullptr, 0, nullptr, nullptr, aggenc, E, HH, HH, PER);
    agg_decode_k<<<(N*HH + 255)/256, 256>>>(N*HH);

    // ---- t1 += agg@U2 + node_fts (t1 in zc cols 256..) ---------------------
    run_gemm<0,0,false,true,true,false>(agh, agl, HH, wU2_h, wU2_l, HH,
        zc + 256, nullptr, nullptr, 384, nullptr, node_fts, nullptr, nullptr,
        nullptr, nullptr, 0, nullptr, nullptr, nullptr, N, HH, HH, PER);
    bn_stats1_k<<<256, 128>>>(zc + 256, 384, N/256);
    bn_stats2_k<<<1, 128>>>(256, 1.0f/(float)N, 0);

    // ---- attention ---------------------------------------------------------
    run_gemm<0,0,true,false,false,false>(z_h, z_l, 256, wQKV_h, wQKV_l, 3*HH,
        qkv, nullptr, nullptr, 3*HH, bqkv, nullptr, nullptr, nullptr,
        nullptr, nullptr, 0, nullptr, nullptr, nullptr, N, 3*HH, HH, PER);
    attn_k<<<dim3(G, 4), PER>>>(qkv, PER);
    run_gemm<0,0,true,false,true,false>(oh, ol, HH, wWo_h, wWo_l, HH,
        t2, nullptr, nullptr, HH, bo, node_fts, nullptr, nullptr,
        nullptr, nullptr, 0, nullptr, nullptr, nullptr, N, HH, HH, PER);
    bn_stats1_k<<<256, 128>>>(t2, HH, N/256);
    bn_stats2_k<<<1, 128>>>(256, 1.0f/(float)N, 256);

    // ---- fused BN1+BN2+add+split -------------------------------------------
    bn12_add_split_k<<<(N*HH + 255)/256, 256>>>(zc + 256, 384, t2,
        bn1_w, bn1_b, bn2_w, bn2_b, N*HH);

    // ---- MLP ---------------------------------------------------------------
    run_gemm<1,1,true,false,false,false>(outh, outl, HH, wW1_h, wW1_l, 2*HH,
        nullptr, mlp1h, mlp1l, 2*HH, b1, nullptr, nullptr, nullptr,
        nullptr, nullptr, 0, nullptr, nullptr, nullptr, N, 2*HH, HH, PER);
    run_gemm<0,0,true,false,true,false>(mlp1h, mlp1l, 2*HH, wW2_h, wW2_l, HH,
        out2, nullptr, nullptr, HH, b2, outf, nullptr, nullptr,
        nullptr, nullptr, 0, nullptr, nullptr, nullptr, N, HH, 2*HH, PER);

    // ---- BN3 -> output ------------------------------------------------------
    bn_stats1_k<<<256, 128>>>(out2, HH, N/256);
    bn_stats2_k<<<1, 128>>>(256, 1.0f/(float)N, 0);
    bn_apply_k<<<(N*HH + 255)/256, 256>>>(out2, HH, bn3_w, bn3_b, outp, N*HH);
}

// round 14
// speedup vs baseline: 1.1343x; 1.0598x over previous
#include <cuda_runtime.h>
#include <cuda_bf16.h>
#include <math.h>
#include <stdint.h>

typedef unsigned short u16;

// Problem constants
#define NN 32768
#define EE 262144
#define GG 64
#define HH 128

// ---------------- scratch ----------------------------------------------------
__device__ u16 g_wZU_h[256*384],  g_wZU_l[256*384];   // combined [zD | zS | U1] B
__device__ u16 g_wM0c_h[HH*HH],   g_wM0c_l[HH*HH];
__device__ u16 g_wM0d_h[HH*HH],   g_wM0d_l[HH*HH];
__device__ u16 g_wee_h[HH*HH],    g_wee_l[HH*HH];
__device__ u16 g_wM1_h[HH*HH],    g_wM1_l[HH*HH];
__device__ u16 g_wM2_h[HH*HH],    g_wM2_l[HH*HH];
__device__ u16 g_wM3_h[HH*HH],    g_wM3_l[HH*HH];
__device__ u16 g_wU2_h[HH*HH],    g_wU2_l[HH*HH];
__device__ u16 g_wQKV_h[3*HH*HH], g_wQKV_l[3*HH*HH];
__device__ u16 g_wWo_h[HH*HH],    g_wWo_l[HH*HH];
__device__ u16 g_wW1_h[2*HH*HH],  g_wW1_l[2*HH*HH];
__device__ u16 g_wW2_h[2*HH*HH],  g_wW2_l[2*HH*HH];
__device__ u16 g_wC_h[HH*HH],     g_wC_l[HH*HH];      // C = W_ee@M0c split
__device__ u16 g_wG_h[GG*HH],     g_wG_l[GG*HH];      // graph_fts split
// activations
__device__ float g_cvec[HH];
__device__ float g_GD[GG*HH];
__device__ float g_zc[(size_t)NN*384];                // [zD | zS | t1] strided 384
__device__ u16 g_z_h[NN*2*HH], g_z_l[NN*2*HH];
__device__ u16 g_m0h[(size_t)EE*HH], g_m0l[(size_t)EE*HH];
__device__ unsigned g_aggenc[NN*HH];
__device__ u16 g_agh[NN*HH], g_agl[NN*HH];
__device__ float g_qkv[NN*3*HH];
__device__ u16 g_oh[NN*HH], g_ol[NN*HH];
__device__ float g_t2[NN*HH];
__device__ float g_out[NN*HH];
__device__ u16 g_outh[NN*HH], g_outl[NN*HH];
__device__ u16 g_mlp1h[NN*2*HH], g_mlp1l[NN*2*HH];
__device__ float g_out2[NN*HH];
__device__ float g_part[256*256];
__device__ float g_stats[512];     // [0:256) = BN1 (mu, rstd), [256:512) = BN2

// ---------------- helpers ----------------------------------------------------
__device__ __forceinline__ float leaky_f(float v) { return v > 0.0f ? v : 0.01f*v; }

__device__ __forceinline__ float fast_exp(float x) {
    x = fmaxf(x, -87.0f);
    float t  = x * 1.4426950408889634f;
    float fl = floorf(t);
    float f  = t - fl;
    float p  =            1.339077600e-4f;
    p = p * f + 9.618437357e-4f;
    p = p * f + 9.556031144e-3f;
    p = p * f + 5.550332471e-2f;
    p = p * f + 2.402264923e-1f;
    p = p * f + 6.931471825e-1f;
    p = p * f + 1.0f;
    int ei = (int)fl;
    return __int_as_float((ei + 127) << 23) * p;
}

__device__ __forceinline__ unsigned enc_f(float f) {
    unsigned u = __float_as_uint(f);
    return (u & 0x80000000u) ? ~u : (u | 0x80000000u);
}
__device__ __forceinline__ float dec_f(unsigned u) {
    return (u & 0x80000000u) ? __uint_as_float(u ^ 0x80000000u) : __uint_as_float(~u);
}
#define ENC_NEGINF 0x007FFFFFu

__device__ __forceinline__ uint32_t smem_u32(const void* p) {
    uint32_t a;
    asm("{ .reg .u64 t; cvta.to.shared.u64 t, %1; cvt.u32.u64 %0, t; }" : "=r"(a) : "l"(p));
    return a;
}

__device__ __forceinline__ void split2(float v, u16& hi, u16& lo) {
    __nv_bfloat16 h = __float2bfloat16(v);
    float r = v - __bfloat162float(h);
    __nv_bfloat16 l = __float2bfloat16(r);
    hi = *reinterpret_cast<u16*>(&h);
    lo = *reinterpret_cast<u16*>(&l);
}

// ---------------- MMA building blocks ----------------------------------------
#define LDM_X4(r, a) \
    asm volatile("ldmatrix.sync.aligned.m8n8.x4.shared.b16 {%0,%1,%2,%3}, [%4];" \
        : "=r"((r)[0]), "=r"((r)[1]), "=r"((r)[2]), "=r"((r)[3]) : "r"(a))
#define LDM_X4T(r, a) \
    asm volatile("ldmatrix.sync.aligned.m8n8.x4.trans.shared.b16 {%0,%1,%2,%3}, [%4];" \
        : "=r"((r)[0]), "=r"((r)[1]), "=r"((r)[2]), "=r"((r)[3]) : "r"(a))
#define MMA16816(c, a, b) \
    asm volatile("mma.sync.aligned.m16n8k16.row.col.f32.bf16.bf16.f32 " \
        "{%0,%1,%2,%3}, {%4,%5,%6,%7}, {%8,%9}, {%0,%1,%2,%3};" \
        : "+f"((c)[0]), "+f"((c)[1]), "+f"((c)[2]), "+f"((c)[3]) \
        : "r"((a)[0]), "r"((a)[1]), "r"((a)[2]), "r"((a)[3]), "r"((b)[0]), "r"((b)[1]))

#define CPA16(dst, src) asm volatile("cp.async.cg.shared.global [%0], [%1], 16;" :: "r"(dst), "l"(src))
#define CPA_COMMIT()    asm volatile("cp.async.commit_group;")
#define CPA_WAIT0()     asm volatile("cp.async.wait_group 0;" ::: "memory")

// XOR-swizzled offset inside a tile: rows of 256B, 16B chunks 0..15
__device__ __forceinline__ uint32_t swz(int row, int cb) {
    return (uint32_t)((row << 8) + (((cb ^ row) & 7) << 4) + ((cb & 8) << 4));
}

// ---------------- split-bf16 3-pass GEMM on mma.sync --------------------------
// Tile 64(M) x 128(N); 8 warps = 2x4; warp tile 32x32. RB M-subtiles reuse B.
template<int OUT, int ACT, bool BIAS, bool ACCUM, bool RESID, bool AF32>
__global__ void __launch_bounds__(256,2) gemm_ps(
    const void* Ah_, const u16* Al, int lda,
    const u16* __restrict__ Bh, const u16* __restrict__ Bl, int ldb,
    float* Cf, u16* Ch, u16* Cl, int ldc,
    const float* __restrict__ bias, const float* __restrict__ resid,
    const int* __restrict__ srcv, const int* __restrict__ dstv,
    const float* __restrict__ zD, const float* __restrict__ zS, int ldz,
    const float* __restrict__ GD, const float* __restrict__ cvec,
    unsigned* aggenc, int M, int N, int K, int PER, int tilesM, int RB)
{
    extern __shared__ char smem[];
    uint32_t sb = smem_u32(smem);
    const int tid = threadIdx.x;
    const int lane = tid & 31, w = tid >> 5;
    const int wm = w >> 2, wn = w & 3;
    const int ncol0 = blockIdx.x << 7;

    const uint32_t offB_h = 0;
    const uint32_t offB_l = (uint32_t)K * 256;
    const uint32_t offA_h = (uint32_t)K * 512;
    const uint32_t offA_l = offA_h + 16384;

    int ty0 = blockIdx.y * RB;
    int tyEnd = ty0 + RB; if (tyEnd > tilesM) tyEnd = tilesM;

    auto fillA = [&](int ty, int kc) {
        int mrow0 = ty << 6;
        if (AF32) {
            const float* Af = (const float*)Ah_;
            for (int idx = tid; idx < 64 * 16; idx += 256) {
                int row = idx >> 4, cb = idx & 15;
                const float* ap = Af + (size_t)(mrow0 + row) * lda + kc + cb * 8;
                float4 v0 = *reinterpret_cast<const float4*>(ap);
                float4 v1 = *reinterpret_cast<const float4*>(ap + 4);
                u16 h[8], l[8];
                split2(v0.x,h[0],l[0]); split2(v0.y,h[1],l[1]);
                split2(v0.z,h[2],l[2]); split2(v0.w,h[3],l[3]);
                split2(v1.x,h[4],l[4]); split2(v1.y,h[5],l[5]);
                split2(v1.z,h[6],l[6]); split2(v1.w,h[7],l[7]);
                uint32_t d = swz(row, cb);
                *reinterpret_cast<uint4*>(smem + offA_h + d) = make_uint4(
                    (uint32_t)h[0]|((uint32_t)h[1]<<16), (uint32_t)h[2]|((uint32_t)h[3]<<16),
                    (uint32_t)h[4]|((uint32_t)h[5]<<16), (uint32_t)h[6]|((uint32_t)h[7]<<16));
                *reinterpret_cast<uint4*>(smem + offA_l + d) = make_uint4(
                    (uint32_t)l[0]|((uint32_t)l[1]<<16), (uint32_t)l[2]|((uint32_t)l[3]<<16),
                    (uint32_t)l[4]|((uint32_t)l[5]<<16), (uint32_t)l[6]|((uint32_t)l[7]<<16));
            }
        } else {
            const u16* Ah = (const u16*)Ah_;
            for (int idx = tid; idx < 64 * 16; idx += 256) {
                int row = idx >> 4, cb = idx & 15;
                size_t so = (size_t)(mrow0 + row) * lda + kc + cb * 8;
                uint32_t d = swz(row, cb);
                CPA16(sb + offA_h + d, Ah + so);
                CPA16(sb + offA_l + d, Al + so);
            }
            CPA_COMMIT();
        }
    };

    // ---- B fill (whole K) + first A chunk ----
    for (int idx = tid; idx < K * 16; idx += 256) {
        int row = idx >> 4, cb = idx & 15;
        size_t so = (size_t)row * ldb + ncol0 + cb * 8;
        uint32_t d = swz(row, cb);
        CPA16(sb + offB_h + d, Bh + so);
        CPA16(sb + offB_l + d, Bl + so);
    }
    CPA_COMMIT();
    fillA(ty0, 0);

    for (int ty = ty0; ty < tyEnd; ty++) {
        const int mrow0 = ty << 6;
        float acc[2][4][4];
        #pragma unroll
        for (int i = 0; i < 2; i++)
            #pragma unroll
            for (int j = 0; j < 4; j++)
                #pragma unroll
                for (int q = 0; q < 4; q++) acc[i][j][q] = 0.0f;

        for (int kc = 0; kc < K; kc += 128) {
            CPA_WAIT0();
            __syncthreads();

            #pragma unroll
            for (int kk = 0; kk < 8; kk++) {
                uint32_t ah[2][4], al[2][4];
                #pragma unroll
                for (int i = 0; i < 2; i++) {
                    int row = wm*32 + i*16 + (lane & 15);
                    uint32_t ad = sb + offA_h + swz(row, kk*2 + (lane >> 4));
                    LDM_X4(ah[i], ad);
                    LDM_X4(al[i], ad + 16384);
                }
                uint32_t bh[4][2], bl[4][2];
                #pragma unroll
                for (int jj = 0; jj < 2; jj++) {
                    int krow = kc + kk*16 + (lane & 15);
                    uint32_t bd = sb + offB_h + swz(krow, wn*4 + jj*2 + (lane >> 4));
                    uint32_t t[4];
                    LDM_X4T(t, bd);
                    bh[jj*2][0]=t[0]; bh[jj*2][1]=t[1]; bh[jj*2+1][0]=t[2]; bh[jj*2+1][1]=t[3];
                    LDM_X4T(t, bd + offB_l);
                    bl[jj*2][0]=t[0]; bl[jj*2][1]=t[1]; bl[jj*2+1][0]=t[2]; bl[jj*2+1][1]=t[3];
                }
                #pragma unroll
                for (int i = 0; i < 2; i++)
                    #pragma unroll
                    for (int j = 0; j < 4; j++) {
                        MMA16816(acc[i][j], ah[i], bh[j]);
                        MMA16816(acc[i][j], ah[i], bl[j]);
                        MMA16816(acc[i][j], al[i], bh[j]);
                    }
            }
            __syncthreads();
            // prefetch next chunk / next subtile (overlaps epilogue below)
            if (kc + 128 < K) fillA(ty, kc + 128);
            else if (ty + 1 < tyEnd) fillA(ty + 1, 0);
        }

        // ---- epilogue ----
        #pragma unroll
        for (int i = 0; i < 2; i++) {
            int r0 = mrow0 + wm*32 + i*16 + (lane >> 2);
            #pragma unroll
            for (int half = 0; half < 2; half++) {
                int r = r0 + half*8;
                int sidx = 0, didx = 0, gidx = 0;
                if (OUT == 2 || OUT == 3) didx = dstv[r];
                if (OUT == 3) { sidx = srcv[r]; gidx = didx / PER; }
                #pragma unroll
                for (int j = 0; j < 4; j++) {
                    int c = ncol0 + wn*32 + j*8 + (lane & 3)*2;
                    size_t idx = (size_t)r * ldc + c;
                    float vx = acc[i][j][half*2], vy = acc[i][j][half*2 + 1];
                    if (BIAS)  { vx += bias[c]; vy += bias[c + 1]; }
                    if (OUT == 3) {
                        vx += zD[(size_t)didx*ldz + c] + zS[(size_t)sidx*ldz + c]
                            + GD[(size_t)gidx*HH + c] + cvec[c];
                        vy += zD[(size_t)didx*ldz + c+1] + zS[(size_t)sidx*ldz + c+1]
                            + GD[(size_t)gidx*HH + c+1] + cvec[c+1];
                        vx = leaky_f(vx); vy = leaky_f(vy);
                        u16 hx,lx,hy,ly; split2(vx,hx,lx); split2(vy,hy,ly);
                        *reinterpret_cast<uint32_t*>(Ch + idx) = (uint32_t)hx | ((uint32_t)hy<<16);
                        *reinterpret_cast<uint32_t*>(Cl + idx) = (uint32_t)lx | ((uint32_t)ly<<16);
                    } else if (OUT == 2) {
                        atomicMax(&aggenc[didx*HH + c],   enc_f(vx));
                        atomicMax(&aggenc[didx*HH + c+1], enc_f(vy));
                    } else {
                        if (ACCUM) { float2 t = *reinterpret_cast<float2*>(Cf + idx); vx += t.x; vy += t.y; }
                        if (RESID) { float2 t = *reinterpret_cast<const float2*>(resid + (size_t)r*HH + c); vx += t.x; vy += t.y; }
                        if (ACT == 1) { vx = fmaxf(vx, 0.f); vy = fmaxf(vy, 0.f); }
                        else if (ACT == 2) { vx = leaky_f(vx); vy = leaky_f(vy); }
                        if (OUT == 1) {
                            u16 hx,lx,hy,ly; split2(vx,hx,lx); split2(vy,hy,ly);
                            *reinterpret_cast<uint32_t*>(Ch + idx) = (uint32_t)hx | ((uint32_t)hy<<16);
                            *reinterpret_cast<uint32_t*>(Cl + idx) = (uint32_t)lx | ((uint32_t)ly<<16);
                        } else {
                            *reinterpret_cast<float2*>(Cf + idx) = make_float2(vx, vy);
                        }
                    }
                }
            }
        }
    }
}

// ---------------- fused edge chain: m3 = leaky(leaky(m0@M1)@M2)@M3, seg-max ---
__global__ void __launch_bounds__(256,1) edge_chain_k(const int* __restrict__ dstv, int tiles)
{
    extern __shared__ char smem[];
    uint32_t sb = smem_u32(smem);
    const int tid = threadIdx.x;
    const int lane = tid & 31, w = tid >> 5;
    const int wm = w >> 2, wn = w & 3;
    const uint32_t offAct = 196608;           // hi; lo at +16384

    // ---- load all weights once (layer L: hi @ L*65536, lo @ +32768) ----
    {
        const u16* srcs[6] = { g_wM1_h, g_wM1_l, g_wM2_h, g_wM2_l, g_wM3_h, g_wM3_l };
        #pragma unroll
        for (int s = 0; s < 6; s++) {
            uint32_t base = sb + (uint32_t)s * 32768;
            const u16* W = srcs[s];
            for (int idx = tid; idx < 128 * 16; idx += 256) {
                int row = idx >> 4, cb = idx & 15;
                CPA16(base + swz(row, cb), W + (size_t)row * 128 + cb * 8);
            }
        }
        CPA_COMMIT(); CPA_WAIT0();
        __syncthreads();
    }

    for (int t = blockIdx.x; t < tiles; t += gridDim.x) {
        int mrow0 = t << 6;
        // ---- load m0 tile into act ----
        for (int idx = tid; idx < 64 * 16; idx += 256) {
            int row = idx >> 4, cb = idx & 15;
            size_t so = (size_t)(mrow0 + row) * 128 + cb * 8;
            uint32_t d = swz(row, cb);
            CPA16(sb + offAct + d, g_m0h + so);
            CPA16(sb + offAct + 16384 + d, g_m0l + so);
        }
        CPA_COMMIT(); CPA_WAIT0();
        __syncthreads();

        #pragma unroll
        for (int layer = 0; layer < 3; layer++) {
            float acc[2][4][4];
            #pragma unroll
            for (int i = 0; i < 2; i++)
                #pragma unroll
                for (int j = 0; j < 4; j++)
                    #pragma unroll
                    for (int q = 0; q < 4; q++) acc[i][j][q] = 0.0f;

            uint32_t wbase = sb + (uint32_t)layer * 65536;
            #pragma unroll
            for (int kk = 0; kk < 8; kk++) {
                uint32_t ah[2][4], al[2][4];
                #pragma unroll
                for (int i = 0; i < 2; i++) {
                    int row = wm*32 + i*16 + (lane & 15);
                    uint32_t ad = sb + offAct + swz(row, kk*2 + (lane >> 4));
                    LDM_X4(ah[i], ad);
                    LDM_X4(al[i], ad + 16384);
                }
                uint32_t bh[4][2], bl[4][2];
                #pragma unroll
                for (int jj = 0; jj < 2; jj++) {
                    int krow = kk*16 + (lane & 15);
                    uint32_t bd = wbase + swz(krow, wn*4 + jj*2 + (lane >> 4));
                    uint32_t tt[4];
                    LDM_X4T(tt, bd);
                    bh[jj*2][0]=tt[0]; bh[jj*2][1]=tt[1]; bh[jj*2+1][0]=tt[2]; bh[jj*2+1][1]=tt[3];
                    LDM_X4T(tt, bd + 32768);
                    bl[jj*2][0]=tt[0]; bl[jj*2][1]=tt[1]; bl[jj*2+1][0]=tt[2]; bl[jj*2+1][1]=tt[3];
                }
                #pragma unroll
                for (int i = 0; i < 2; i++)
                    #pragma unroll
                    for (int j = 0; j < 4; j++) {
                        MMA16816(acc[i][j], ah[i], bh[j]);
                        MMA16816(acc[i][j], ah[i], bl[j]);
                        MMA16816(acc[i][j], al[i], bh[j]);
                    }
            }
            __syncthreads();     // all reads of act complete

            if (layer < 2) {
                #pragma unroll
                for (int i = 0; i < 2; i++) {
                    #pragma unroll
                    for (int half = 0; half < 2; half++) {
                        int rl = wm*32 + i*16 + (lane >> 2) + half*8;
                        #pragma unroll
                        for (int j = 0; j < 4; j++) {
                            int c = wn*32 + j*8 + (lane & 3)*2;
                            float vx = leaky_f(acc[i][j][half*2]);
                            float vy = leaky_f(acc[i][j][half*2 + 1]);
                            u16 hx,lx,hy,ly; split2(vx,hx,lx); split2(vy,hy,ly);
                            uint32_t d = swz(rl, c >> 3) + (c & 7) * 2;
                            *reinterpret_cast<uint32_t*>(smem + offAct + d) =
                                (uint32_t)hx | ((uint32_t)hy << 16);
                            *reinterpret_cast<uint32_t*>(smem + offAct + 16384 + d) =
                                (uint32_t)lx | ((uint32_t)ly << 16);
                        }
                    }
                }
                __syncthreads();
            } else {
                #pragma unroll
                for (int i = 0; i < 2; i++) {
                    #pragma unroll
                    for (int half = 0; half < 2; half++) {
                        int r = mrow0 + wm*32 + i*16 + (lane >> 2) + half*8;
                        int didx = dstv[r];
                        #pragma unroll
                        for (int j = 0; j < 4; j++) {
                            int c = wn*32 + j*8 + (lane & 3)*2;
                            atomicMax(&g_aggenc[didx*HH + c],   enc_f(acc[i][j][half*2]));
                            atomicMax(&g_aggenc[didx*HH + c+1], enc_f(acc[i][j][half*2+1]));
                        }
                    }
                }
            }
        }
    }
}

// ---------------- small kernels ----------------------------------------------
__global__ void split_all_k(const float* __restrict__ M0, const float* __restrict__ W_ee,
                            const float* __restrict__ M1, const float* __restrict__ M2,
                            const float* __restrict__ M3, const float* __restrict__ U2,
                            const float* __restrict__ Wqkv, const float* __restrict__ Wo,
                            const float* __restrict__ W1, const float* __restrict__ W2,
                            const float* __restrict__ Gf)
{
    int i = blockIdx.x*blockDim.x + threadIdx.x;
    struct Job { const float* s; u16* h; u16* l; int n; };
    const Job jobs[12] = {
        { M0 + (size_t)4*HH*HH, g_wM0c_h, g_wM0c_l, HH*HH },
        { M0 + (size_t)5*HH*HH, g_wM0d_h, g_wM0d_l, HH*HH },
        { W_ee, g_wee_h, g_wee_l, HH*HH },
        { M1, g_wM1_h, g_wM1_l, HH*HH },
        { M2, g_wM2_h, g_wM2_l, HH*HH },
        { M3, g_wM3_h, g_wM3_l, HH*HH },
        { U2, g_wU2_h, g_wU2_l, HH*HH },
        { Wqkv, g_wQKV_h, g_wQKV_l, 3*HH*HH },
        { Wo, g_wWo_h, g_wWo_l, HH*HH },
        { W1, g_wW1_h, g_wW1_l, 2*HH*HH },
        { W2, g_wW2_h, g_wW2_l, 2*HH*HH },
        { Gf, g_wG_h, g_wG_l, GG*HH },
    };
    #pragma unroll
    for (int j = 0; j < 12; j++) {
        if (i < jobs[j].n) {
            u16 h, l; split2(jobs[j].s[i], h, l);
            jobs[j].h[i] = h; jobs[j].l[i] = l;
            return;
        }
        i -= jobs[j].n;
    }
}
// 7xHH^2 (M0c,M0d,Wee,M1,M2,M3,U2) + 3xHH^2 (QKV) + 1xHH^2 (Wo)
// + 2xHH^2 (W1) + 2xHH^2 (W2) + GG*HH (graph_fts) = 15*HH^2 + GG*HH
#define SPLIT_ALL_TOTAL (15*HH*HH + GG*HH)

__global__ void build_zu_k(const float* __restrict__ M0, const float* __restrict__ U1)
{
    int i = blockIdx.x*blockDim.x + threadIdx.x;
    if (i >= 256*384) return;
    int k = i / 384, c = i - k*384;
    float v;
    if (c < 128)       v = M0[(size_t)k*HH + c];
    else if (c < 256)  v = M0[(size_t)(256 + k)*HH + (c - 128)];
    else               v = U1[(size_t)k*HH + (c - 256)];
    u16 h, l; split2(v, h, l);
    g_wZU_h[i] = h; g_wZU_l[i] = l;
}

__global__ void split_z_k(const float* __restrict__ node, const float* __restrict__ hid, int n)
{
    int i = blockIdx.x*blockDim.x + threadIdx.x;
    if (i >= n) return;
    int row = i >> 8, col = i & 255;
    float v = (col < 128) ? node[row*HH + col] : hid[row*HH + col - 128];
    u16 h, l; split2(v, h, l);
    g_z_h[i] = h; g_z_l[i] = l;
}

__global__ void cvec_k(const float* __restrict__ b_ee, const float* __restrict__ M0) {
    int j = threadIdx.x;
    float s = 0.0f;
    for (int t = 0; t < HH; t++) s += b_ee[t] * M0[(size_t)(4*HH + t)*HH + j];
    g_cvec[j] = s;
}

__global__ void agg_init_k(int total) {
    int i = blockIdx.x*blockDim.x + threadIdx.x;
    if (i < total) g_aggenc[i] = ENC_NEGINF;
}

__global__ void agg_decode_k(int total) {
    int i = blockIdx.x*blockDim.x + threadIdx.x;
    if (i >= total) return;
    float f = dec_f(g_aggenc[i]);
    if (!isfinite(f)) f = 0.0f;
    u16 h, l; split2(f, h, l);
    g_agh[i] = h; g_agl[i] = l;
}

__global__ void __launch_bounds__(512) attn_k(const float* __restrict__ qkv, int PER)
{
    __shared__ float Ks[128][32];
    __shared__ float Vs[128][32];
    int g = blockIdx.x, h = blockIdx.y;
    int tid = threadIdx.x;
    int n = g*PER + tid;
    const float scale = 0.17677669529663687f;
    float q[32];
    #pragma unroll
    for (int d = 0; d < 32; d++)
        q[d] = qkv[(size_t)n*384 + h*32 + d] * scale;

    float m = -INFINITY, l = 0.0f;
    float acc[32];
    #pragma unroll
    for (int d = 0; d < 32; d++) acc[d] = 0.0f;

    for (int c0 = 0; c0 < PER; c0 += 128) {
        __syncthreads();
        for (int i = tid; i < 128*32; i += 512) {
            int r = i >> 5, d = i & 31;
            size_t base = (size_t)(g*PER + c0 + r)*384 + h*32 + d;
            Ks[r][d] = qkv[base + 128];
            Vs[r][d] = qkv[base + 256];
        }
        __syncthreads();
        for (int j = 0; j < 128; j++) {
            float s = 0.0f;
            #pragma unroll
            for (int d = 0; d < 32; d++) s += q[d]*Ks[j][d];
            float mn = fmaxf(m, s);
            float a = fast_exp(m - mn);
            float p = fast_exp(s - mn);
            l = l*a + p;
            #pragma unroll
            for (int d = 0; d < 32; d++) acc[d] = acc[d]*a + p*Vs[j][d];
            m = mn;
        }
    }
    float inv = 1.0f / l;
    #pragma unroll
    for (int d = 0; d < 32; d += 2) {
        float vx = acc[d]*inv, vy = acc[d+1]*inv;
        u16 hx,lx,hy,ly; split2(vx,hx,lx); split2(vy,hy,ly);
        size_t idx = (size_t)n*HH + h*32 + d;
        *reinterpret_cast<uint32_t*>(g_oh + idx) = (uint32_t)hx | ((uint32_t)hy<<16);
        *reinterpret_cast<uint32_t*>(g_ol + idx) = (uint32_t)lx | ((uint32_t)ly<<16);
    }
}

__global__ void bn_stats1_k(const float* __restrict__ x, int ld, int rowsPer) {
    int c = threadIdx.x;
    int b = blockIdx.x;
    size_t r0 = (size_t)b * rowsPer;
    float s = 0.0f, s2 = 0.0f;
    for (int r = 0; r < rowsPer; r++) {
        float v = x[(r0 + r)*ld + c];
        s += v; s2 += v*v;
    }
    g_part[b*256 + c] = s;
    g_part[b*256 + 128 + c] = s2;
}
__global__ void bn_stats2_k(int nb, float invN, int sbase) {
    int c = threadIdx.x;
    float s = 0.0f, s2 = 0.0f;
    for (int b = 0; b < nb; b++) { s += g_part[b*256 + c]; s2 += g_part[b*256 + 128 + c]; }
    float mu = s * invN;
    float var = s2 * invN - mu*mu;
    g_stats[sbase + c] = mu;
    g_stats[sbase + 128 + c] = rsqrtf(var + 1e-5f);
}
__global__ void bn_apply_k(const float* __restrict__ x, int ld, const float* __restrict__ w,
                           const float* __restrict__ b, float* __restrict__ y, int total)
{
    int i = blockIdx.x*blockDim.x + threadIdx.x;
    if (i >= total) return;
    int c = i & 127;
    int row = i >> 7;
    y[i] = (x[(size_t)row*ld + c] - g_stats[c]) * g_stats[128 + c] * w[c] + b[c];
}

// fused: out = BN1(t1) + BN2(t2); writes fp32 + split hi/lo
__global__ void bn12_add_split_k(const float* __restrict__ t1, int ld1,
                                 const float* __restrict__ t2,
                                 const float* __restrict__ w1, const float* __restrict__ b1,
                                 const float* __restrict__ w2, const float* __restrict__ b2,
                                 int total)
{
    int i = blockIdx.x*blockDim.x + threadIdx.x;
    if (i >= total) return;
    int c = i & 127;
    int row = i >> 7;
    float v1 = (t1[(size_t)row*ld1 + c] - g_stats[c])       * g_stats[128 + c] * w1[c] + b1[c];
    float v2 = (t2[i]                   - g_stats[256 + c]) * g_stats[384 + c] * w2[c] + b2[c];
    float v = v1 + v2;
    g_out[i] = v;
    u16 h, l; split2(v, h, l);
    g_outh[i] = h; g_outl[i] = l;
}

// ---------------- host orchestration -----------------------------------------
template<int OUT, int ACT, bool BIAS, bool ACCUM, bool RESID, bool AF32>
static void run_gemm(const void* Ah, const u16* Al, int lda,
                     const u16* Bh, const u16* Bl, int ldb,
                     float* Cf, u16* Ch, u16* Cl, int ldc,
                     const float* bias, const float* resid,
                     const int* srcv, const int* dstv,
                     const float* zD, const float* zS, int ldz,
                     const float* GD, const float* cvec,
                     unsigned* aggenc, int M, int N, int K, int PER)
{
    auto kfn = gemm_ps<OUT,ACT,BIAS,ACCUM,RESID,AF32>;
    cudaFuncSetAttribute(kfn, cudaFuncAttributeMaxDynamicSharedMemorySize, 163840);
    size_t smemsz = (size_t)K*512 + 32768;
    int tilesM = (M + 63) / 64;
    int tilesN = N / 128;
    int RB = (tilesM * tilesN) / 304;
    if (RB < 1) RB = 1;
    if (RB > 8) RB = 8;
    int gy = (tilesM + RB - 1) / RB;
    dim3 grid(tilesN, gy);
    kfn<<<grid, 256, smemsz>>>(Ah, Al, lda, Bh, Bl, ldb, Cf, Ch, Cl, ldc, bias, resid,
                               srcv, dstv, zD, zS, ldz, GD, cvec, aggenc, M, N, K, PER, tilesM, RB);
}

#define SYMADDR(p, s) cudaGetSymbolAddress((void**)&p, s)

extern "C" void kernel_launch(void* const* d_in, const int* in_sizes, int n_in,
                              void* d_out, int out_size)
{
    const float* node_fts  = (const float*)d_in[0];
    const float* edge_attr = (const float*)d_in[1];
    const float* graph_fts = (const float*)d_in[2];
    const float* hidden    = (const float*)d_in[3];
    const float* W_ee      = (const float*)d_in[4];
    const float* b_ee      = (const float*)d_in[5];
    const float* M0        = (const float*)d_in[6];
    const float* M1        = (const float*)d_in[7];
    const float* M2        = (const float*)d_in[8];
    const float* M3        = (const float*)d_in[9];
    const float* U1        = (const float*)d_in[10];
    const float* U2        = (const float*)d_in[11];
    const float* Wqkv      = (const float*)d_in[12];
    const float* bqkv      = (const float*)d_in[13];
    const float* Wo        = (const float*)d_in[14];
    const float* bo        = (const float*)d_in[15];
    const float* bn1_w     = (const float*)d_in[16];
    const float* bn1_b     = (const float*)d_in[17];
    const float* bn2_w     = (const float*)d_in[18];
    const float* bn2_b     = (const float*)d_in[19];
    const float* bn3_w     = (const float*)d_in[20];
    const float* bn3_b     = (const float*)d_in[21];
    const float* W1        = (const float*)d_in[22];
    const float* b1        = (const float*)d_in[23];
    const float* W2        = (const float*)d_in[24];
    const float* b2        = (const float*)d_in[25];
    const int*   edge_index= (const int*)d_in[26];

    const int N = in_sizes[0] / HH;
    const int E = in_sizes[1] / HH;
    const int G = in_sizes[2] / HH;
    const int PER = N / G;
    const int* src = edge_index;
    const int* dst = edge_index + E;
    float* outp = (float*)d_out;

    u16 *wZU_h,*wZU_l,*wM0c_h,*wM0c_l,*wM0d_h,*wM0d_l,*wee_h,*wee_l;
    u16 *wU2_h,*wU2_l,*wQKV_h,*wQKV_l,*wWo_h,*wWo_l,*wW1_h,*wW1_l,*wW2_h,*wW2_l,*wC_h,*wC_l,*wG_h,*wG_l;
    u16 *z_h,*z_l,*m0h,*m0l,*agh,*agl,*oh,*ol,*outh,*outl,*mlp1h,*mlp1l;
    float *cvec,*GDp,*zc,*qkv,*t2,*outf,*out2;
    unsigned *aggenc;
    SYMADDR(wZU_h,g_wZU_h);   SYMADDR(wZU_l,g_wZU_l);
    SYMADDR(wM0c_h,g_wM0c_h); SYMADDR(wM0c_l,g_wM0c_l);
    SYMADDR(wM0d_h,g_wM0d_h); SYMADDR(wM0d_l,g_wM0d_l);
    SYMADDR(wee_h,g_wee_h);   SYMADDR(wee_l,g_wee_l);
    SYMADDR(wU2_h,g_wU2_h);   SYMADDR(wU2_l,g_wU2_l);
    SYMADDR(wQKV_h,g_wQKV_h); SYMADDR(wQKV_l,g_wQKV_l);
    SYMADDR(wWo_h,g_wWo_h);   SYMADDR(wWo_l,g_wWo_l);
    SYMADDR(wW1_h,g_wW1_h);   SYMADDR(wW1_l,g_wW1_l);
    SYMADDR(wW2_h,g_wW2_h);   SYMADDR(wW2_l,g_wW2_l);
    SYMADDR(wC_h,g_wC_h);     SYMADDR(wC_l,g_wC_l);
    SYMADDR(wG_h,g_wG_h);     SYMADDR(wG_l,g_wG_l);
    SYMADDR(z_h,g_z_h);       SYMADDR(z_l,g_z_l);
    SYMADDR(m0h,g_m0h); SYMADDR(m0l,g_m0l);
    SYMADDR(agh,g_agh); SYMADDR(agl,g_agl); SYMADDR(oh,g_oh); SYMADDR(ol,g_ol);
    SYMADDR(outh,g_outh); SYMADDR(outl,g_outl); SYMADDR(mlp1h,g_mlp1h); SYMADDR(mlp1l,g_mlp1l);
    SYMADDR(cvec,g_cvec); SYMADDR(GDp,g_GD); SYMADDR(zc,g_zc);
    SYMADDR(qkv,g_qkv); SYMADDR(t2,g_t2);
    SYMADDR(outf,g_out); SYMADDR(out2,g_out2);
    SYMADDR(aggenc,g_aggenc);

    // ---- weight prep (one batched split + combined ZU + cvec + z) ----------
    split_all_k<<<(SPLIT_ALL_TOTAL + 255)/256, 256>>>(M0, W_ee, M1, M2, M3, U2,
                                                      Wqkv, Wo, W1, W2, graph_fts);
    build_zu_k<<<(256*384 + 255)/256, 256>>>(M0, U1);
    cvec_k<<<1, HH>>>(b_ee, M0);
    split_z_k<<<(N*256 + 255)/256, 256>>>(node_fts, hidden, N*256);
    agg_init_k<<<(N*HH + 255)/256, 256>>>(N*HH);

    // ---- C = W_ee @ M0c (split out); GD = graph_fts @ M0d ------------------
    run_gemm<1,0,false,false,false,false>(wee_h, wee_l, HH, wM0c_h, wM0c_l, HH,
        nullptr, wC_h, wC_l, HH, nullptr, nullptr, nullptr, nullptr,
        nullptr, nullptr, 0, nullptr, nullptr, nullptr, HH, HH, HH, PER);
    run_gemm<0,0,false,false,false,false>(wG_h, wG_l, HH, wM0d_h, wM0d_l, HH,
        GDp, nullptr, nullptr, HH, nullptr, nullptr, nullptr, nullptr,
        nullptr, nullptr, 0, nullptr, nullptr, nullptr, G, HH, HH, PER);

    // ---- combined [zD | zS | t1] = z @ [M0a | M0b | U1]  (K=256, N=384) ----
    run_gemm<0,0,false,false,false,false>(z_h, z_l, 256, wZU_h, wZU_l, 384,
        zc, nullptr, nullptr, 384, nullptr, nullptr, nullptr, nullptr,
        nullptr, nullptr, 0, nullptr, nullptr, nullptr, N, 384, 256, PER);

    // ---- e0 GEMM + fused gather ------------------------------------------
    run_gemm<3,0,false,false,false,true>(edge_attr, nullptr, HH, wC_h, wC_l, HH,
        nullptr, m0h, m0l, HH, nullptr, nullptr, src, dst,
        zc, zc + 128, 384, GDp, cvec, nullptr, E, HH, HH, PER);

    // ---- fused M1->M2->M3 chain + seg-max atomics --------------------------
    {
        cudaFuncSetAttribute(edge_chain_k, cudaFuncAttributeMaxDynamicSharedMemorySize, 229376);
        edge_chain_k<<<152, 256, 229376>>>(dst, E/64);
    }
    agg_decode_k<<<(N*HH + 255)/256, 256>>>(N*HH);

    // ---- t1 += agg@U2 + node_fts (t1 in zc cols 256..) ---------------------
    run_gemm<0,0,false,true,true,false>(agh, agl, HH, wU2_h, wU2_l, HH,
        zc + 256, nullptr, nullptr, 384, nullptr, node_fts, nullptr, nullptr,
        nullptr, nullptr, 0, nullptr, nullptr, nullptr, N, HH, HH, PER);
    bn_stats1_k<<<256, 128>>>(zc + 256, 384, N/256);
    bn_stats2_k<<<1, 128>>>(256, 1.0f/(float)N, 0);

    // ---- attention ---------------------------------------------------------
    run_gemm<0,0,true,false,false,false>(z_h, z_l, 256, wQKV_h, wQKV_l, 3*HH,
        qkv, nullptr, nullptr, 3*HH, bqkv, nullptr, nullptr, nullptr,
        nullptr, nullptr, 0, nullptr, nullptr, nullptr, N, 3*HH, HH, PER);
    attn_k<<<dim3(G, 4), PER>>>(qkv, PER);
    run_gemm<0,0,true,false,true,false>(oh, ol, HH, wWo_h, wWo_l, HH,
        t2, nullptr, nullptr, HH, bo, node_fts, nullptr, nullptr,
        nullptr, nullptr, 0, nullptr, nullptr, nullptr, N, HH, HH, PER);
    bn_stats1_k<<<256, 128>>>(t2, HH, N/256);
    bn_stats2_k<<<1, 128>>>(256, 1.0f/(float)N, 256);

    // ---- fused BN1+BN2+add+split -------------------------------------------
    bn12_add_split_k<<<(N*HH + 255)/256, 256>>>(zc + 256, 384, t2,
        bn1_w, bn1_b, bn2_w, bn2_b, N*HH);

    // ---- MLP ---------------------------------------------------------------
    run_gemm<1,1,true,false,false,false>(outh, outl, HH, wW1_h, wW1_l, 2*HH,
        nullptr, mlp1h, mlp1l, 2*HH, b1, nullptr, nullptr, nullptr,
        nullptr, nullptr, 0, nullptr, nullptr, nullptr, N, 2*HH, HH, PER);
    run_gemm<0,0,true,false,true,false>(mlp1h, mlp1l, 2*HH, wW2_h, wW2_l, HH,
        out2, nullptr, nullptr, HH, b2, outf, nullptr, nullptr,
        nullptr, nullptr, 0, nullptr, nullptr, nullptr, N, HH, 2*HH, PER);

    // ---- BN3 -> output ------------------------------------------------------
    bn_stats1_k<<<256, 128>>>(out2, HH, N/256);
    bn_stats2_k<<<1, 128>>>(256, 1.0f/(float)N, 0);
    bn_apply_k<<<(N*HH + 255)/256, 256>>>(out2, HH, bn3_w, bn3_b, outp, N*HH);
}

// round 15
// speedup vs baseline: 1.1823x; 1.0424x over previous
#include <cuda_runtime.h>
#include <cuda_bf16.h>
#include <math.h>
#include <stdint.h>

typedef unsigned short u16;

// Problem constants
#define NN 32768
#define EE 262144
#define GG 64
#define HH 128

// ---------------- scratch ----------------------------------------------------
__device__ u16 g_wZU_h[256*384],  g_wZU_l[256*384];   // combined [zD | zS | U1] B
__device__ u16 g_wM0c_h[HH*HH],   g_wM0c_l[HH*HH];
__device__ u16 g_wM0d_h[HH*HH],   g_wM0d_l[HH*HH];
__device__ u16 g_wee_h[HH*HH],    g_wee_l[HH*HH];
__device__ u16 g_wM1_h[HH*HH],    g_wM1_l[HH*HH];
__device__ u16 g_wM2_h[HH*HH],    g_wM2_l[HH*HH];
__device__ u16 g_wM3_h[HH*HH],    g_wM3_l[HH*HH];
__device__ u16 g_wU2_h[HH*HH],    g_wU2_l[HH*HH];
__device__ u16 g_wQKV_h[3*HH*HH], g_wQKV_l[3*HH*HH];
__device__ u16 g_wWo_h[HH*HH],    g_wWo_l[HH*HH];
__device__ u16 g_wW1_h[2*HH*HH],  g_wW1_l[2*HH*HH];
__device__ u16 g_wW2_h[2*HH*HH],  g_wW2_l[2*HH*HH];
__device__ u16 g_wC_h[HH*HH],     g_wC_l[HH*HH];      // C = W_ee@M0c split
__device__ u16 g_wG_h[GG*HH],     g_wG_l[GG*HH];      // graph_fts split
// activations
__device__ float g_cvec[HH];
__device__ float g_GD[GG*HH];
__device__ float g_zc[(size_t)NN*384];                // [zD | zS | t1] strided 384
__device__ u16 g_z_h[NN*2*HH], g_z_l[NN*2*HH];
__device__ u16 g_m0h[(size_t)EE*HH], g_m0l[(size_t)EE*HH];
__device__ unsigned g_aggenc[NN*HH];
__device__ u16 g_agh[NN*HH], g_agl[NN*HH];
__device__ float g_qkv[NN*3*HH];
__device__ u16 g_oh[NN*HH], g_ol[NN*HH];
__device__ float g_t2[NN*HH];
__device__ float g_out[NN*HH];
__device__ u16 g_outh[NN*HH], g_outl[NN*HH];
__device__ u16 g_mlp1h[NN*2*HH], g_mlp1l[NN*2*HH];
__device__ float g_out2[NN*HH];
__device__ float g_part[256*256];
__device__ float g_stats[512];     // [0:256) = BN1 (mu, rstd), [256:512) = BN2

// ---------------- helpers ----------------------------------------------------
__device__ __forceinline__ float leaky_f(float v) { return v > 0.0f ? v : 0.01f*v; }

__device__ __forceinline__ float fast_exp(float x) {
    x = fmaxf(x, -87.0f);
    float t  = x * 1.4426950408889634f;
    float fl = floorf(t);
    float f  = t - fl;
    float p  =            1.339077600e-4f;
    p = p * f + 9.618437357e-4f;
    p = p * f + 9.556031144e-3f;
    p = p * f + 5.550332471e-2f;
    p = p * f + 2.402264923e-1f;
    p = p * f + 6.931471825e-1f;
    p = p * f + 1.0f;
    int ei = (int)fl;
    return __int_as_float((ei + 127) << 23) * p;
}

__device__ __forceinline__ unsigned enc_f(float f) {
    unsigned u = __float_as_uint(f);
    return (u & 0x80000000u) ? ~u : (u | 0x80000000u);
}
__device__ __forceinline__ float dec_f(unsigned u) {
    return (u & 0x80000000u) ? __uint_as_float(u ^ 0x80000000u) : __uint_as_float(~u);
}
#define ENC_NEGINF 0x007FFFFFu

__device__ __forceinline__ uint32_t smem_u32(const void* p) {
    uint32_t a;
    asm("{ .reg .u64 t; cvta.to.shared.u64 t, %1; cvt.u32.u64 %0, t; }" : "=r"(a) : "l"(p));
    return a;
}

__device__ __forceinline__ void split2(float v, u16& hi, u16& lo) {
    __nv_bfloat16 h = __float2bfloat16(v);
    float r = v - __bfloat162float(h);
    __nv_bfloat16 l = __float2bfloat16(r);
    hi = *reinterpret_cast<u16*>(&h);
    lo = *reinterpret_cast<u16*>(&l);
}

__device__ __forceinline__ void split4(float4 v, uint2& hi, uint2& lo) {
    u16 h0,l0,h1,l1,h2,l2,h3,l3;
    split2(v.x,h0,l0); split2(v.y,h1,l1); split2(v.z,h2,l2); split2(v.w,h3,l3);
    hi = make_uint2((uint32_t)h0 | ((uint32_t)h1<<16), (uint32_t)h2 | ((uint32_t)h3<<16));
    lo = make_uint2((uint32_t)l0 | ((uint32_t)l1<<16), (uint32_t)l2 | ((uint32_t)l3<<16));
}

// ---------------- MMA building blocks ----------------------------------------
#define LDM_X4(r, a) \
    asm volatile("ldmatrix.sync.aligned.m8n8.x4.shared.b16 {%0,%1,%2,%3}, [%4];" \
        : "=r"((r)[0]), "=r"((r)[1]), "=r"((r)[2]), "=r"((r)[3]) : "r"(a))
#define LDM_X4T(r, a) \
    asm volatile("ldmatrix.sync.aligned.m8n8.x4.trans.shared.b16 {%0,%1,%2,%3}, [%4];" \
        : "=r"((r)[0]), "=r"((r)[1]), "=r"((r)[2]), "=r"((r)[3]) : "r"(a))
#define MMA16816(c, a, b) \
    asm volatile("mma.sync.aligned.m16n8k16.row.col.f32.bf16.bf16.f32 " \
        "{%0,%1,%2,%3}, {%4,%5,%6,%7}, {%8,%9}, {%0,%1,%2,%3};" \
        : "+f"((c)[0]), "+f"((c)[1]), "+f"((c)[2]), "+f"((c)[3]) \
        : "r"((a)[0]), "r"((a)[1]), "r"((a)[2]), "r"((a)[3]), "r"((b)[0]), "r"((b)[1]))

#define CPA16(dst, src) asm volatile("cp.async.cg.shared.global [%0], [%1], 16;" :: "r"(dst), "l"(src))
#define CPA_COMMIT()    asm volatile("cp.async.commit_group;")
#define CPA_WAIT0()     asm volatile("cp.async.wait_group 0;" ::: "memory")

// XOR-swizzled offset inside a tile: rows of 256B, 16B chunks 0..15
__device__ __forceinline__ uint32_t swz(int row, int cb) {
    return (uint32_t)((row << 8) + (((cb ^ row) & 7) << 4) + ((cb & 8) << 4));
}

// ---------------- split-bf16 3-pass GEMM on mma.sync --------------------------
// Tile 64(M) x 128(N); 8 warps = 2x4; warp tile 32x32. RB M-subtiles reuse B.
template<int OUT, int ACT, bool BIAS, bool ACCUM, bool RESID, bool AF32>
__global__ void __launch_bounds__(256,2) gemm_ps(
    const void* Ah_, const u16* Al, int lda,
    const u16* __restrict__ Bh, const u16* __restrict__ Bl, int ldb,
    float* Cf, u16* Ch, u16* Cl, int ldc,
    const float* __restrict__ bias, const float* __restrict__ resid,
    const int* __restrict__ srcv, const int* __restrict__ dstv,
    const float* __restrict__ zD, const float* __restrict__ zS, int ldz,
    const float* __restrict__ GD, const float* __restrict__ cvec,
    unsigned* aggenc, int M, int N, int K, int PER, int tilesM, int RB)
{
    extern __shared__ char smem[];
    uint32_t sb = smem_u32(smem);
    const int tid = threadIdx.x;
    const int lane = tid & 31, w = tid >> 5;
    const int wm = w >> 2, wn = w & 3;
    const int ncol0 = blockIdx.x << 7;

    const uint32_t offB_h = 0;
    const uint32_t offB_l = (uint32_t)K * 256;
    const uint32_t offA_h = (uint32_t)K * 512;
    const uint32_t offA_l = offA_h + 16384;

    int ty0 = blockIdx.y * RB;
    int tyEnd = ty0 + RB; if (tyEnd > tilesM) tyEnd = tilesM;

    auto fillA = [&](int ty, int kc) {
        int mrow0 = ty << 6;
        if (AF32) {
            const float* Af = (const float*)Ah_;
            for (int idx = tid; idx < 64 * 16; idx += 256) {
                int row = idx >> 4, cb = idx & 15;
                const float* ap = Af + (size_t)(mrow0 + row) * lda + kc + cb * 8;
                float4 v0 = *reinterpret_cast<const float4*>(ap);
                float4 v1 = *reinterpret_cast<const float4*>(ap + 4);
                uint2 h0, l0, h1, l1;
                split4(v0, h0, l0); split4(v1, h1, l1);
                uint32_t d = swz(row, cb);
                *reinterpret_cast<uint4*>(smem + offA_h + d) = make_uint4(h0.x, h0.y, h1.x, h1.y);
                *reinterpret_cast<uint4*>(smem + offA_l + d) = make_uint4(l0.x, l0.y, l1.x, l1.y);
            }
        } else {
            const u16* Ah = (const u16*)Ah_;
            for (int idx = tid; idx < 64 * 16; idx += 256) {
                int row = idx >> 4, cb = idx & 15;
                size_t so = (size_t)(mrow0 + row) * lda + kc + cb * 8;
                uint32_t d = swz(row, cb);
                CPA16(sb + offA_h + d, Ah + so);
                CPA16(sb + offA_l + d, Al + so);
            }
            CPA_COMMIT();
        }
    };

    // ---- B fill (whole K) + first A chunk ----
    for (int idx = tid; idx < K * 16; idx += 256) {
        int row = idx >> 4, cb = idx & 15;
        size_t so = (size_t)row * ldb + ncol0 + cb * 8;
        uint32_t d = swz(row, cb);
        CPA16(sb + offB_h + d, Bh + so);
        CPA16(sb + offB_l + d, Bl + so);
    }
    CPA_COMMIT();
    fillA(ty0, 0);

    for (int ty = ty0; ty < tyEnd; ty++) {
        const int mrow0 = ty << 6;
        float acc[2][4][4];
        #pragma unroll
        for (int i = 0; i < 2; i++)
            #pragma unroll
            for (int j = 0; j < 4; j++)
                #pragma unroll
                for (int q = 0; q < 4; q++) acc[i][j][q] = 0.0f;

        for (int kc = 0; kc < K; kc += 128) {
            CPA_WAIT0();
            __syncthreads();

            #pragma unroll
            for (int kk = 0; kk < 8; kk++) {
                uint32_t ah[2][4], al[2][4];
                #pragma unroll
                for (int i = 0; i < 2; i++) {
                    int row = wm*32 + i*16 + (lane & 15);
                    uint32_t ad = sb + offA_h + swz(row, kk*2 + (lane >> 4));
                    LDM_X4(ah[i], ad);
                    LDM_X4(al[i], ad + 16384);
                }
                uint32_t bh[4][2], bl[4][2];
                #pragma unroll
                for (int jj = 0; jj < 2; jj++) {
                    int krow = kc + kk*16 + (lane & 15);
                    uint32_t bd = sb + offB_h + swz(krow, wn*4 + jj*2 + (lane >> 4));
                    uint32_t t[4];
                    LDM_X4T(t, bd);
                    bh[jj*2][0]=t[0]; bh[jj*2][1]=t[1]; bh[jj*2+1][0]=t[2]; bh[jj*2+1][1]=t[3];
                    LDM_X4T(t, bd + offB_l);
                    bl[jj*2][0]=t[0]; bl[jj*2][1]=t[1]; bl[jj*2+1][0]=t[2]; bl[jj*2+1][1]=t[3];
                }
                #pragma unroll
                for (int i = 0; i < 2; i++)
                    #pragma unroll
                    for (int j = 0; j < 4; j++) {
                        MMA16816(acc[i][j], ah[i], bh[j]);
                        MMA16816(acc[i][j], ah[i], bl[j]);
                        MMA16816(acc[i][j], al[i], bh[j]);
                    }
            }
            __syncthreads();
            // prefetch next chunk / next subtile (overlaps epilogue below)
            if (kc + 128 < K) fillA(ty, kc + 128);
            else if (ty + 1 < tyEnd) fillA(ty + 1, 0);
        }

        // ---- epilogue ----
        #pragma unroll
        for (int i = 0; i < 2; i++) {
            int r0 = mrow0 + wm*32 + i*16 + (lane >> 2);
            #pragma unroll
            for (int half = 0; half < 2; half++) {
                int r = r0 + half*8;
                int sidx = 0, didx = 0, gidx = 0;
                if (OUT == 2 || OUT == 3) didx = dstv[r];
                if (OUT == 3) { sidx = srcv[r]; gidx = didx / PER; }
                #pragma unroll
                for (int j = 0; j < 4; j++) {
                    int c = ncol0 + wn*32 + j*8 + (lane & 3)*2;
                    size_t idx = (size_t)r * ldc + c;
                    float vx = acc[i][j][half*2], vy = acc[i][j][half*2 + 1];
                    if (BIAS)  { vx += bias[c]; vy += bias[c + 1]; }
                    if (OUT == 3) {
                        vx += zD[(size_t)didx*ldz + c] + zS[(size_t)sidx*ldz + c]
                            + GD[(size_t)gidx*HH + c] + cvec[c];
                        vy += zD[(size_t)didx*ldz + c+1] + zS[(size_t)sidx*ldz + c+1]
                            + GD[(size_t)gidx*HH + c+1] + cvec[c+1];
                        vx = leaky_f(vx); vy = leaky_f(vy);
                        u16 hx,lx,hy,ly; split2(vx,hx,lx); split2(vy,hy,ly);
                        *reinterpret_cast<uint32_t*>(Ch + idx) = (uint32_t)hx | ((uint32_t)hy<<16);
                        *reinterpret_cast<uint32_t*>(Cl + idx) = (uint32_t)lx | ((uint32_t)ly<<16);
                    } else if (OUT == 2) {
                        atomicMax(&aggenc[didx*HH + c],   enc_f(vx));
                        atomicMax(&aggenc[didx*HH + c+1], enc_f(vy));
                    } else {
                        if (ACCUM) { float2 t = *reinterpret_cast<float2*>(Cf + idx); vx += t.x; vy += t.y; }
                        if (RESID) { float2 t = *reinterpret_cast<const float2*>(resid + (size_t)r*HH + c); vx += t.x; vy += t.y; }
                        if (ACT == 1) { vx = fmaxf(vx, 0.f); vy = fmaxf(vy, 0.f); }
                        else if (ACT == 2) { vx = leaky_f(vx); vy = leaky_f(vy); }
                        if (OUT == 1) {
                            u16 hx,lx,hy,ly; split2(vx,hx,lx); split2(vy,hy,ly);
                            *reinterpret_cast<uint32_t*>(Ch + idx) = (uint32_t)hx | ((uint32_t)hy<<16);
                            *reinterpret_cast<uint32_t*>(Cl + idx) = (uint32_t)lx | ((uint32_t)ly<<16);
                        } else {
                            *reinterpret_cast<float2*>(Cf + idx) = make_float2(vx, vy);
                        }
                    }
                }
            }
        }
    }
}

// ---------------- fused edge chain: m3 = leaky(leaky(m0@M1)@M2)@M3, seg-max ---
__global__ void __launch_bounds__(256,1) edge_chain_k(const int* __restrict__ dstv, int tiles)
{
    extern __shared__ char smem[];
    uint32_t sb = smem_u32(smem);
    const int tid = threadIdx.x;
    const int lane = tid & 31, w = tid >> 5;
    const int wm = w >> 2, wn = w & 3;
    const uint32_t offAct = 196608;           // hi; lo at +16384

    // ---- load all weights once (layer L: hi @ L*65536, lo @ +32768) ----
    {
        const u16* srcs[6] = { g_wM1_h, g_wM1_l, g_wM2_h, g_wM2_l, g_wM3_h, g_wM3_l };
        #pragma unroll
        for (int s = 0; s < 6; s++) {
            uint32_t base = sb + (uint32_t)s * 32768;
            const u16* W = srcs[s];
            for (int idx = tid; idx < 128 * 16; idx += 256) {
                int row = idx >> 4, cb = idx & 15;
                CPA16(base + swz(row, cb), W + (size_t)row * 128 + cb * 8);
            }
        }
        CPA_COMMIT();
    }

    auto fillAct = [&](int t) {
        int mrow0 = t << 6;
        for (int idx = tid; idx < 64 * 16; idx += 256) {
            int row = idx >> 4, cb = idx & 15;
            size_t so = (size_t)(mrow0 + row) * 128 + cb * 8;
            uint32_t d = swz(row, cb);
            CPA16(sb + offAct + d, g_m0h + so);
            CPA16(sb + offAct + 16384 + d, g_m0l + so);
        }
        CPA_COMMIT();
    };

    fillAct(blockIdx.x);
    CPA_WAIT0();
    __syncthreads();

    for (int t = blockIdx.x; t < tiles; t += gridDim.x) {
        int mrow0 = t << 6;

        #pragma unroll
        for (int layer = 0; layer < 3; layer++) {
            float acc[2][4][4];
            #pragma unroll
            for (int i = 0; i < 2; i++)
                #pragma unroll
                for (int j = 0; j < 4; j++)
                    #pragma unroll
                    for (int q = 0; q < 4; q++) acc[i][j][q] = 0.0f;

            uint32_t wbase = sb + (uint32_t)layer * 65536;
            #pragma unroll
            for (int kk = 0; kk < 8; kk++) {
                uint32_t ah[2][4], al[2][4];
                #pragma unroll
                for (int i = 0; i < 2; i++) {
                    int row = wm*32 + i*16 + (lane & 15);
                    uint32_t ad = sb + offAct + swz(row, kk*2 + (lane >> 4));
                    LDM_X4(ah[i], ad);
                    LDM_X4(al[i], ad + 16384);
                }
                uint32_t bh[4][2], bl[4][2];
                #pragma unroll
                for (int jj = 0; jj < 2; jj++) {
                    int krow = kk*16 + (lane & 15);
                    uint32_t bd = wbase + swz(krow, wn*4 + jj*2 + (lane >> 4));
                    uint32_t tt[4];
                    LDM_X4T(tt, bd);
                    bh[jj*2][0]=tt[0]; bh[jj*2][1]=tt[1]; bh[jj*2+1][0]=tt[2]; bh[jj*2+1][1]=tt[3];
                    LDM_X4T(tt, bd + 32768);
                    bl[jj*2][0]=tt[0]; bl[jj*2][1]=tt[1]; bl[jj*2+1][0]=tt[2]; bl[jj*2+1][1]=tt[3];
                }
                #pragma unroll
                for (int i = 0; i < 2; i++)
                    #pragma unroll
                    for (int j = 0; j < 4; j++) {
                        MMA16816(acc[i][j], ah[i], bh[j]);
                        MMA16816(acc[i][j], ah[i], bl[j]);
                        MMA16816(acc[i][j], al[i], bh[j]);
                    }
            }
            __syncthreads();     // all reads of act complete

            if (layer < 2) {
                #pragma unroll
                for (int i = 0; i < 2; i++) {
                    #pragma unroll
                    for (int half = 0; half < 2; half++) {
                        int rl = wm*32 + i*16 + (lane >> 2) + half*8;
                        #pragma unroll
                        for (int j = 0; j < 4; j++) {
                            int c = wn*32 + j*8 + (lane & 3)*2;
                            float vx = leaky_f(acc[i][j][half*2]);
                            float vy = leaky_f(acc[i][j][half*2 + 1]);
                            u16 hx,lx,hy,ly; split2(vx,hx,lx); split2(vy,hy,ly);
                            uint32_t d = swz(rl, c >> 3) + (c & 7) * 2;
                            *reinterpret_cast<uint32_t*>(smem + offAct + d) =
                                (uint32_t)hx | ((uint32_t)hy << 16);
                            *reinterpret_cast<uint32_t*>(smem + offAct + 16384 + d) =
                                (uint32_t)lx | ((uint32_t)ly << 16);
                        }
                    }
                }
                __syncthreads();
            } else {
                // act fully consumed: prefetch next tile while doing atomics
                int nt = t + gridDim.x;
                if (nt < tiles) fillAct(nt);
                #pragma unroll
                for (int i = 0; i < 2; i++) {
                    #pragma unroll
                    for (int half = 0; half < 2; half++) {
                        int r = mrow0 + wm*32 + i*16 + (lane >> 2) + half*8;
                        int didx = dstv[r];
                        #pragma unroll
                        for (int j = 0; j < 4; j++) {
                            int c = wn*32 + j*8 + (lane & 3)*2;
                            atomicMax(&g_aggenc[didx*HH + c],   enc_f(acc[i][j][half*2]));
                            atomicMax(&g_aggenc[didx*HH + c+1], enc_f(acc[i][j][half*2+1]));
                        }
                    }
                }
            }
        }
        if (t + gridDim.x < tiles) {
            CPA_WAIT0();
            __syncthreads();
        }
    }
}

// ---------------- small kernels (vectorized) ----------------------------------
__global__ void split_all_k(const float* __restrict__ M0, const float* __restrict__ W_ee,
                            const float* __restrict__ M1, const float* __restrict__ M2,
                            const float* __restrict__ M3, const float* __restrict__ U2,
                            const float* __restrict__ Wqkv, const float* __restrict__ Wo,
                            const float* __restrict__ W1, const float* __restrict__ W2,
                            const float* __restrict__ Gf)
{
    int i = (blockIdx.x*blockDim.x + threadIdx.x) * 4;
    struct Job { const float* s; u16* h; u16* l; int n; };
    const Job jobs[12] = {
        { M0 + (size_t)4*HH*HH, g_wM0c_h, g_wM0c_l, HH*HH },
        { M0 + (size_t)5*HH*HH, g_wM0d_h, g_wM0d_l, HH*HH },
        { W_ee, g_wee_h, g_wee_l, HH*HH },
        { M1, g_wM1_h, g_wM1_l, HH*HH },
        { M2, g_wM2_h, g_wM2_l, HH*HH },
        { M3, g_wM3_h, g_wM3_l, HH*HH },
        { U2, g_wU2_h, g_wU2_l, HH*HH },
        { Wqkv, g_wQKV_h, g_wQKV_l, 3*HH*HH },
        { Wo, g_wWo_h, g_wWo_l, HH*HH },
        { W1, g_wW1_h, g_wW1_l, 2*HH*HH },
        { W2, g_wW2_h, g_wW2_l, 2*HH*HH },
        { Gf, g_wG_h, g_wG_l, GG*HH },
    };
    #pragma unroll
    for (int j = 0; j < 12; j++) {
        if (i < jobs[j].n) {
            float4 v = *reinterpret_cast<const float4*>(jobs[j].s + i);
            uint2 h, l; split4(v, h, l);
            *reinterpret_cast<uint2*>(jobs[j].h + i) = h;
            *reinterpret_cast<uint2*>(jobs[j].l + i) = l;
            return;
        }
        i -= jobs[j].n;
    }
}
// 15*HH^2 + GG*HH total elements
#define SPLIT_ALL_TOTAL (15*HH*HH + GG*HH)

__global__ void build_zu_k(const float* __restrict__ M0, const float* __restrict__ U1)
{
    int i = blockIdx.x*blockDim.x + threadIdx.x;
    if (i >= 256*384) return;
    int k = i / 384, c = i - k*384;
    float v;
    if (c < 128)       v = M0[(size_t)k*HH + c];
    else if (c < 256)  v = M0[(size_t)(256 + k)*HH + (c - 128)];
    else               v = U1[(size_t)k*HH + (c - 256)];
    u16 h, l; split2(v, h, l);
    g_wZU_h[i] = h; g_wZU_l[i] = l;
}

__global__ void split_z_k(const float* __restrict__ node, const float* __restrict__ hid, int nvec)
{
    int idx = blockIdx.x*blockDim.x + threadIdx.x;
    if (idx >= nvec) return;
    int i8 = idx * 8;
    int row = i8 >> 8, col = i8 & 255;
    const float* src = (col < 128) ? (node + (size_t)row*HH + col) : (hid + (size_t)row*HH + col - 128);
    float4 v0 = *reinterpret_cast<const float4*>(src);
    float4 v1 = *reinterpret_cast<const float4*>(src + 4);
    uint2 h0, l0, h1, l1;
    split4(v0, h0, l0); split4(v1, h1, l1);
    *reinterpret_cast<uint4*>(g_z_h + i8) = make_uint4(h0.x, h0.y, h1.x, h1.y);
    *reinterpret_cast<uint4*>(g_z_l + i8) = make_uint4(l0.x, l0.y, l1.x, l1.y);
}

__global__ void cvec_k(const float* __restrict__ b_ee, const float* __restrict__ M0) {
    int j = threadIdx.x;
    float s = 0.0f;
    for (int t = 0; t < HH; t++) s += b_ee[t] * M0[(size_t)(4*HH + t)*HH + j];
    g_cvec[j] = s;
}

__global__ void agg_init_k(int nvec) {
    int i = blockIdx.x*blockDim.x + threadIdx.x;
    if (i < nvec)
        *reinterpret_cast<uint4*>(g_aggenc + i*4) =
            make_uint4(ENC_NEGINF, ENC_NEGINF, ENC_NEGINF, ENC_NEGINF);
}

__global__ void agg_decode_k(int nvec) {
    int idx = blockIdx.x*blockDim.x + threadIdx.x;
    if (idx >= nvec) return;
    int i = idx * 4;
    uint4 e = *reinterpret_cast<uint4*>(g_aggenc + i);
    float4 v;
    v.x = dec_f(e.x); v.y = dec_f(e.y); v.z = dec_f(e.z); v.w = dec_f(e.w);
    if (!isfinite(v.x)) v.x = 0.0f;
    if (!isfinite(v.y)) v.y = 0.0f;
    if (!isfinite(v.z)) v.z = 0.0f;
    if (!isfinite(v.w)) v.w = 0.0f;
    uint2 h, l; split4(v, h, l);
    *reinterpret_cast<uint2*>(g_agh + i) = h;
    *reinterpret_cast<uint2*>(g_agl + i) = l;
}

// attention: block = 256 queries of one (g,h); lazy online-softmax rescale
__global__ void __launch_bounds__(256) attn_k(const float* __restrict__ qkv, int PER)
{
    __shared__ float Ks[128][32];
    __shared__ float Vs[128][32];
    int g = blockIdx.x, h = blockIdx.y;
    int tid = threadIdx.x;
    int n = g*PER + blockIdx.z*256 + tid;
    const float scale = 0.17677669529663687f;
    float q[32];
    #pragma unroll
    for (int d = 0; d < 32; d++)
        q[d] = qkv[(size_t)n*384 + h*32 + d] * scale;

    float m = -INFINITY, l = 0.0f;
    float acc[32];
    #pragma unroll
    for (int d = 0; d < 32; d++) acc[d] = 0.0f;

    for (int c0 = 0; c0 < PER; c0 += 128) {
        __syncthreads();
        for (int i = tid; i < 128*32; i += 256) {
            int r = i >> 5, d = i & 31;
            size_t base = (size_t)(g*PER + c0 + r)*384 + h*32 + d;
            Ks[r][d] = qkv[base + 128];
            Vs[r][d] = qkv[base + 256];
        }
        __syncthreads();
        for (int j = 0; j < 128; j++) {
            float s = 0.0f;
            #pragma unroll
            for (int d = 0; d < 32; d++) s += q[d]*Ks[j][d];
            if (s > m) {
                float a = fast_exp(m - s);
                l = l*a + 1.0f;
                #pragma unroll
                for (int d = 0; d < 32; d++) acc[d] = acc[d]*a + Vs[j][d];
                m = s;
            } else {
                float p = fast_exp(s - m);
                l += p;
                #pragma unroll
                for (int d = 0; d < 32; d++) acc[d] += p*Vs[j][d];
            }
        }
    }
    float inv = 1.0f / l;
    #pragma unroll
    for (int d = 0; d < 32; d += 2) {
        float vx = acc[d]*inv, vy = acc[d+1]*inv;
        u16 hx,lx,hy,ly; split2(vx,hx,lx); split2(vy,hy,ly);
        size_t idx = (size_t)n*HH + h*32 + d;
        *reinterpret_cast<uint32_t*>(g_oh + idx) = (uint32_t)hx | ((uint32_t)hy<<16);
        *reinterpret_cast<uint32_t*>(g_ol + idx) = (uint32_t)lx | ((uint32_t)ly<<16);
    }
}

__global__ void bn_stats1_k(const float* __restrict__ x, int ld, int rowsPer) {
    int c = threadIdx.x;
    int b = blockIdx.x;
    size_t r0 = (size_t)b * rowsPer;
    float s = 0.0f, s2 = 0.0f;
    for (int r = 0; r < rowsPer; r++) {
        float v = x[(r0 + r)*ld + c];
        s += v; s2 += v*v;
    }
    g_part[b*256 + c] = s;
    g_part[b*256 + 128 + c] = s2;
}
__global__ void bn_stats2_k(int nb, float invN, int sbase) {
    int c = threadIdx.x;
    float s = 0.0f, s2 = 0.0f;
    for (int b = 0; b < nb; b++) { s += g_part[b*256 + c]; s2 += g_part[b*256 + 128 + c]; }
    float mu = s * invN;
    float var = s2 * invN - mu*mu;
    g_stats[sbase + c] = mu;
    g_stats[sbase + 128 + c] = rsqrtf(var + 1e-5f);
}
__global__ void bn_apply_k(const float* __restrict__ x, int ld, const float* __restrict__ w,
                           const float* __restrict__ b, float* __restrict__ y, int nvec)
{
    int idx = blockIdx.x*blockDim.x + threadIdx.x;
    if (idx >= nvec) return;
    int i = idx * 4;
    int c = i & 127;
    int row = i >> 7;
    float4 v = *reinterpret_cast<const float4*>(x + (size_t)row*ld + c);
    float4 o;
    o.x = (v.x - g_stats[c])   * g_stats[128 + c]   * w[c]   + b[c];
    o.y = (v.y - g_stats[c+1]) * g_stats[128 + c+1] * w[c+1] + b[c+1];
    o.z = (v.z - g_stats[c+2]) * g_stats[128 + c+2] * w[c+2] + b[c+2];
    o.w = (v.w - g_stats[c+3]) * g_stats[128 + c+3] * w[c+3] + b[c+3];
    *reinterpret_cast<float4*>(y + i) = o;
}

// fused: out = BN1(t1) + BN2(t2); writes fp32 + split hi/lo (vec4)
__global__ void bn12_add_split_k(const float* __restrict__ t1, int ld1,
                                 const float* __restrict__ t2,
                                 const float* __restrict__ w1, const float* __restrict__ b1,
                                 const float* __restrict__ w2, const float* __restrict__ b2,
                                 int nvec)
{
    int idx = blockIdx.x*blockDim.x + threadIdx.x;
    if (idx >= nvec) return;
    int i = idx * 4;
    int c = i & 127;
    int row = i >> 7;
    float4 a = *reinterpret_cast<const float4*>(t1 + (size_t)row*ld1 + c);
    float4 d = *reinterpret_cast<const float4*>(t2 + i);
    float4 v;
    v.x = (a.x - g_stats[c])   * g_stats[128+c]   * w1[c]   + b1[c]
        + (d.x - g_stats[256+c])   * g_stats[384+c]   * w2[c]   + b2[c];
    v.y = (a.y - g_stats[c+1]) * g_stats[128+c+1] * w1[c+1] + b1[c+1]
        + (d.y - g_stats[256+c+1]) * g_stats[384+c+1] * w2[c+1] + b2[c+1];
    v.z = (a.z - g_stats[c+2]) * g_stats[128+c+2] * w1[c+2] + b1[c+2]
        + (d.z - g_stats[256+c+2]) * g_stats[384+c+2] * w2[c+2] + b2[c+2];
    v.w = (a.w - g_stats[c+3]) * g_stats[128+c+3] * w1[c+3] + b1[c+3]
        + (d.w - g_stats[256+c+3]) * g_stats[384+c+3] * w2[c+3] + b2[c+3];
    *reinterpret_cast<float4*>(g_out + i) = v;
    uint2 h, l; split4(v, h, l);
    *reinterpret_cast<uint2*>(g_outh + i) = h;
    *reinterpret_cast<uint2*>(g_outl + i) = l;
}

// ---------------- host orchestration -----------------------------------------
template<int OUT, int ACT, bool BIAS, bool ACCUM, bool RESID, bool AF32>
static void run_gemm(const void* Ah, const u16* Al, int lda,
                     const u16* Bh, const u16* Bl, int ldb,
                     float* Cf, u16* Ch, u16* Cl, int ldc,
                     const float* bias, const float* resid,
                     const int* srcv, const int* dstv,
                     const float* zD, const float* zS, int ldz,
                     const float* GD, const float* cvec,
                     unsigned* aggenc, int M, int N, int K, int PER)
{
    auto kfn = gemm_ps<OUT,ACT,BIAS,ACCUM,RESID,AF32>;
    cudaFuncSetAttribute(kfn, cudaFuncAttributeMaxDynamicSharedMemorySize, 163840);
    size_t smemsz = (size_t)K*512 + 32768;
    int tilesM = (M + 63) / 64;
    int tilesN = N / 128;
    int RB = (tilesM * tilesN) / 304;
    if (RB < 1) RB = 1;
    if (RB > 8) RB = 8;
    int gy = (tilesM + RB - 1) / RB;
    dim3 grid(tilesN, gy);
    kfn<<<grid, 256, smemsz>>>(Ah, Al, lda, Bh, Bl, ldb, Cf, Ch, Cl, ldc, bias, resid,
                               srcv, dstv, zD, zS, ldz, GD, cvec, aggenc, M, N, K, PER, tilesM, RB);
}

#define SYMADDR(p, s) cudaGetSymbolAddress((void**)&p, s)

extern "C" void kernel_launch(void* const* d_in, const int* in_sizes, int n_in,
                              void* d_out, int out_size)
{
    const float* node_fts  = (const float*)d_in[0];
    const float* edge_attr = (const float*)d_in[1];
    const float* graph_fts = (const float*)d_in[2];
    const float* hidden    = (const float*)d_in[3];
    const float* W_ee      = (const float*)d_in[4];
    const float* b_ee      = (const float*)d_in[5];
    const float* M0        = (const float*)d_in[6];
    const float* M1        = (const float*)d_in[7];
    const float* M2        = (const float*)d_in[8];
    const float* M3        = (const float*)d_in[9];
    const float* U1        = (const float*)d_in[10];
    const float* U2        = (const float*)d_in[11];
    const float* Wqkv      = (const float*)d_in[12];
    const float* bqkv      = (const float*)d_in[13];
    const float* Wo        = (const float*)d_in[14];
    const float* bo        = (const float*)d_in[15];
    const float* bn1_w     = (const float*)d_in[16];
    const float* bn1_b     = (const float*)d_in[17];
    const float* bn2_w     = (const float*)d_in[18];
    const float* bn2_b     = (const float*)d_in[19];
    const float* bn3_w     = (const float*)d_in[20];
    const float* bn3_b     = (const float*)d_in[21];
    const float* W1        = (const float*)d_in[22];
    const float* b1        = (const float*)d_in[23];
    const float* W2        = (const float*)d_in[24];
    const float* b2        = (const float*)d_in[25];
    const int*   edge_index= (const int*)d_in[26];

    const int N = in_sizes[0] / HH;
    const int E = in_sizes[1] / HH;
    const int G = in_sizes[2] / HH;
    const int PER = N / G;
    const int* src = edge_index;
    const int* dst = edge_index + E;
    float* outp = (float*)d_out;

    u16 *wZU_h,*wZU_l,*wM0c_h,*wM0c_l,*wM0d_h,*wM0d_l,*wee_h,*wee_l;
    u16 *wU2_h,*wU2_l,*wQKV_h,*wQKV_l,*wWo_h,*wWo_l,*wW1_h,*wW1_l,*wW2_h,*wW2_l,*wC_h,*wC_l,*wG_h,*wG_l;
    u16 *z_h,*z_l,*m0h,*m0l,*agh,*agl,*oh,*ol,*outh,*outl,*mlp1h,*mlp1l;
    float *cvec,*GDp,*zc,*qkv,*t2,*outf,*out2;
    unsigned *aggenc;
    SYMADDR(wZU_h,g_wZU_h);   SYMADDR(wZU_l,g_wZU_l);
    SYMADDR(wM0c_h,g_wM0c_h); SYMADDR(wM0c_l,g_wM0c_l);
    SYMADDR(wM0d_h,g_wM0d_h); SYMADDR(wM0d_l,g_wM0d_l);
    SYMADDR(wee_h,g_wee_h);   SYMADDR(wee_l,g_wee_l);
    SYMADDR(wU2_h,g_wU2_h);   SYMADDR(wU2_l,g_wU2_l);
    SYMADDR(wQKV_h,g_wQKV_h); SYMADDR(wQKV_l,g_wQKV_l);
    SYMADDR(wWo_h,g_wWo_h);   SYMADDR(wWo_l,g_wWo_l);
    SYMADDR(wW1_h,g_wW1_h);   SYMADDR(wW1_l,g_wW1_l);
    SYMADDR(wW2_h,g_wW2_h);   SYMADDR(wW2_l,g_wW2_l);
    SYMADDR(wC_h,g_wC_h);     SYMADDR(wC_l,g_wC_l);
    SYMADDR(wG_h,g_wG_h);     SYMADDR(wG_l,g_wG_l);
    SYMADDR(z_h,g_z_h);       SYMADDR(z_l,g_z_l);
    SYMADDR(m0h,g_m0h); SYMADDR(m0l,g_m0l);
    SYMADDR(agh,g_agh); SYMADDR(agl,g_agl); SYMADDR(oh,g_oh); SYMADDR(ol,g_ol);
    SYMADDR(outh,g_outh); SYMADDR(outl,g_outl); SYMADDR(mlp1h,g_mlp1h); SYMADDR(mlp1l,g_mlp1l);
    SYMADDR(cvec,g_cvec); SYMADDR(GDp,g_GD); SYMADDR(zc,g_zc);
    SYMADDR(qkv,g_qkv); SYMADDR(t2,g_t2);
    SYMADDR(outf,g_out); SYMADDR(out2,g_out2);
    SYMADDR(aggenc,g_aggenc);

    // ---- weight prep (vectorized batched split + combined ZU + cvec + z) ---
    split_all_k<<<(SPLIT_ALL_TOTAL/4 + 255)/256, 256>>>(M0, W_ee, M1, M2, M3, U2,
                                                        Wqkv, Wo, W1, W2, graph_fts);
    build_zu_k<<<(256*384 + 255)/256, 256>>>(M0, U1);
    cvec_k<<<1, HH>>>(b_ee, M0);
    split_z_k<<<(N*256/8 + 255)/256, 256>>>(node_fts, hidden, N*256/8);
    agg_init_k<<<(N*HH/4 + 255)/256, 256>>>(N*HH/4);

    // ---- C = W_ee @ M0c (split out); GD = graph_fts @ M0d ------------------
    run_gemm<1,0,false,false,false,false>(wee_h, wee_l, HH, wM0c_h, wM0c_l, HH,
        nullptr, wC_h, wC_l, HH, nullptr, nullptr, nullptr, nullptr,
        nullptr, nullptr, 0, nullptr, nullptr, nullptr, HH, HH, HH, PER);
    run_gemm<0,0,false,false,false,false>(wG_h, wG_l, HH, wM0d_h, wM0d_l, HH,
        GDp, nullptr, nullptr, HH, nullptr, nullptr, nullptr, nullptr,
        nullptr, nullptr, 0, nullptr, nullptr, nullptr, G, HH, HH, PER);

    // ---- combined [zD | zS | t1] = z @ [M0a | M0b | U1]  (K=256, N=384) ----
    run_gemm<0,0,false,false,false,false>(z_h, z_l, 256, wZU_h, wZU_l, 384,
        zc, nullptr, nullptr, 384, nullptr, nullptr, nullptr, nullptr,
        nullptr, nullptr, 0, nullptr, nullptr, nullptr, N, 384, 256, PER);

    // ---- e0 GEMM + fused gather ------------------------------------------
    run_gemm<3,0,false,false,false,true>(edge_attr, nullptr, HH, wC_h, wC_l, HH,
        nullptr, m0h, m0l, HH, nullptr, nullptr, src, dst,
        zc, zc + 128, 384, GDp, cvec, nullptr, E, HH, HH, PER);

    // ---- fused M1->M2->M3 chain + seg-max atomics --------------------------
    {
        cudaFuncSetAttribute(edge_chain_k, cudaFuncAttributeMaxDynamicSharedMemorySize, 229376);
        edge_chain_k<<<152, 256, 229376>>>(dst, E/64);
    }
    agg_decode_k<<<(N*HH/4 + 255)/256, 256>>>(N*HH/4);

    // ---- t1 += agg@U2 + node_fts (t1 in zc cols 256..) ---------------------
    run_gemm<0,0,false,true,true,false>(agh, agl, HH, wU2_h, wU2_l, HH,
        zc + 256, nullptr, nullptr, 384, nullptr, node_fts, nullptr, nullptr,
        nullptr, nullptr, 0, nullptr, nullptr, nullptr, N, HH, HH, PER);
    bn_stats1_k<<<256, 128>>>(zc + 256, 384, N/256);
    bn_stats2_k<<<1, 128>>>(256, 1.0f/(float)N, 0);

    // ---- attention ---------------------------------------------------------
    run_gemm<0,0,true,false,false,false>(z_h, z_l, 256, wQKV_h, wQKV_l, 3*HH,
        qkv, nullptr, nullptr, 3*HH, bqkv, nullptr, nullptr, nullptr,
        nullptr, nullptr, 0, nullptr, nullptr, nullptr, N, 3*HH, HH, PER);
    attn_k<<<dim3(G, 4, PER/256), 256>>>(qkv, PER);
    run_gemm<0,0,true,false,true,false>(oh, ol, HH, wWo_h, wWo_l, HH,
        t2, nullptr, nullptr, HH, bo, node_fts, nullptr, nullptr,
        nullptr, nullptr, 0, nullptr, nullptr, nullptr, N, HH, HH, PER);
    bn_stats1_k<<<256, 128>>>(t2, HH, N/256);
    bn_stats2_k<<<1, 128>>>(256, 1.0f/(float)N, 256);

    // ---- fused BN1+BN2+add+split -------------------------------------------
    bn12_add_split_k<<<(N*HH/4 + 255)/256, 256>>>(zc + 256, 384, t2,
        bn1_w, bn1_b, bn2_w, bn2_b, N*HH/4);

    // ---- MLP ---------------------------------------------------------------
    run_gemm<1,1,true,false,false,false>(outh, outl, HH, wW1_h, wW1_l, 2*HH,
        nullptr, mlp1h, mlp1l, 2*HH, b1, nullptr, nullptr, nullptr,
        nullptr, nullptr, 0, nullptr, nullptr, nullptr, N, 2*HH, HH, PER);
    run_gemm<0,0,true,false,true,false>(mlp1h, mlp1l, 2*HH, wW2_h, wW2_l, HH,
        out2, nullptr, nullptr, HH, b2, outf, nullptr, nullptr,
        nullptr, nullptr, 0, nullptr, nullptr, nullptr, N, HH, 2*HH, PER);

    // ---- BN3 -> output ------------------------------------------------------
    bn_stats1_k<<<256, 128>>>(out2, HH, N/256);
    bn_stats2_k<<<1, 128>>>(256, 1.0f/(float)N, 0);
    bn_apply_k<<<(N*HH/4 + 255)/256, 256>>>(out2, HH, bn3_w, bn3_b, outp, N*HH/4);
}

// round 16
// speedup vs baseline: 1.5094x; 1.2766x over previous
#include <cuda_runtime.h>
#include <cuda_bf16.h>
#include <math.h>
#include <stdint.h>

typedef unsigned short u16;

// Problem constants
#define NN 32768
#define EE 262144
#define GG 64
#define HH 128

// ---------------- scratch ----------------------------------------------------
__device__ u16 g_wZU_h[256*384],  g_wZU_l[256*384];
__device__ u16 g_wM0c_h[HH*HH],   g_wM0c_l[HH*HH];
__device__ u16 g_wM0d_h[HH*HH],   g_wM0d_l[HH*HH];
__device__ u16 g_wee_h[HH*HH],    g_wee_l[HH*HH];
__device__ u16 g_wM1_h[HH*HH],    g_wM1_l[HH*HH];
__device__ u16 g_wM2_h[HH*HH],    g_wM2_l[HH*HH];
__device__ u16 g_wM3_h[HH*HH],    g_wM3_l[HH*HH];
__device__ u16 g_wU2_h[HH*HH],    g_wU2_l[HH*HH];
__device__ u16 g_wQKV_h[3*HH*HH], g_wQKV_l[3*HH*HH];
__device__ u16 g_wWo_h[HH*HH],    g_wWo_l[HH*HH];
__device__ u16 g_wW1_h[2*HH*HH],  g_wW1_l[2*HH*HH];
__device__ u16 g_wW2_h[2*HH*HH],  g_wW2_l[2*HH*HH];
__device__ u16 g_wC_h[HH*HH],     g_wC_l[HH*HH];
__device__ u16 g_wG_h[GG*HH],     g_wG_l[GG*HH];
// activations
__device__ float g_cvec[HH];
__device__ float g_GD[GG*HH];
__device__ float g_zc[(size_t)NN*384];
__device__ u16 g_z_h[NN*2*HH], g_z_l[NN*2*HH];
__device__ u16 g_m0h[(size_t)EE*HH], g_m0l[(size_t)EE*HH];
__device__ unsigned g_aggenc[NN*HH];
__device__ u16 g_agh[NN*HH], g_agl[NN*HH];
__device__ u16 g_qkvh[(size_t)NN*384], g_qkvl[(size_t)NN*384];
__device__ u16 g_oh[NN*HH], g_ol[NN*HH];
__device__ float g_t2[NN*HH];
__device__ float g_out[NN*HH];
__device__ u16 g_outh[NN*HH], g_outl[NN*HH];
__device__ u16 g_mlp1h[NN*2*HH], g_mlp1l[NN*2*HH];
__device__ float g_out2[NN*HH];
__device__ float g_part[256*256];
__device__ float g_stats[512];

// ---------------- helpers ----------------------------------------------------
__device__ __forceinline__ float leaky_f(float v) { return v > 0.0f ? v : 0.01f*v; }

__device__ __forceinline__ float fast_exp(float x) {
    x = fmaxf(x, -87.0f);
    float t  = x * 1.4426950408889634f;
    float fl = floorf(t);
    float f  = t - fl;
    float p  =            1.339077600e-4f;
    p = p * f + 9.618437357e-4f;
    p = p * f + 9.556031144e-3f;
    p = p * f + 5.550332471e-2f;
    p = p * f + 2.402264923e-1f;
    p = p * f + 6.931471825e-1f;
    p = p * f + 1.0f;
    int ei = (int)fl;
    return __int_as_float((ei + 127) << 23) * p;
}

__device__ __forceinline__ unsigned enc_f(float f) {
    unsigned u = __float_as_uint(f);
    return (u & 0x80000000u) ? ~u : (u | 0x80000000u);
}
__device__ __forceinline__ float dec_f(unsigned u) {
    return (u & 0x80000000u) ? __uint_as_float(u ^ 0x80000000u) : __uint_as_float(~u);
}
#define ENC_NEGINF 0x007FFFFFu

__device__ __forceinline__ uint32_t smem_u32(const void* p) {
    uint32_t a;
    asm("{ .reg .u64 t; cvta.to.shared.u64 t, %1; cvt.u32.u64 %0, t; }" : "=r"(a) : "l"(p));
    return a;
}

__device__ __forceinline__ void split2(float v, u16& hi, u16& lo) {
    __nv_bfloat16 h = __float2bfloat16(v);
    float r = v - __bfloat162float(h);
    __nv_bfloat16 l = __float2bfloat16(r);
    hi = *reinterpret_cast<u16*>(&h);
    lo = *reinterpret_cast<u16*>(&l);
}

__device__ __forceinline__ void split4(float4 v, uint2& hi, uint2& lo) {
    u16 h0,l0,h1,l1,h2,l2,h3,l3;
    split2(v.x,h0,l0); split2(v.y,h1,l1); split2(v.z,h2,l2); split2(v.w,h3,l3);
    hi = make_uint2((uint32_t)h0 | ((uint32_t)h1<<16), (uint32_t)h2 | ((uint32_t)h3<<16));
    lo = make_uint2((uint32_t)l0 | ((uint32_t)l1<<16), (uint32_t)l2 | ((uint32_t)l3<<16));
}

__device__ __forceinline__ uint32_t pack_split_hi(float a, float b) {
    u16 ha,la,hb,lb; split2(a,ha,la); split2(b,hb,lb);
    return (uint32_t)ha | ((uint32_t)hb<<16);
}
__device__ __forceinline__ void pack_split_both(float a, float b, uint32_t& hi, uint32_t& lo) {
    u16 ha,la,hb,lb; split2(a,ha,la); split2(b,hb,lb);
    hi = (uint32_t)ha | ((uint32_t)hb<<16);
    lo = (uint32_t)la | ((uint32_t)lb<<16);
}

// ---------------- MMA building blocks ----------------------------------------
#define LDM_X4(r, a) \
    asm volatile("ldmatrix.sync.aligned.m8n8.x4.shared.b16 {%0,%1,%2,%3}, [%4];" \
        : "=r"((r)[0]), "=r"((r)[1]), "=r"((r)[2]), "=r"((r)[3]) : "r"(a))
#define LDM_X4T(r, a) \
    asm volatile("ldmatrix.sync.aligned.m8n8.x4.trans.shared.b16 {%0,%1,%2,%3}, [%4];" \
        : "=r"((r)[0]), "=r"((r)[1]), "=r"((r)[2]), "=r"((r)[3]) : "r"(a))
#define MMA16816(c, a, b) \
    asm volatile("mma.sync.aligned.m16n8k16.row.col.f32.bf16.bf16.f32 " \
        "{%0,%1,%2,%3}, {%4,%5,%6,%7}, {%8,%9}, {%0,%1,%2,%3};" \
        : "+f"((c)[0]), "+f"((c)[1]), "+f"((c)[2]), "+f"((c)[3]) \
        : "r"((a)[0]), "r"((a)[1]), "r"((a)[2]), "r"((a)[3]), "r"((b)[0]), "r"((b)[1]))

#define CPA16(dst, src) asm volatile("cp.async.cg.shared.global [%0], [%1], 16;" :: "r"(dst), "l"(src))
#define CPA_COMMIT()    asm volatile("cp.async.commit_group;")
#define CPA_WAIT0()     asm volatile("cp.async.wait_group 0;" ::: "memory")

// XOR-swizzled offset inside a tile: rows of 256B, 16B chunks 0..15
__device__ __forceinline__ uint32_t swz(int row, int cb) {
    return (uint32_t)((row << 8) + (((cb ^ row) & 7) << 4) + ((cb & 8) << 4));
}

// ---------------- split-bf16 3-pass GEMM on mma.sync --------------------------
template<int OUT, int ACT, bool BIAS, bool ACCUM, bool RESID, bool AF32>
__global__ void __launch_bounds__(256,2) gemm_ps(
    const void* Ah_, const u16* Al, int lda,
    const u16* __restrict__ Bh, const u16* __restrict__ Bl, int ldb,
    float* Cf, u16* Ch, u16* Cl, int ldc,
    const float* __restrict__ bias, const float* __restrict__ resid,
    const int* __restrict__ srcv, const int* __restrict__ dstv,
    const float* __restrict__ zD, const float* __restrict__ zS, int ldz,
    const float* __restrict__ GD, const float* __restrict__ cvec,
    unsigned* aggenc, int M, int N, int K, int PER, int tilesM, int RB)
{
    extern __shared__ char smem[];
    uint32_t sb = smem_u32(smem);
    const int tid = threadIdx.x;
    const int lane = tid & 31, w = tid >> 5;
    const int wm = w >> 2, wn = w & 3;
    const int ncol0 = blockIdx.x << 7;

    const uint32_t offB_h = 0;
    const uint32_t offB_l = (uint32_t)K * 256;
    const uint32_t offA_h = (uint32_t)K * 512;
    const uint32_t offA_l = offA_h + 16384;

    int ty0 = blockIdx.y * RB;
    int tyEnd = ty0 + RB; if (tyEnd > tilesM) tyEnd = tilesM;

    auto fillA = [&](int ty, int kc) {
        int mrow0 = ty << 6;
        if (AF32) {
            const float* Af = (const float*)Ah_;
            for (int idx = tid; idx < 64 * 16; idx += 256) {
                int row = idx >> 4, cb = idx & 15;
                const float* ap = Af + (size_t)(mrow0 + row) * lda + kc + cb * 8;
                float4 v0 = *reinterpret_cast<const float4*>(ap);
                float4 v1 = *reinterpret_cast<const float4*>(ap + 4);
                uint2 h0, l0, h1, l1;
                split4(v0, h0, l0); split4(v1, h1, l1);
                uint32_t d = swz(row, cb);
                *reinterpret_cast<uint4*>(smem + offA_h + d) = make_uint4(h0.x, h0.y, h1.x, h1.y);
                *reinterpret_cast<uint4*>(smem + offA_l + d) = make_uint4(l0.x, l0.y, l1.x, l1.y);
            }
        } else {
            const u16* Ah = (const u16*)Ah_;
            for (int idx = tid; idx < 64 * 16; idx += 256) {
                int row = idx >> 4, cb = idx & 15;
                size_t so = (size_t)(mrow0 + row) * lda + kc + cb * 8;
                uint32_t d = swz(row, cb);
                CPA16(sb + offA_h + d, Ah + so);
                CPA16(sb + offA_l + d, Al + so);
            }
            CPA_COMMIT();
        }
    };

    for (int idx = tid; idx < K * 16; idx += 256) {
        int row = idx >> 4, cb = idx & 15;
        size_t so = (size_t)row * ldb + ncol0 + cb * 8;
        uint32_t d = swz(row, cb);
        CPA16(sb + offB_h + d, Bh + so);
        CPA16(sb + offB_l + d, Bl + so);
    }
    CPA_COMMIT();
    fillA(ty0, 0);

    for (int ty = ty0; ty < tyEnd; ty++) {
        const int mrow0 = ty << 6;
        float acc[2][4][4];
        #pragma unroll
        for (int i = 0; i < 2; i++)
            #pragma unroll
            for (int j = 0; j < 4; j++)
                #pragma unroll
                for (int q = 0; q < 4; q++) acc[i][j][q] = 0.0f;

        for (int kc = 0; kc < K; kc += 128) {
            CPA_WAIT0();
            __syncthreads();

            #pragma unroll
            for (int kk = 0; kk < 8; kk++) {
                uint32_t ah[2][4], al[2][4];
                #pragma unroll
                for (int i = 0; i < 2; i++) {
                    int row = wm*32 + i*16 + (lane & 15);
                    uint32_t ad = sb + offA_h + swz(row, kk*2 + (lane >> 4));
                    LDM_X4(ah[i], ad);
                    LDM_X4(al[i], ad + 16384);
                }
                uint32_t bh[4][2], bl[4][2];
                #pragma unroll
                for (int jj = 0; jj < 2; jj++) {
                    int krow = kc + kk*16 + (lane & 15);
                    uint32_t bd = sb + offB_h + swz(krow, wn*4 + jj*2 + (lane >> 4));
                    uint32_t t[4];
                    LDM_X4T(t, bd);
                    bh[jj*2][0]=t[0]; bh[jj*2][1]=t[1]; bh[jj*2+1][0]=t[2]; bh[jj*2+1][1]=t[3];
                    LDM_X4T(t, bd + offB_l);
                    bl[jj*2][0]=t[0]; bl[jj*2][1]=t[1]; bl[jj*2+1][0]=t[2]; bl[jj*2+1][1]=t[3];
                }
                #pragma unroll
                for (int i = 0; i < 2; i++)
                    #pragma unroll
                    for (int j = 0; j < 4; j++) {
                        MMA16816(acc[i][j], ah[i], bh[j]);
                        MMA16816(acc[i][j], ah[i], bl[j]);
                        MMA16816(acc[i][j], al[i], bh[j]);
                    }
            }
            __syncthreads();
            if (kc + 128 < K) fillA(ty, kc + 128);
            else if (ty + 1 < tyEnd) fillA(ty + 1, 0);
        }

        #pragma unroll
        for (int i = 0; i < 2; i++) {
            int r0 = mrow0 + wm*32 + i*16 + (lane >> 2);
            #pragma unroll
            for (int half = 0; half < 2; half++) {
                int r = r0 + half*8;
                int sidx = 0, didx = 0, gidx = 0;
                if (OUT == 2 || OUT == 3) didx = dstv[r];
                if (OUT == 3) { sidx = srcv[r]; gidx = didx / PER; }
                #pragma unroll
                for (int j = 0; j < 4; j++) {
                    int c = ncol0 + wn*32 + j*8 + (lane & 3)*2;
                    size_t idx = (size_t)r * ldc + c;
                    float vx = acc[i][j][half*2], vy = acc[i][j][half*2 + 1];
                    if (BIAS)  { vx += bias[c]; vy += bias[c + 1]; }
                    if (OUT == 3) {
                        vx += zD[(size_t)didx*ldz + c] + zS[(size_t)sidx*ldz + c]
                            + GD[(size_t)gidx*HH + c] + cvec[c];
                        vy += zD[(size_t)didx*ldz + c+1] + zS[(size_t)sidx*ldz + c+1]
                            + GD[(size_t)gidx*HH + c+1] + cvec[c+1];
                        vx = leaky_f(vx); vy = leaky_f(vy);
                        uint32_t ph, pl; pack_split_both(vx, vy, ph, pl);
                        *reinterpret_cast<uint32_t*>(Ch + idx) = ph;
                        *reinterpret_cast<uint32_t*>(Cl + idx) = pl;
                    } else if (OUT == 2) {
                        atomicMax(&aggenc[didx*HH + c],   enc_f(vx));
                        atomicMax(&aggenc[didx*HH + c+1], enc_f(vy));
                    } else {
                        if (ACCUM) { float2 t = *reinterpret_cast<float2*>(Cf + idx); vx += t.x; vy += t.y; }
                        if (RESID) { float2 t = *reinterpret_cast<const float2*>(resid + (size_t)r*HH + c); vx += t.x; vy += t.y; }
                        if (ACT == 1) { vx = fmaxf(vx, 0.f); vy = fmaxf(vy, 0.f); }
                        else if (ACT == 2) { vx = leaky_f(vx); vy = leaky_f(vy); }
                        if (OUT == 1) {
                            uint32_t ph, pl; pack_split_both(vx, vy, ph, pl);
                            *reinterpret_cast<uint32_t*>(Ch + idx) = ph;
                            *reinterpret_cast<uint32_t*>(Cl + idx) = pl;
                        } else {
                            *reinterpret_cast<float2*>(Cf + idx) = make_float2(vx, vy);
                        }
                    }
                }
            }
        }
    }
}

// ---------------- fused edge chain ------------------------------------------
__global__ void __launch_bounds__(256,1) edge_chain_k(const int* __restrict__ dstv, int tiles)
{
    extern __shared__ char smem[];
    uint32_t sb = smem_u32(smem);
    const int tid = threadIdx.x;
    const int lane = tid & 31, w = tid >> 5;
    const int wm = w >> 2, wn = w & 3;
    const uint32_t offAct = 196608;

    {
        const u16* srcs[6] = { g_wM1_h, g_wM1_l, g_wM2_h, g_wM2_l, g_wM3_h, g_wM3_l };
        #pragma unroll
        for (int s = 0; s < 6; s++) {
            uint32_t base = sb + (uint32_t)s * 32768;
            const u16* W = srcs[s];
            for (int idx = tid; idx < 128 * 16; idx += 256) {
                int row = idx >> 4, cb = idx & 15;
                CPA16(base + swz(row, cb), W + (size_t)row * 128 + cb * 8);
            }
        }
        CPA_COMMIT();
    }

    auto fillAct = [&](int t) {
        int mrow0 = t << 6;
        for (int idx = tid; idx < 64 * 16; idx += 256) {
            int row = idx >> 4, cb = idx & 15;
            size_t so = (size_t)(mrow0 + row) * 128 + cb * 8;
            uint32_t d = swz(row, cb);
            CPA16(sb + offAct + d, g_m0h + so);
            CPA16(sb + offAct + 16384 + d, g_m0l + so);
        }
        CPA_COMMIT();
    };

    fillAct(blockIdx.x);
    CPA_WAIT0();
    __syncthreads();

    for (int t = blockIdx.x; t < tiles; t += gridDim.x) {
        int mrow0 = t << 6;

        #pragma unroll
        for (int layer = 0; layer < 3; layer++) {
            float acc[2][4][4];
            #pragma unroll
            for (int i = 0; i < 2; i++)
                #pragma unroll
                for (int j = 0; j < 4; j++)
                    #pragma unroll
                    for (int q = 0; q < 4; q++) acc[i][j][q] = 0.0f;

            uint32_t wbase = sb + (uint32_t)layer * 65536;
            #pragma unroll
            for (int kk = 0; kk < 8; kk++) {
                uint32_t ah[2][4], al[2][4];
                #pragma unroll
                for (int i = 0; i < 2; i++) {
                    int row = wm*32 + i*16 + (lane & 15);
                    uint32_t ad = sb + offAct + swz(row, kk*2 + (lane >> 4));
                    LDM_X4(ah[i], ad);
                    LDM_X4(al[i], ad + 16384);
                }
                uint32_t bh[4][2], bl[4][2];
                #pragma unroll
                for (int jj = 0; jj < 2; jj++) {
                    int krow = kk*16 + (lane & 15);
                    uint32_t bd = wbase + swz(krow, wn*4 + jj*2 + (lane >> 4));
                    uint32_t tt[4];
                    LDM_X4T(tt, bd);
                    bh[jj*2][0]=tt[0]; bh[jj*2][1]=tt[1]; bh[jj*2+1][0]=tt[2]; bh[jj*2+1][1]=tt[3];
                    LDM_X4T(tt, bd + 32768);
                    bl[jj*2][0]=tt[0]; bl[jj*2][1]=tt[1]; bl[jj*2+1][0]=tt[2]; bl[jj*2+1][1]=tt[3];
                }
                #pragma unroll
                for (int i = 0; i < 2; i++)
                    #pragma unroll
                    for (int j = 0; j < 4; j++) {
                        MMA16816(acc[i][j], ah[i], bh[j]);
                        MMA16816(acc[i][j], ah[i], bl[j]);
                        MMA16816(acc[i][j], al[i], bh[j]);
                    }
            }
            __syncthreads();

            if (layer < 2) {
                #pragma unroll
                for (int i = 0; i < 2; i++) {
                    #pragma unroll
                    for (int half = 0; half < 2; half++) {
                        int rl = wm*32 + i*16 + (lane >> 2) + half*8;
                        #pragma unroll
                        for (int j = 0; j < 4; j++) {
                            int c = wn*32 + j*8 + (lane & 3)*2;
                            float vx = leaky_f(acc[i][j][half*2]);
                            float vy = leaky_f(acc[i][j][half*2 + 1]);
                            uint32_t ph, pl; pack_split_both(vx, vy, ph, pl);
                            uint32_t d = swz(rl, c >> 3) + (c & 7) * 2;
                            *reinterpret_cast<uint32_t*>(smem + offAct + d) = ph;
                            *reinterpret_cast<uint32_t*>(smem + offAct + 16384 + d) = pl;
                        }
                    }
                }
                __syncthreads();
            } else {
                int nt = t + gridDim.x;
                if (nt < tiles) fillAct(nt);
                #pragma unroll
                for (int i = 0; i < 2; i++) {
                    #pragma unroll
                    for (int half = 0; half < 2; half++) {
                        int r = mrow0 + wm*32 + i*16 + (lane >> 2) + half*8;
                        int didx = dstv[r];
                        #pragma unroll
                        for (int j = 0; j < 4; j++) {
                            int c = wn*32 + j*8 + (lane & 3)*2;
                            atomicMax(&g_aggenc[didx*HH + c],   enc_f(acc[i][j][half*2]));
                            atomicMax(&g_aggenc[didx*HH + c+1], enc_f(acc[i][j][half*2+1]));
                        }
                    }
                }
            }
        }
        if (t + gridDim.x < tiles) {
            CPA_WAIT0();
            __syncthreads();
        }
    }
}

// ---------------- flash attention on mma.sync ---------------------------------
// CTA = 64 queries of one (g,h); key tiles of 128; split-bf16 3-pass QK and PV.
// Q/K/V staged in smem (80B row stride). P reused from S registers (FA2 style).
#define AT_QH 0
#define AT_QL 5120
#define AT_KH 10240
#define AT_KL 20480
#define AT_VH 30720
#define AT_VL 40960
#define AT_ST 51200
#define AT_O  10240
#define AT_SMEM 52224

__global__ void __launch_bounds__(256) attn_mma_k(
    const u16* __restrict__ qh, const u16* __restrict__ ql, int PER)
{
    extern __shared__ char smem[];
    uint32_t sb = smem_u32(smem);
    const int tid = threadIdx.x;
    const int lane = tid & 31, w = tid >> 5;
    const int wm = w >> 2, wn = w & 3;
    const int g = blockIdx.x, h = blockIdx.y, qb = blockIdx.z;
    const int nbase = g*PER + qb*64;
    const float scale = 0.17677669529663687f;

    // Q tile (64 x 32, hi/lo)
    for (int idx = tid; idx < 64*4; idx += 256) {
        int r = idx >> 2, cb = idx & 3;
        size_t so = (size_t)(nbase + r)*384 + h*32 + cb*8;
        CPA16(sb + AT_QH + r*80 + cb*16, qh + so);
        CPA16(sb + AT_QL + r*80 + cb*16, ql + so);
    }
    CPA_COMMIT();

    float o[2][4][4];
    #pragma unroll
    for (int i=0;i<2;i++)
        #pragma unroll
        for (int j=0;j<4;j++)
            #pragma unroll
            for (int q=0;q<4;q++) o[i][j][q]=0.f;
    float m_run[2][2], l_run[2][2];
    #pragma unroll
    for (int i=0;i<2;i++)
        #pragma unroll
        for (int hf=0;hf<2;hf++){ m_run[i][hf]=-1e30f; l_run[i][hf]=0.f; }

    for (int c0 = 0; c0 < PER; c0 += 128) {
        // K,V tile (128 x 32 each, hi/lo)
        for (int idx = tid; idx < 128*4; idx += 256) {
            int r = idx >> 2, cb = idx & 3;
            size_t sk = (size_t)(g*PER + c0 + r)*384 + h*32 + 128 + cb*8;
            CPA16(sb + AT_KH + r*80 + cb*16, qh + sk);
            CPA16(sb + AT_KL + r*80 + cb*16, ql + sk);
            CPA16(sb + AT_VH + r*80 + cb*16, qh + sk + 128);
            CPA16(sb + AT_VL + r*80 + cb*16, ql + sk + 128);
        }
        CPA_COMMIT(); CPA_WAIT0();
        __syncthreads();

        // ---- S = Q @ K^T (3-pass) ----
        float s[2][4][4];
        #pragma unroll
        for (int i=0;i<2;i++)
            #pragma unroll
            for (int j=0;j<4;j++)
                #pragma unroll
                for (int q=0;q<4;q++) s[i][j][q]=0.f;

        #pragma unroll
        for (int kk = 0; kk < 2; kk++) {
            uint32_t ah[2][4], al[2][4];
            #pragma unroll
            for (int i=0;i<2;i++) {
                uint32_t ad = sb + AT_QH + (uint32_t)((wm*32 + i*16 + (lane&15))*80 + (kk*2 + (lane>>4))*16);
                LDM_X4(ah[i], ad);
                LDM_X4(al[i], ad + (AT_QL - AT_QH));
            }
            uint32_t bh[4][2], bl[4][2];
            #pragma unroll
            for (int jj=0;jj<2;jj++) {
                uint32_t bd = sb + AT_KH + (uint32_t)((wn*32 + jj*16 + (lane&15))*80 + (kk*2 + (lane>>4))*16);
                uint32_t t[4];
                LDM_X4(t, bd);
                bh[jj*2][0]=t[0]; bh[jj*2][1]=t[2]; bh[jj*2+1][0]=t[1]; bh[jj*2+1][1]=t[3];
                LDM_X4(t, bd + (AT_KL - AT_KH));
                bl[jj*2][0]=t[0]; bl[jj*2][1]=t[2]; bl[jj*2+1][0]=t[1]; bl[jj*2+1][1]=t[3];
            }
            #pragma unroll
            for (int i=0;i<2;i++)
                #pragma unroll
                for (int j=0;j<4;j++) {
                    MMA16816(s[i][j], ah[i], bh[j]);
                    MMA16816(s[i][j], ah[i], bl[j]);
                    MMA16816(s[i][j], al[i], bh[j]);
                }
        }
        #pragma unroll
        for (int i=0;i<2;i++)
            #pragma unroll
            for (int j=0;j<4;j++)
                #pragma unroll
                for (int q=0;q<4;q++) s[i][j][q] *= scale;

        // ---- row max (quad shuffle + cross-warp smem) ----
        #pragma unroll
        for (int i=0;i<2;i++)
            #pragma unroll
            for (int hf=0;hf<2;hf++) {
                float mx = -1e30f;
                #pragma unroll
                for (int j=0;j<4;j++) {
                    mx = fmaxf(mx, s[i][j][hf*2]);
                    mx = fmaxf(mx, s[i][j][hf*2+1]);
                }
                mx = fmaxf(mx, __shfl_xor_sync(0xffffffffu, mx, 1));
                mx = fmaxf(mx, __shfl_xor_sync(0xffffffffu, mx, 2));
                if ((lane&3)==0) {
                    int r = wm*32 + i*16 + (lane>>2) + hf*8;
                    *reinterpret_cast<float*>(smem + AT_ST + (r*4 + wn)*4) = mx;
                }
            }
        __syncthreads();
        float a_f[2][2], mnew[2][2];
        #pragma unroll
        for (int i=0;i<2;i++)
            #pragma unroll
            for (int hf=0;hf<2;hf++) {
                int r = wm*32 + i*16 + (lane>>2) + hf*8;
                const float* st = reinterpret_cast<const float*>(smem + AT_ST) + r*4;
                float mt = fmaxf(fmaxf(st[0], st[1]), fmaxf(st[2], st[3]));
                float mn = fmaxf(m_run[i][hf], mt);
                a_f[i][hf] = fast_exp(m_run[i][hf] - mn);
                mnew[i][hf] = mn;
                m_run[i][hf] = mn;
            }
        __syncthreads();

        // ---- p = exp(s - m), row sums ----
        #pragma unroll
        for (int i=0;i<2;i++)
            #pragma unroll
            for (int hf=0;hf<2;hf++) {
                float sum = 0.f;
                #pragma unroll
                for (int j=0;j<4;j++) {
                    float p0 = fast_exp(s[i][j][hf*2]   - mnew[i][hf]);
                    float p1 = fast_exp(s[i][j][hf*2+1] - mnew[i][hf]);
                    s[i][j][hf*2] = p0; s[i][j][hf*2+1] = p1;
                    sum += p0 + p1;
                }
                sum += __shfl_xor_sync(0xffffffffu, sum, 1);
                sum += __shfl_xor_sync(0xffffffffu, sum, 2);
                if ((lane&3)==0) {
                    int r = wm*32 + i*16 + (lane>>2) + hf*8;
                    *reinterpret_cast<float*>(smem + AT_ST + (r*4 + wn)*4) = sum;
                }
            }
        __syncthreads();
        #pragma unroll
        for (int i=0;i<2;i++)
            #pragma unroll
            for (int hf=0;hf<2;hf++) {
                int r = wm*32 + i*16 + (lane>>2) + hf*8;
                const float* st = reinterpret_cast<const float*>(smem + AT_ST) + r*4;
                l_run[i][hf] = l_run[i][hf]*a_f[i][hf] + (st[0]+st[1]+st[2]+st[3]);
            }

        // ---- rescale O, PV accumulate (3-pass, P from registers) ----
        #pragma unroll
        for (int i=0;i<2;i++)
            #pragma unroll
            for (int j=0;j<4;j++)
                #pragma unroll
                for (int q=0;q<4;q++) o[i][j][q] *= a_f[i][q>>1];

        #pragma unroll
        for (int kk2 = 0; kk2 < 2; kk2++) {
            uint32_t pah[2][4], pal[2][4];
            #pragma unroll
            for (int i=0;i<2;i++) {
                int j0 = kk2*2;
                pack_split_both(s[i][j0][0],   s[i][j0][1],   pah[i][0], pal[i][0]);
                pack_split_both(s[i][j0][2],   s[i][j0][3],   pah[i][1], pal[i][1]);
                pack_split_both(s[i][j0+1][0], s[i][j0+1][1], pah[i][2], pal[i][2]);
                pack_split_both(s[i][j0+1][2], s[i][j0+1][3], pah[i][3], pal[i][3]);
            }
            uint32_t bvh[4][2], bvl[4][2];
            #pragma unroll
            for (int jj2=0;jj2<2;jj2++) {
                uint32_t vd = sb + AT_VH + (uint32_t)((wn*32 + kk2*16 + (lane&15))*80 + (jj2*2 + (lane>>4))*16);
                uint32_t t[4];
                LDM_X4T(t, vd);
                bvh[jj2*2][0]=t[0]; bvh[jj2*2][1]=t[1]; bvh[jj2*2+1][0]=t[2]; bvh[jj2*2+1][1]=t[3];
                LDM_X4T(t, vd + (AT_VL - AT_VH));
                bvl[jj2*2][0]=t[0]; bvl[jj2*2][1]=t[1]; bvl[jj2*2+1][0]=t[2]; bvl[jj2*2+1][1]=t[3];
            }
            #pragma unroll
            for (int i=0;i<2;i++)
                #pragma unroll
                for (int j=0;j<4;j++) {
                    MMA16816(o[i][j], pah[i], bvh[j]);
                    MMA16816(o[i][j], pah[i], bvl[j]);
                    MMA16816(o[i][j], pal[i], bvh[j]);
                }
        }
        __syncthreads();   // protect K/V smem before next tile's loads
    }

    // ---- cross-warp O reduction + final store ----
    #pragma unroll
    for (int i=0;i<2;i++)
        #pragma unroll
        for (int j=0;j<4;j++)
            #pragma unroll
            for (int q=0;q<4;q++) {
                int r = wm*32 + i*16 + (lane>>2) + ((q>>1)<<3);
                int c = j*8 + (lane&3)*2 + (q&1);
                *reinterpret_cast<float*>(smem + AT_O + (((wn*64)+r)*32 + c)*4) = o[i][j][q];
            }
    if (wn == 0 && (lane&3)==0) {
        #pragma unroll
        for (int i=0;i<2;i++)
            #pragma unroll
            for (int hf=0;hf<2;hf++) {
                int r = wm*32 + i*16 + (lane>>2) + hf*8;
                *reinterpret_cast<float*>(smem + AT_ST + r*4) = l_run[i][hf];
            }
    }
    __syncthreads();
    {
        int r = tid >> 2;
        int cbase = (tid & 3) * 8;
        float linv = 1.0f / *reinterpret_cast<float*>(smem + AT_ST + r*4);
        size_t nrow = (size_t)(nbase + r)*HH + h*32;
        #pragma unroll
        for (int e = 0; e < 8; e += 2) {
            int c = cbase + e;
            float v0 = 0.f, v1 = 0.f;
            #pragma unroll
            for (int p = 0; p < 4; p++) {
                v0 += *reinterpret_cast<float*>(smem + AT_O + (((p*64)+r)*32 + c)*4);
                v1 += *reinterpret_cast<float*>(smem + AT_O + (((p*64)+r)*32 + c+1)*4);
            }
            v0 *= linv; v1 *= linv;
            uint32_t ph, pl; pack_split_both(v0, v1, ph, pl);
            *reinterpret_cast<uint32_t*>(g_oh + nrow + c) = ph;
            *reinterpret_cast<uint32_t*>(g_ol + nrow + c) = pl;
        }
    }
}

// ---------------- small kernels (vectorized) ----------------------------------
__global__ void split_all_k(const float* __restrict__ M0, const float* __restrict__ W_ee,
                            const float* __restrict__ M1, const float* __restrict__ M2,
                            const float* __restrict__ M3, const float* __restrict__ U2,
                            const float* __restrict__ Wqkv, const float* __restrict__ Wo,
                            const float* __restrict__ W1, const float* __restrict__ W2,
                            const float* __restrict__ Gf)
{
    int i = (blockIdx.x*blockDim.x + threadIdx.x) * 4;
    struct Job { const float* s; u16* h; u16* l; int n; };
    const Job jobs[12] = {
        { M0 + (size_t)4*HH*HH, g_wM0c_h, g_wM0c_l, HH*HH },
        { M0 + (size_t)5*HH*HH, g_wM0d_h, g_wM0d_l, HH*HH },
        { W_ee, g_wee_h, g_wee_l, HH*HH },
        { M1, g_wM1_h, g_wM1_l, HH*HH },
        { M2, g_wM2_h, g_wM2_l, HH*HH },
        { M3, g_wM3_h, g_wM3_l, HH*HH },
        { U2, g_wU2_h, g_wU2_l, HH*HH },
        { Wqkv, g_wQKV_h, g_wQKV_l, 3*HH*HH },
        { Wo, g_wWo_h, g_wWo_l, HH*HH },
        { W1, g_wW1_h, g_wW1_l, 2*HH*HH },
        { W2, g_wW2_h, g_wW2_l, 2*HH*HH },
        { Gf, g_wG_h, g_wG_l, GG*HH },
    };
    #pragma unroll
    for (int j = 0; j < 12; j++) {
        if (i < jobs[j].n) {
            float4 v = *reinterpret_cast<const float4*>(jobs[j].s + i);
            uint2 h, l; split4(v, h, l);
            *reinterpret_cast<uint2*>(jobs[j].h + i) = h;
            *reinterpret_cast<uint2*>(jobs[j].l + i) = l;
            return;
        }
        i -= jobs[j].n;
    }
}
#define SPLIT_ALL_TOTAL (15*HH*HH + GG*HH)

__global__ void build_zu_k(const float* __restrict__ M0, const float* __restrict__ U1)
{
    int i = blockIdx.x*blockDim.x + threadIdx.x;
    if (i >= 256*384) return;
    int k = i / 384, c = i - k*384;
    float v;
    if (c < 128)       v = M0[(size_t)k*HH + c];
    else if (c < 256)  v = M0[(size_t)(256 + k)*HH + (c - 128)];
    else               v = U1[(size_t)k*HH + (c - 256)];
    u16 h, l; split2(v, h, l);
    g_wZU_h[i] = h; g_wZU_l[i] = l;
}

__global__ void split_z_k(const float* __restrict__ node, const float* __restrict__ hid, int nvec)
{
    int idx = blockIdx.x*blockDim.x + threadIdx.x;
    if (idx >= nvec) return;
    int i8 = idx * 8;
    int row = i8 >> 8, col = i8 & 255;
    const float* src = (col < 128) ? (node + (size_t)row*HH + col) : (hid + (size_t)row*HH + col - 128);
    float4 v0 = *reinterpret_cast<const float4*>(src);
    float4 v1 = *reinterpret_cast<const float4*>(src + 4);
    uint2 h0, l0, h1, l1;
    split4(v0, h0, l0); split4(v1, h1, l1);
    *reinterpret_cast<uint4*>(g_z_h + i8) = make_uint4(h0.x, h0.y, h1.x, h1.y);
    *reinterpret_cast<uint4*>(g_z_l + i8) = make_uint4(l0.x, l0.y, l1.x, l1.y);
}

__global__ void cvec_k(const float* __restrict__ b_ee, const float* __restrict__ M0) {
    int j = threadIdx.x;
    float s = 0.0f;
    for (int t = 0; t < HH; t++) s += b_ee[t] * M0[(size_t)(4*HH + t)*HH + j];
    g_cvec[j] = s;
}

__global__ void agg_init_k(int nvec) {
    int i = blockIdx.x*blockDim.x + threadIdx.x;
    if (i < nvec)
        *reinterpret_cast<uint4*>(g_aggenc + i*4) =
            make_uint4(ENC_NEGINF, ENC_NEGINF, ENC_NEGINF, ENC_NEGINF);
}

__global__ void agg_decode_k(int nvec) {
    int idx = blockIdx.x*blockDim.x + threadIdx.x;
    if (idx >= nvec) return;
    int i = idx * 4;
    uint4 e = *reinterpret_cast<uint4*>(g_aggenc + i);
    float4 v;
    v.x = dec_f(e.x); v.y = dec_f(e.y); v.z = dec_f(e.z); v.w = dec_f(e.w);
    if (!isfinite(v.x)) v.x = 0.0f;
    if (!isfinite(v.y)) v.y = 0.0f;
    if (!isfinite(v.z)) v.z = 0.0f;
    if (!isfinite(v.w)) v.w = 0.0f;
    uint2 h, l; split4(v, h, l);
    *reinterpret_cast<uint2*>(g_agh + i) = h;
    *reinterpret_cast<uint2*>(g_agl + i) = l;
}

__global__ void bn_stats1_k(const float* __restrict__ x, int ld, int rowsPer) {
    int c = threadIdx.x;
    int b = blockIdx.x;
    size_t r0 = (size_t)b * rowsPer;
    float s = 0.0f, s2 = 0.0f;
    for (int r = 0; r < rowsPer; r++) {
        float v = x[(r0 + r)*ld + c];
        s += v; s2 += v*v;
    }
    g_part[b*256 + c] = s;
    g_part[b*256 + 128 + c] = s2;
}
__global__ void bn_stats2_k(int nb, float invN, int sbase) {
    int c = threadIdx.x;
    float s = 0.0f, s2 = 0.0f;
    for (int b = 0; b < nb; b++) { s += g_part[b*256 + c]; s2 += g_part[b*256 + 128 + c]; }
    float mu = s * invN;
    float var = s2 * invN - mu*mu;
    g_stats[sbase + c] = mu;
    g_stats[sbase + 128 + c] = rsqrtf(var + 1e-5f);
}
__global__ void bn_apply_k(const float* __restrict__ x, int ld, const float* __restrict__ w,
                           const float* __restrict__ b, float* __restrict__ y, int nvec)
{
    int idx = blockIdx.x*blockDim.x + threadIdx.x;
    if (idx >= nvec) return;
    int i = idx * 4;
    int c = i & 127;
    int row = i >> 7;
    float4 v = *reinterpret_cast<const float4*>(x + (size_t)row*ld + c);
    float4 o;
    o.x = (v.x - g_stats[c])   * g_stats[128 + c]   * w[c]   + b[c];
    o.y = (v.y - g_stats[c+1]) * g_stats[128 + c+1] * w[c+1] + b[c+1];
    o.z = (v.z - g_stats[c+2]) * g_stats[128 + c+2] * w[c+2] + b[c+2];
    o.w = (v.w - g_stats[c+3]) * g_stats[128 + c+3] * w[c+3] + b[c+3];
    *reinterpret_cast<float4*>(y + i) = o;
}

__global__ void bn12_add_split_k(const float* __restrict__ t1, int ld1,
                                 const float* __restrict__ t2,
                                 const float* __restrict__ w1, const float* __restrict__ b1,
                                 const float* __restrict__ w2, const float* __restrict__ b2,
                                 int nvec)
{
    int idx = blockIdx.x*blockDim.x + threadIdx.x;
    if (idx >= nvec) return;
    int i = idx * 4;
    int c = i & 127;
    int row = i >> 7;
    float4 a = *reinterpret_cast<const float4*>(t1 + (size_t)row*ld1 + c);
    float4 d = *reinterpret_cast<const float4*>(t2 + i);
    float4 v;
    v.x = (a.x - g_stats[c])   * g_stats[128+c]   * w1[c]   + b1[c]
        + (d.x - g_stats[256+c])   * g_stats[384+c]   * w2[c]   + b2[c];
    v.y = (a.y - g_stats[c+1]) * g_stats[128+c+1] * w1[c+1] + b1[c+1]
        + (d.y - g_stats[256+c+1]) * g_stats[384+c+1] * w2[c+1] + b2[c+1];
    v.z = (a.z - g_stats[c+2]) * g_stats[128+c+2] * w1[c+2] + b1[c+2]
        + (d.z - g_stats[256+c+2]) * g_stats[384+c+2] * w2[c+2] + b2[c+2];
    v.w = (a.w - g_stats[c+3]) * g_stats[128+c+3] * w1[c+3] + b1[c+3]
        + (d.w - g_stats[256+c+3]) * g_stats[384+c+3] * w2[c+3] + b2[c+3];
    *reinterpret_cast<float4*>(g_out + i) = v;
    uint2 h, l; split4(v, h, l);
    *reinterpret_cast<uint2*>(g_outh + i) = h;
    *reinterpret_cast<uint2*>(g_outl + i) = l;
}

// ---------------- host orchestration -----------------------------------------
template<int OUT, int ACT, bool BIAS, bool ACCUM, bool RESID, bool AF32>
static void run_gemm(const void* Ah, const u16* Al, int lda,
                     const u16* Bh, const u16* Bl, int ldb,
                     float* Cf, u16* Ch, u16* Cl, int ldc,
                     const float* bias, const float* resid,
                     const int* srcv, const int* dstv,
                     const float* zD, const float* zS, int ldz,
                     const float* GD, const float* cvec,
                     unsigned* aggenc, int M, int N, int K, int PER)
{
    auto kfn = gemm_ps<OUT,ACT,BIAS,ACCUM,RESID,AF32>;
    cudaFuncSetAttribute(kfn, cudaFuncAttributeMaxDynamicSharedMemorySize, 163840);
    size_t smemsz = (size_t)K*512 + 32768;
    int tilesM = (M + 63) / 64;
    int tilesN = N / 128;
    int RB = (tilesM * tilesN) / 304;
    if (RB < 1) RB = 1;
    if (RB > 8) RB = 8;
    int gy = (tilesM + RB - 1) / RB;
    dim3 grid(tilesN, gy);
    kfn<<<grid, 256, smemsz>>>(Ah, Al, lda, Bh, Bl, ldb, Cf, Ch, Cl, ldc, bias, resid,
                               srcv, dstv, zD, zS, ldz, GD, cvec, aggenc, M, N, K, PER, tilesM, RB);
}

#define SYMADDR(p, s) cudaGetSymbolAddress((void**)&p, s)

extern "C" void kernel_launch(void* const* d_in, const int* in_sizes, int n_in,
                              void* d_out, int out_size)
{
    const float* node_fts  = (const float*)d_in[0];
    const float* edge_attr = (const float*)d_in[1];
    const float* graph_fts = (const float*)d_in[2];
    const float* hidden    = (const float*)d_in[3];
    const float* W_ee      = (const float*)d_in[4];
    const float* b_ee      = (const float*)d_in[5];
    const float* M0        = (const float*)d_in[6];
    const float* M1        = (const float*)d_in[7];
    const float* M2        = (const float*)d_in[8];
    const float* M3        = (const float*)d_in[9];
    const float* U1        = (const float*)d_in[10];
    const float* U2        = (const float*)d_in[11];
    const float* Wqkv      = (const float*)d_in[12];
    const float* bqkv      = (const float*)d_in[13];
    const float* Wo        = (const float*)d_in[14];
    const float* bo        = (const float*)d_in[15];
    const float* bn1_w     = (const float*)d_in[16];
    const float* bn1_b     = (const float*)d_in[17];
    const float* bn2_w     = (const float*)d_in[18];
    const float* bn2_b     = (const float*)d_in[19];
    const float* bn3_w     = (const float*)d_in[20];
    const float* bn3_b     = (const float*)d_in[21];
    const float* W1        = (const float*)d_in[22];
    const float* b1        = (const float*)d_in[23];
    const float* W2        = (const float*)d_in[24];
    const float* b2        = (const float*)d_in[25];
    const int*   edge_index= (const int*)d_in[26];

    const int N = in_sizes[0] / HH;
    const int E = in_sizes[1] / HH;
    const int G = in_sizes[2] / HH;
    const int PER = N / G;
    const int* src = edge_index;
    const int* dst = edge_index + E;
    float* outp = (float*)d_out;

    u16 *wZU_h,*wZU_l,*wM0c_h,*wM0c_l,*wM0d_h,*wM0d_l,*wee_h,*wee_l;
    u16 *wU2_h,*wU2_l,*wQKV_h,*wQKV_l,*wWo_h,*wWo_l,*wW1_h,*wW1_l,*wW2_h,*wW2_l,*wC_h,*wC_l,*wG_h,*wG_l;
    u16 *z_h,*z_l,*m0h,*m0l,*agh,*agl,*oh,*ol,*outh,*outl,*mlp1h,*mlp1l,*qkvh,*qkvl;
    float *cvec,*GDp,*zc,*t2,*outf,*out2;
    unsigned *aggenc;
    SYMADDR(wZU_h,g_wZU_h);   SYMADDR(wZU_l,g_wZU_l);
    SYMADDR(wM0c_h,g_wM0c_h); SYMADDR(wM0c_l,g_wM0c_l);
    SYMADDR(wM0d_h,g_wM0d_h); SYMADDR(wM0d_l,g_wM0d_l);
    SYMADDR(wee_h,g_wee_h);   SYMADDR(wee_l,g_wee_l);
    SYMADDR(wU2_h,g_wU2_h);   SYMADDR(wU2_l,g_wU2_l);
    SYMADDR(wQKV_h,g_wQKV_h); SYMADDR(wQKV_l,g_wQKV_l);
    SYMADDR(wWo_h,g_wWo_h);   SYMADDR(wWo_l,g_wWo_l);
    SYMADDR(wW1_h,g_wW1_h);   SYMADDR(wW1_l,g_wW1_l);
    SYMADDR(wW2_h,g_wW2_h);   SYMADDR(wW2_l,g_wW2_l);
    SYMADDR(wC_h,g_wC_h);     SYMADDR(wC_l,g_wC_l);
    SYMADDR(wG_h,g_wG_h);     SYMADDR(wG_l,g_wG_l);
    SYMADDR(z_h,g_z_h);       SYMADDR(z_l,g_z_l);
    SYMADDR(m0h,g_m0h); SYMADDR(m0l,g_m0l);
    SYMADDR(agh,g_agh); SYMADDR(agl,g_agl); SYMADDR(oh,g_oh); SYMADDR(ol,g_ol);
    SYMADDR(outh,g_outh); SYMADDR(outl,g_outl); SYMADDR(mlp1h,g_mlp1h); SYMADDR(mlp1l,g_mlp1l);
    SYMADDR(qkvh,g_qkvh); SYMADDR(qkvl,g_qkvl);
    SYMADDR(cvec,g_cvec); SYMADDR(GDp,g_GD); SYMADDR(zc,g_zc);
    SYMADDR(t2,g_t2);
    SYMADDR(outf,g_out); SYMADDR(out2,g_out2);
    SYMADDR(aggenc,g_aggenc);

    // ---- weight prep -------------------------------------------------------
    split_all_k<<<(SPLIT_ALL_TOTAL/4 + 255)/256, 256>>>(M0, W_ee, M1, M2, M3, U2,
                                                        Wqkv, Wo, W1, W2, graph_fts);
    build_zu_k<<<(256*384 + 255)/256, 256>>>(M0, U1);
    cvec_k<<<1, HH>>>(b_ee, M0);
    split_z_k<<<(N*256/8 + 255)/256, 256>>>(node_fts, hidden, N*256/8);
    agg_init_k<<<(N*HH/4 + 255)/256, 256>>>(N*HH/4);

    // ---- C = W_ee @ M0c; GD = graph_fts @ M0d ------------------------------
    run_gemm<1,0,false,false,false,false>(wee_h, wee_l, HH, wM0c_h, wM0c_l, HH,
        nullptr, wC_h, wC_l, HH, nullptr, nullptr, nullptr, nullptr,
        nullptr, nullptr, 0, nullptr, nullptr, nullptr, HH, HH, HH, PER);
    run_gemm<0,0,false,false,false,false>(wG_h, wG_l, HH, wM0d_h, wM0d_l, HH,
        GDp, nullptr, nullptr, HH, nullptr, nullptr, nullptr, nullptr,
        nullptr, nullptr, 0, nullptr, nullptr, nullptr, G, HH, HH, PER);

    // ---- [zD | zS | t1] = z @ [M0a | M0b | U1] -----------------------------
    run_gemm<0,0,false,false,false,false>(z_h, z_l, 256, wZU_h, wZU_l, 384,
        zc, nullptr, nullptr, 384, nullptr, nullptr, nullptr, nullptr,
        nullptr, nullptr, 0, nullptr, nullptr, nullptr, N, 384, 256, PER);

    // ---- e0 GEMM + fused gather -------------------------------------------
    run_gemm<3,0,false,false,false,true>(edge_attr, nullptr, HH, wC_h, wC_l, HH,
        nullptr, m0h, m0l, HH, nullptr, nullptr, src, dst,
        zc, zc + 128, 384, GDp, cvec, nullptr, E, HH, HH, PER);

    // ---- fused M1->M2->M3 chain + seg-max ----------------------------------
    {
        cudaFuncSetAttribute(edge_chain_k, cudaFuncAttributeMaxDynamicSharedMemorySize, 229376);
        edge_chain_k<<<152, 256, 229376>>>(dst, E/64);
    }
    agg_decode_k<<<(N*HH/4 + 255)/256, 256>>>(N*HH/4);

    // ---- t1 += agg@U2 + node_fts -------------------------------------------
    run_gemm<0,0,false,true,true,false>(agh, agl, HH, wU2_h, wU2_l, HH,
        zc + 256, nullptr, nullptr, 384, nullptr, node_fts, nullptr, nullptr,
        nullptr, nullptr, 0, nullptr, nullptr, nullptr, N, HH, HH, PER);
    bn_stats1_k<<<256, 128>>>(zc + 256, 384, N/256);
    bn_stats2_k<<<1, 128>>>(256, 1.0f/(float)N, 0);

    // ---- attention (qkv split out, flash-mma) ------------------------------
    run_gemm<1,0,true,false,false,false>(z_h, z_l, 256, wQKV_h, wQKV_l, 3*HH,
        nullptr, qkvh, qkvl, 3*HH, bqkv, nullptr, nullptr, nullptr,
        nullptr, nullptr, 0, nullptr, nullptr, nullptr, N, 3*HH, HH, PER);
    {
        cudaFuncSetAttribute(attn_mma_k, cudaFuncAttributeMaxDynamicSharedMemorySize, AT_SMEM);
        attn_mma_k<<<dim3(G, 4, PER/64), 256, AT_SMEM>>>(qkvh, qkvl, PER);
    }
    run_gemm<0,0,true,false,true,false>(oh, ol, HH, wWo_h, wWo_l, HH,
        t2, nullptr, nullptr, HH, bo, node_fts, nullptr, nullptr,
        nullptr, nullptr, 0, nullptr, nullptr, nullptr, N, HH, HH, PER);
    bn_stats1_k<<<256, 128>>>(t2, HH, N/256);
    bn_stats2_k<<<1, 128>>>(256, 1.0f/(float)N, 256);

    // ---- fused BN1+BN2+add+split -------------------------------------------
    bn12_add_split_k<<<(N*HH/4 + 255)/256, 256>>>(zc + 256, 384, t2,
        bn1_w, bn1_b, bn2_w, bn2_b, N*HH/4);

    // ---- MLP ---------------------------------------------------------------
    run_gemm<1,1,true,false,false,false>(outh, outl, HH, wW1_h, wW1_l, 2*HH,
        nullptr, mlp1h, mlp1l, 2*HH, b1, nullptr, nullptr, nullptr,
        nullptr, nullptr, 0, nullptr, nullptr, nullptr, N, 2*HH, HH, PER);
    run_gemm<0,0,true,false,true,false>(mlp1h, mlp1l, 2*HH, wW2_h, wW2_l, HH,
        out2, nullptr, nullptr, HH, b2, outf, nullptr, nullptr,
        nullptr, nullptr, 0, nullptr, nullptr, nullptr, N, HH, 2*HH, PER);

    // ---- BN3 -> output ------------------------------------------------------
    bn_stats1_k<<<256, 128>>>(out2, HH, N/256);
    bn_stats2_k<<<1, 128>>>(256, 1.0f/(float)N, 0);
    bn_apply_k<<<(N*HH/4 + 255)/256, 256>>>(out2, HH, bn3_w, bn3_b, outp, N*HH/4);
}